// round 2
// baseline (speedup 1.0000x reference)
#include <cuda_runtime.h>
#include <math.h>

typedef unsigned long long ull;

// ---------------- device scratch (allocations are forbidden) ----------------
__device__ float g_Pvis[1024*512];   // people  @ Wvis[0:1024]
__device__ float g_Ovis[1024*512];   // objects @ Wvis[1024:2048]
__device__ float g_Cvis[64*512];     // context @ Wvis[2048:3072] + Wvis_b
__device__ float g_HO[1024*1024];    // relu(people  @ Who + b)
__device__ float g_OH[1024*1024];    // relu(objects @ Woh + b)
__device__ float g_adj[16384];       // sigmoid(i_ho)
__device__ float g_Wcat[512*64];     // packed [Wip | Wref(29) | Watt(29) | pad]

// ---------------- f32x2 helpers ----------------
__device__ __forceinline__ ull pk2(float x){ ull r; asm("mov.b64 %0,{%1,%1};":"=l"(r):"f"(x)); return r; }
__device__ __forceinline__ ull pk(float x,float y){ ull r; asm("mov.b64 %0,{%1,%2};":"=l"(r):"f"(x),"f"(y)); return r; }
__device__ __forceinline__ void ffma2(ull&d, ull a, ull b){ asm("fma.rn.f32x2 %0,%1,%2,%0;":"+l"(d):"l"(a),"l"(b)); }
__device__ __forceinline__ float2 upk(ull p){ float2 f; asm("mov.b64 {%0,%1},%2;":"=f"(f.x),"=f"(f.y):"l"(p)); return f; }

// ---------------- k0: pack head weights into [512,64] ----------------
__global__ __launch_bounds__(256) void k0_pack(const float* __restrict__ Wip_w,
                                               const float* __restrict__ Wref_w,
                                               const float* __restrict__ Watt_w) {
    int idx = blockIdx.x*256 + threadIdx.x;   // 32768 total
    int k = idx >> 6, c = idx & 63;
    float v = 0.f;
    if (c == 0)                  v = Wip_w[k];
    else if (c <= 29)            v = Wref_w[k*29 + c - 1];
    else if (c >= 30 && c <= 58) v = Watt_w[k*29 + c - 30];
    g_Wcat[idx] = v;
}

// ---------------- k1: five K=1024 GEMMs, wave-packed ----------------
// BM=128, BN=128, BK=16, 256 threads, 8x8 per thread via f32x2
__global__ __launch_bounds__(256,2) void k1_sgemm(
    const float* __restrict__ people, const float* __restrict__ objects,
    const float* __restrict__ context,
    const float* __restrict__ Wvis_w, const float* __restrict__ Wvis_b,
    const float* __restrict__ Who_w,  const float* __restrict__ Who_b,
    const float* __restrict__ Woh_w,  const float* __restrict__ Woh_b)
{
    __shared__ float As[128][20];   // [m][k], pad 16->20
    __shared__ float Bs[16][128];   // [k][n]

    int bid = blockIdx.x;
    const float* A; const float* B; float* C; const float* bias = 0;
    int M, N, rl = 0, local;
    if (bid < 32)       { A=people;  B=Wvis_w;          C=g_Pvis; M=1024; N=512;  local=bid;     }
    else if (bid < 64)  { A=objects; B=Wvis_w+1024*512; C=g_Ovis; M=1024; N=512;  local=bid-32;  }
    else if (bid < 68)  { A=context; B=Wvis_w+2048*512; C=g_Cvis; bias=Wvis_b; M=64; N=512; local=bid-64; }
    else if (bid < 132) { A=people;  B=Who_w; C=g_HO; bias=Who_b; rl=1; M=1024; N=1024; local=bid-68;  }
    else                { A=objects; B=Woh_w; C=g_OH; bias=Woh_b; rl=1; M=1024; N=1024; local=bid-132; }

    int ncols = N >> 7;
    int m0 = (local / ncols) * 128, n0 = (local % ncols) * 128;
    int tid = threadIdx.x, ty = tid >> 4, tx = tid & 15;

    ull acc[8][4];
    #pragma unroll
    for (int i = 0; i < 8; i++)
        #pragma unroll
        for (int q = 0; q < 4; q++) acc[i][q] = 0ull;

    for (int kt = 0; kt < 1024; kt += 16) {
        #pragma unroll
        for (int i = 0; i < 2; i++) {
            int v = tid + i*256;               // 0..511
            int row = v >> 2, kq = (v & 3) << 2;
            int gm = m0 + row;
            float4 a4 = make_float4(0.f,0.f,0.f,0.f);
            if (gm < M) a4 = *(const float4*)&A[gm*1024 + kt + kq];
            *(float4*)&As[row][kq] = a4;
        }
        #pragma unroll
        for (int i = 0; i < 2; i++) {
            int v = tid + i*256;
            int k = v >> 5, nq = (v & 31) << 2;
            *(float4*)&Bs[k][nq] = *(const float4*)&B[(kt + k)*N + n0 + nq];
        }
        __syncthreads();
        #pragma unroll
        for (int k = 0; k < 16; k++) {
            float4 b0 = *(float4*)&Bs[k][tx*4];
            float4 b1 = *(float4*)&Bs[k][64 + tx*4];
            ull bu0 = pk(b0.x,b0.y), bu1 = pk(b0.z,b0.w);
            ull bu2 = pk(b1.x,b1.y), bu3 = pk(b1.z,b1.w);
            #pragma unroll
            for (int i = 0; i < 8; i++) {
                ull am = pk2(As[ty*8 + i][k]);
                ffma2(acc[i][0], am, bu0);
                ffma2(acc[i][1], am, bu1);
                ffma2(acc[i][2], am, bu2);
                ffma2(acc[i][3], am, bu3);
            }
        }
        __syncthreads();
    }

    #pragma unroll
    for (int i = 0; i < 8; i++) {
        int gm = m0 + ty*8 + i;
        if (gm >= M) continue;
        #pragma unroll
        for (int q = 0; q < 4; q++) {
            int gn = n0 + (q >> 1)*64 + tx*4 + (q & 1)*2;
            float2 v = upk(acc[i][q]);
            float b0v = bias ? bias[gn]   : 0.f;
            float b1v = bias ? bias[gn+1] : 0.f;
            float x = v.x + b0v, y = v.y + b1v;
            if (rl) { x = fmaxf(x, 0.f); y = fmaxf(y, 0.f); }
            C[gm*N + gn]     = x;
            C[gm*N + gn + 1] = y;
        }
    }
}

// ---------------- k2: fused per-(b,p) kernel: a_ho, f_ref, 3 heads ----------------
#define FA_PITCH 517
#define K2_SMEM ((512 + 32*FA_PITCH + 128*64) * 4)

__global__ __launch_bounds__(256,2) void k2_pairs(
    const float* __restrict__ spatial,
    const float* __restrict__ Wspat_w, const float* __restrict__ Wspat_b,
    const float* __restrict__ Wip_b,   const float* __restrict__ Wref_b,
    const float* __restrict__ Watt_b,  float* __restrict__ out)
{
    extern __shared__ float sm[];
    float* s_sp = sm;                    // 16 x 32
    float* s_fa = sm + 512;              // 32 x 517 (rows 0-15 f_ref, 16-31 a_ho)
    float* s_w  = s_fa + 32*FA_PITCH;    // 128 x 64 weight chunk

    int tid = threadIdx.x;
    int bp = blockIdx.x;                 // (b,p) group, 1024 total
    int b = bp >> 4;

    #pragma unroll
    for (int i = 0; i < 2; i++) s_sp[tid + i*256] = spatial[bp*512 + tid + i*256];
    __syncthreads();

    // phase 1: a_ho + f_ref into smem; each thread owns 2 columns
    for (int jj = 0; jj < 2; jj++) {
        int j = tid + jj*256;
        float wk[32];
        #pragma unroll
        for (int k = 0; k < 32; k++) wk[k] = Wspat_w[k*512 + j];
        float bs = Wspat_b[j];
        float pv = g_Pvis[bp*512 + j];
        float cv = g_Cvis[b*512 + j];
        #pragma unroll 4
        for (int l = 0; l < 16; l++) {
            float acc = bs;
            #pragma unroll
            for (int k = 0; k < 32; k++) acc += s_sp[l*32 + k] * wk[k];
            float a = fmaxf(acc, 0.f);
            float ov = g_Ovis[(b*16 + l)*512 + j];
            float f = fmaxf(pv + ov + cv, 0.f) * a;
            s_fa[l*FA_PITCH + j]        = f;
            s_fa[(16 + l)*FA_PITCH + j] = a;
        }
    }
    __syncthreads();

    // phase 2: [32 x 512] @ [512 x 64] (packed heads), chunked weights in smem
    int r = tid & 31, c0 = (tid >> 5) * 8;
    ull acc2[4] = {0ull, 0ull, 0ull, 0ull};
    for (int kt = 0; kt < 512; kt += 128) {
        __syncthreads();
        #pragma unroll
        for (int i = 0; i < 8; i++) {
            int v = tid + i*256;
            *(float4*)&s_w[v*4] = *(const float4*)&g_Wcat[kt*64 + v*4];
        }
        __syncthreads();
        #pragma unroll 4
        for (int k = 0; k < 128; k++) {
            ull sv = pk2(s_fa[r*FA_PITCH + kt + k]);
            float4 w0 = *(float4*)&s_w[k*64 + c0];
            float4 w1 = *(float4*)&s_w[k*64 + c0 + 4];
            ffma2(acc2[0], sv, pk(w0.x,w0.y));
            ffma2(acc2[1], sv, pk(w0.z,w0.w));
            ffma2(acc2[2], sv, pk(w1.x,w1.y));
            ffma2(acc2[3], sv, pk(w1.z,w1.w));
        }
    }

    float res[8];
    #pragma unroll
    for (int q = 0; q < 4; q++) { float2 v = upk(acc2[q]); res[q*2] = v.x; res[q*2+1] = v.y; }

    if (r < 16) {                       // f_ref rows -> i_ho (col 0) + p_ref (cols 1..29)
        int cidx = bp*16 + r;
        #pragma unroll
        for (int q = 0; q < 8; q++) {
            int c = c0 + q;
            if (c == 0) {
                float v = res[q] + Wip_b[0];
                out[cidx] = v;
                g_adj[cidx] = 1.f / (1.f + expf(-v));
            } else if (c <= 29) {
                out[16384 + cidx*29 + (c - 1)] = res[q] + Wref_b[c - 1];
            }
        }
    } else {                            // a_ho rows -> p_att (cols 30..58)
        int cidx = bp*16 + (r - 16);
        #pragma unroll
        for (int q = 0; q < 8; q++) {
            int c = c0 + q;
            if (c >= 30 && c <= 58) {
                out[491520 + cidx*29 + (c - 30)] = res[q] + Watt_b[c - 30];
            }
        }
    }
}

// ---------------- k3: per-image graph message passing + p_graph ----------------
#define K3_SMEM ((16*1024 + 15*1024 + 240 + 464 + 464) * 4)

__global__ __launch_bounds__(256) void k3_graph(
    const float* __restrict__ people, const float* __restrict__ objects,
    const float* __restrict__ Wg_w,   const float* __restrict__ Wg_b,
    float* __restrict__ out_pg)
{
    extern __shared__ float sm[];
    float* pr  = sm;               // people_r   [16][1024]
    float* orr = pr + 16*1024;     // objects_r  [15][1024]
    float* adj = orr + 15*1024;    // [16][15]
    float* Gp  = adj + 240;        // [16][29]
    float* Go  = Gp + 464;         // [16][29] (incl. slot0)

    int b = blockIdx.x, tid = threadIdx.x;
    if (tid < 240) adj[tid] = g_adj[(b*16 + tid/15)*16 + (tid % 15) + 1];
    __syncthreads();

    #pragma unroll
    for (int dd = 0; dd < 4; dd++) {
        int d = tid + dd*256;
        float oh[15], ho[16];
        #pragma unroll
        for (int o = 0; o < 15; o++) oh[o] = g_OH[(b*16 + o + 1)*1024 + d];
        #pragma unroll
        for (int p = 0; p < 16; p++) ho[p] = g_HO[(b*16 + p)*1024 + d];
        #pragma unroll
        for (int p = 0; p < 16; p++) {
            float acc = people[(b*16 + p)*1024 + d];
            #pragma unroll
            for (int o = 0; o < 15; o++) acc += adj[p*15 + o] * oh[o];
            pr[p*1024 + d] = acc;
        }
        #pragma unroll
        for (int o = 0; o < 15; o++) {
            float acc = objects[(b*16 + o + 1)*1024 + d];
            #pragma unroll
            for (int p = 0; p < 16; p++) acc += adj[p*15 + o] * ho[p];
            orr[o*1024 + d] = acc;
        }
    }
    __syncthreads();

    // Gp = people_r @ Wg[:1024], Go = objects_full @ Wg[1024:] + Wg_b
    for (int it = tid; it < 928; it += 256) {
        int half = (it >= 464);
        int t2 = half ? it - 464 : it;
        int rr = t2 / 29, a = t2 % 29;
        const float* W = Wg_w + (half ? 1024*29 : 0);
        float acc = half ? Wg_b[a] : 0.f;
        if (!half) {
            for (int k = 0; k < 1024; k++) acc += pr[rr*1024 + k] * W[k*29 + a];
            Gp[t2] = acc;
        } else if (rr == 0) {
            for (int k = 0; k < 1024; k++) acc += objects[b*16*1024 + k] * W[k*29 + a];
            Go[t2] = acc;
        } else {
            for (int k = 0; k < 1024; k++) acc += orr[(rr-1)*1024 + k] * W[k*29 + a];
            Go[t2] = acc;
        }
    }
    __syncthreads();

    for (int it = tid; it < 16*16*29; it += 256) {
        int a = it % 29, l = (it / 29) & 15, p = it / (29*16);
        out_pg[(b*256 + p*16 + l)*29 + a] = Gp[p*29 + a] + Go[l*29 + a];
    }
}

// ---------------- launch ----------------
extern "C" void kernel_launch(void* const* d_in, const int* in_sizes, int n_in,
                              void* d_out, int out_size) {
    const float* people  = (const float*)d_in[0];
    const float* objects = (const float*)d_in[1];
    const float* context = (const float*)d_in[2];
    const float* spatial = (const float*)d_in[3];
    const float* Wvis_w  = (const float*)d_in[4];
    const float* Wvis_b  = (const float*)d_in[5];
    const float* Wspat_w = (const float*)d_in[6];
    const float* Wspat_b = (const float*)d_in[7];
    const float* Wip_w   = (const float*)d_in[8];
    const float* Wip_b   = (const float*)d_in[9];
    const float* Wref_w  = (const float*)d_in[10];
    const float* Wref_b  = (const float*)d_in[11];
    const float* Watt_w  = (const float*)d_in[12];
    const float* Watt_b  = (const float*)d_in[13];
    const float* Woh_w   = (const float*)d_in[14];
    const float* Woh_b   = (const float*)d_in[15];
    const float* Who_w   = (const float*)d_in[16];
    const float* Who_b   = (const float*)d_in[17];
    const float* Wg_w    = (const float*)d_in[18];
    const float* Wg_b    = (const float*)d_in[19];
    float* out = (float*)d_out;

    cudaFuncSetAttribute(k2_pairs, cudaFuncAttributeMaxDynamicSharedMemorySize, K2_SMEM);
    cudaFuncSetAttribute(k3_graph, cudaFuncAttributeMaxDynamicSharedMemorySize, K3_SMEM);

    k0_pack<<<128, 256>>>(Wip_w, Wref_w, Watt_w);
    k1_sgemm<<<196, 256>>>(people, objects, context, Wvis_w, Wvis_b,
                           Who_w, Who_b, Woh_w, Woh_b);
    k2_pairs<<<1024, 256, K2_SMEM>>>(spatial, Wspat_w, Wspat_b,
                                     Wip_b, Wref_b, Watt_b, out);
    k3_graph<<<64, 256, K3_SMEM>>>(people, objects, Wg_w, Wg_b, out + 966656);
}

// round 3
// speedup vs baseline: 1.0341x; 1.0341x over previous
#include <cuda_runtime.h>
#include <math.h>

typedef unsigned long long ull;

// ---------------- device scratch (allocations are forbidden) ----------------
__device__ float g_Pvis[1024*512];   // people  @ Wvis[0:1024]
__device__ float g_Ovis[1024*512];   // objects @ Wvis[1024:2048]
__device__ float g_Cvis[64*512];     // context @ Wvis[2048:3072] + Wvis_b
__device__ float g_HO[1024*1024];    // relu(people  @ Who + b)
__device__ float g_OH[1024*1024];    // relu(objects @ Woh + b)
__device__ float g_adj[16384];       // sigmoid(i_ho)
__device__ float g_Wcat[512*64];     // packed [Wip | Wref(29) | Watt(29) | pad]
__device__ float g_PR[1024*1024];    // people_r
__device__ float g_OBF[1024*1024];   // objects_full (slot0 + refined 1..15)
__device__ float g_Gp[1024*29];
__device__ float g_Go[1024*29];

// ---------------- f32x2 helpers ----------------
__device__ __forceinline__ void ffma2(ull&d, ull a, ull b){ asm("fma.rn.f32x2 %0,%1,%2,%0;":"+l"(d):"l"(a),"l"(b)); }
__device__ __forceinline__ float2 upk(ull p){ float2 f; asm("mov.b64 {%0,%1},%2;":"=f"(f.x),"=f"(f.y):"l"(p)); return f; }

// ---------------- k0: pack head weights into [512,64] ----------------
__global__ __launch_bounds__(256) void k0_pack(const float* __restrict__ Wip_w,
                                               const float* __restrict__ Wref_w,
                                               const float* __restrict__ Watt_w) {
    int idx = blockIdx.x*256 + threadIdx.x;   // 32768 total
    int k = idx >> 6, c = idx & 63;
    float v = 0.f;
    if (c == 0)                  v = Wip_w[k];
    else if (c <= 29)            v = Wref_w[k*29 + c - 1];
    else if (c >= 30 && c <= 58) v = Watt_w[k*29 + c - 30];
    g_Wcat[idx] = v;
}

// ---------------- k1: five K=1024 GEMMs, K-paired f32x2, tile 128x64 ----------------
#define AP 20
#define BP 20
__global__ __launch_bounds__(256,2) void k1_sgemm(
    const float* __restrict__ people, const float* __restrict__ objects,
    const float* __restrict__ context,
    const float* __restrict__ Wvis_w, const float* __restrict__ Wvis_b,
    const float* __restrict__ Who_w,  const float* __restrict__ Who_b,
    const float* __restrict__ Woh_w,  const float* __restrict__ Woh_b)
{
    __shared__ __align__(16) float As[128*AP];   // [m][k] pitch 20
    __shared__ __align__(16) float Bs[64*BP];    // [n][k] pitch 20 (transposed)

    int bid = blockIdx.x;
    const float* A; const float* B; float* C; const float* bias = 0;
    int M, N, rl = 0, local;
    if (bid < 64)       { A=people;  B=Wvis_w;          C=g_Pvis; M=1024; N=512;  local=bid;     }
    else if (bid < 128) { A=objects; B=Wvis_w+1024*512; C=g_Ovis; M=1024; N=512;  local=bid-64;  }
    else if (bid < 136) { A=context; B=Wvis_w+2048*512; C=g_Cvis; bias=Wvis_b; M=64; N=512; local=bid-128; }
    else if (bid < 264) { A=people;  B=Who_w; C=g_HO; bias=Who_b; rl=1; M=1024; N=1024; local=bid-136; }
    else                { A=objects; B=Woh_w; C=g_OH; bias=Woh_b; rl=1; M=1024; N=1024; local=bid-264; }

    int ncols = N >> 6;
    int m0 = (local / ncols) * 128, n0 = (local % ncols) * 64;
    int tid = threadIdx.x;
    int tx = tid & 15;          // n lane (coalesced stores)
    int tyy = tid >> 4;         // m group (broadcast A reads)

    ull acc[8][4];
    #pragma unroll
    for (int i = 0; i < 8; i++)
        #pragma unroll
        for (int j = 0; j < 4; j++) acc[i][j] = 0ull;

    for (int kt = 0; kt < 1024; kt += 16) {
        // load A tile: 128 rows x 16 k, float4 per thread x2
        #pragma unroll
        for (int i = 0; i < 2; i++) {
            int v = tid + i*256;
            int row = v >> 2, kq = (v & 3) << 2;
            int gm = m0 + row;
            float4 a4 = make_float4(0.f,0.f,0.f,0.f);
            if (gm < M) a4 = *(const float4*)&A[gm*1024 + kt + kq];
            *(float4*)&As[row*AP + kq] = a4;
        }
        // load B tile transposed: 16 k x 64 n -> Bs[n][k]
        #pragma unroll
        for (int i = 0; i < 4; i++) {
            int v = tid + i*256;
            int k = v >> 6, n = v & 63;
            Bs[n*BP + k] = B[(kt + k)*N + n0 + n];
        }
        __syncthreads();
        #pragma unroll
        for (int kq = 0; kq < 4; kq++) {
            ulonglong2 bb[4];
            #pragma unroll
            for (int j = 0; j < 4; j++)
                bb[j] = *(const ulonglong2*)&Bs[(tx + 16*j)*BP + kq*4];
            #pragma unroll
            for (int i = 0; i < 8; i++) {
                ulonglong2 av = *(const ulonglong2*)&As[(tyy + 16*i)*AP + kq*4];
                #pragma unroll
                for (int j = 0; j < 4; j++) {
                    ffma2(acc[i][j], av.x, bb[j].x);
                    ffma2(acc[i][j], av.y, bb[j].y);
                }
            }
        }
        __syncthreads();
    }

    #pragma unroll
    for (int i = 0; i < 8; i++) {
        int gm = m0 + tyy + 16*i;
        if (gm >= M) continue;
        #pragma unroll
        for (int j = 0; j < 4; j++) {
            int gn = n0 + tx + 16*j;
            float2 v = upk(acc[i][j]);
            float r = v.x + v.y + (bias ? bias[gn] : 0.f);
            if (rl) r = fmaxf(r, 0.f);
            C[gm*N + gn] = r;
        }
    }
}

// ---------------- k2: fused per-(b,p) kernel: a_ho, f_ref, 3 heads ----------------
#define FA_PITCH 516
#define WT_PITCH 132
#define K2_SMEM ((512 + 32*FA_PITCH + 64*WT_PITCH) * 4)

__global__ __launch_bounds__(256,2) void k2_pairs(
    const float* __restrict__ spatial,
    const float* __restrict__ Wspat_w, const float* __restrict__ Wspat_b,
    const float* __restrict__ Wip_b,   const float* __restrict__ Wref_b,
    const float* __restrict__ Watt_b,  float* __restrict__ out)
{
    extern __shared__ float sm[];
    float* s_sp = sm;                    // 16 x 32
    float* s_fa = sm + 512;              // 32 x 516 (rows 0-15 f_ref, 16-31 a_ho)
    float* s_w  = s_fa + 32*FA_PITCH;    // [64 c][132] transposed weight chunk

    int tid = threadIdx.x;
    int bp = blockIdx.x;                 // (b,p) group, 1024 total
    int b = bp >> 4;

    #pragma unroll
    for (int i = 0; i < 2; i++) s_sp[tid + i*256] = spatial[bp*512 + tid + i*256];
    __syncthreads();

    // phase 1: a_ho + f_ref into smem; each thread owns 2 columns
    for (int jj = 0; jj < 2; jj++) {
        int j = tid + jj*256;
        float wk[32];
        #pragma unroll
        for (int k = 0; k < 32; k++) wk[k] = Wspat_w[k*512 + j];
        float bs = Wspat_b[j];
        float pv = g_Pvis[bp*512 + j];
        float cv = g_Cvis[b*512 + j];
        #pragma unroll 4
        for (int l = 0; l < 16; l++) {
            float acc = bs;
            #pragma unroll
            for (int k = 0; k < 32; k++) acc += s_sp[l*32 + k] * wk[k];
            float a = fmaxf(acc, 0.f);
            float ov = g_Ovis[(b*16 + l)*512 + j];
            float f = fmaxf(pv + ov + cv, 0.f) * a;
            s_fa[l*FA_PITCH + j]        = f;
            s_fa[(16 + l)*FA_PITCH + j] = a;
        }
    }

    // phase 2: [32 x 512] @ [512 x 64] (packed heads), K-paired f32x2
    int r = tid & 31, c0 = (tid >> 5) * 8;
    ull acc2[8];
    #pragma unroll
    for (int q = 0; q < 8; q++) acc2[q] = 0ull;

    for (int kt = 0; kt < 512; kt += 128) {
        __syncthreads();
        // load + transpose W chunk: [128 k][64 c] -> s_w[c][k], 4 k per thread-task
        #pragma unroll
        for (int i = 0; i < 8; i++) {
            int task = tid + i*256;            // 0..2047
            int c = task & 63, kq = (task >> 6) << 2;
            float4 w;
            w.x = g_Wcat[(kt + kq + 0)*64 + c];
            w.y = g_Wcat[(kt + kq + 1)*64 + c];
            w.z = g_Wcat[(kt + kq + 2)*64 + c];
            w.w = g_Wcat[(kt + kq + 3)*64 + c];
            *(float4*)&s_w[c*WT_PITCH + kq] = w;
        }
        __syncthreads();
        #pragma unroll 8
        for (int k = 0; k < 128; k += 4) {
            ulonglong2 sv = *(const ulonglong2*)&s_fa[r*FA_PITCH + kt + k];
            #pragma unroll
            for (int q = 0; q < 8; q++) {
                ulonglong2 wv = *(const ulonglong2*)&s_w[(c0 + q)*WT_PITCH + k];
                ffma2(acc2[q], sv.x, wv.x);
                ffma2(acc2[q], sv.y, wv.y);
            }
        }
    }

    float res[8];
    #pragma unroll
    for (int q = 0; q < 8; q++) { float2 v = upk(acc2[q]); res[q] = v.x + v.y; }

    if (r < 16) {                       // f_ref rows -> i_ho (col 0) + p_ref (cols 1..29)
        int cidx = bp*16 + r;
        #pragma unroll
        for (int q = 0; q < 8; q++) {
            int c = c0 + q;
            if (c == 0) {
                float v = res[q] + Wip_b[0];
                out[cidx] = v;
                g_adj[cidx] = 1.f / (1.f + expf(-v));
            } else if (c <= 29) {
                out[16384 + cidx*29 + (c - 1)] = res[q] + Wref_b[c - 1];
            }
        }
    } else {                            // a_ho rows -> p_att (cols 30..58)
        int cidx = bp*16 + (r - 16);
        #pragma unroll
        for (int q = 0; q < 8; q++) {
            int c = c0 + q;
            if (c >= 30 && c <= 58) {
                out[491520 + cidx*29 + (c - 30)] = res[q] + Watt_b[c - 30];
            }
        }
    }
}

// ---------------- k3a: message passing -> g_PR, g_OBF ----------------
__global__ __launch_bounds__(256) void k3a_msg(const float* __restrict__ people,
                                               const float* __restrict__ objects)
{
    __shared__ float adj[240];
    int b = blockIdx.x >> 2, ch = blockIdx.x & 3;
    int tid = threadIdx.x;
    if (tid < 240) adj[tid] = g_adj[(b*16 + tid/15)*16 + (tid % 15) + 1];
    __syncthreads();

    int d = ch*256 + tid;
    float oh[15], ho[16];
    #pragma unroll
    for (int o = 0; o < 15; o++) oh[o] = g_OH[(b*16 + o + 1)*1024 + d];
    #pragma unroll
    for (int p = 0; p < 16; p++) ho[p] = g_HO[(b*16 + p)*1024 + d];

    #pragma unroll
    for (int p = 0; p < 16; p++) {
        float acc = people[(b*16 + p)*1024 + d];
        #pragma unroll
        for (int o = 0; o < 15; o++) acc += adj[p*15 + o] * oh[o];
        g_PR[(b*16 + p)*1024 + d] = acc;
    }
    g_OBF[(b*16)*1024 + d] = objects[(b*16)*1024 + d];
    #pragma unroll
    for (int o = 0; o < 15; o++) {
        float acc = objects[(b*16 + o + 1)*1024 + d];
        #pragma unroll
        for (int p = 0; p < 16; p++) acc += adj[p*15 + o] * ho[p];
        g_OBF[(b*16 + o + 1)*1024 + d] = acc;
    }
}

// ---------------- k3b: skinny GEMM [2048,1024]@[1024,29] warp-per-row ----------------
__global__ __launch_bounds__(256) void k3b_gemm(const float* __restrict__ Wg_w,
                                                const float* __restrict__ Wg_b)
{
    __shared__ float Ws[256*33];
    int half = blockIdx.x >> 7;
    int row = (blockIdx.x & 127)*8 + (threadIdx.x >> 5);
    int lane = threadIdx.x & 31;
    const float* src = half ? g_OBF : g_PR;
    const float* W = Wg_w + half*1024*29;
    float* dst = half ? g_Go : g_Gp;

    float acc[29];
    #pragma unroll
    for (int a = 0; a < 29; a++) acc[a] = 0.f;

    for (int kt = 0; kt < 4; kt++) {
        __syncthreads();
        #pragma unroll
        for (int i = 0; i < 29; i++) {
            int idx = threadIdx.x + i*256;         // 0..7423
            int k = idx / 29, a = idx - k*29;
            Ws[k*33 + a] = W[kt*7424 + idx];
        }
        __syncthreads();
        #pragma unroll
        for (int t = 0; t < 8; t++) {
            int k = t*32 + lane;
            float rv = src[row*1024 + kt*256 + k];
            #pragma unroll
            for (int a = 0; a < 29; a++) acc[a] += rv * Ws[k*33 + a];
        }
    }
    #pragma unroll
    for (int off = 16; off; off >>= 1)
        #pragma unroll
        for (int a = 0; a < 29; a++)
            acc[a] += __shfl_down_sync(0xffffffffu, acc[a], off);
    if (lane == 0) {
        #pragma unroll
        for (int a = 0; a < 29; a++)
            dst[row*29 + a] = acc[a] + (half ? Wg_b[a] : 0.f);
    }
}

// ---------------- k3c: broadcast add -> p_graph ----------------
__global__ __launch_bounds__(256) void k3c_add(float* __restrict__ out_pg)
{
    int idx = blockIdx.x*256 + threadIdx.x;        // 475136 total, exact
    int c = idx / 29;
    int a = idx - c*29;
    int prow = c >> 4;
    int lrow = (c >> 8)*16 + (c & 15);
    out_pg[idx] = g_Gp[prow*29 + a] + g_Go[lrow*29 + a];
}

// ---------------- launch ----------------
extern "C" void kernel_launch(void* const* d_in, const int* in_sizes, int n_in,
                              void* d_out, int out_size) {
    const float* people  = (const float*)d_in[0];
    const float* objects = (const float*)d_in[1];
    const float* context = (const float*)d_in[2];
    const float* spatial = (const float*)d_in[3];
    const float* Wvis_w  = (const float*)d_in[4];
    const float* Wvis_b  = (const float*)d_in[5];
    const float* Wspat_w = (const float*)d_in[6];
    const float* Wspat_b = (const float*)d_in[7];
    const float* Wip_w   = (const float*)d_in[8];
    const float* Wip_b   = (const float*)d_in[9];
    const float* Wref_w  = (const float*)d_in[10];
    const float* Wref_b  = (const float*)d_in[11];
    const float* Watt_w  = (const float*)d_in[12];
    const float* Watt_b  = (const float*)d_in[13];
    const float* Woh_w   = (const float*)d_in[14];
    const float* Woh_b   = (const float*)d_in[15];
    const float* Who_w   = (const float*)d_in[16];
    const float* Who_b   = (const float*)d_in[17];
    const float* Wg_w    = (const float*)d_in[18];
    const float* Wg_b    = (const float*)d_in[19];
    float* out = (float*)d_out;

    cudaFuncSetAttribute(k2_pairs, cudaFuncAttributeMaxDynamicSharedMemorySize, K2_SMEM);

    k0_pack<<<128, 256>>>(Wip_w, Wref_w, Watt_w);
    k1_sgemm<<<392, 256>>>(people, objects, context, Wvis_w, Wvis_b,
                           Who_w, Who_b, Woh_w, Woh_b);
    k2_pairs<<<1024, 256, K2_SMEM>>>(spatial, Wspat_w, Wspat_b,
                                     Wip_b, Wref_b, Watt_b, out);
    k3a_msg<<<256, 256>>>(people, objects);
    k3b_gemm<<<256, 256>>>(Wg_w, Wg_b);
    k3c_add<<<1856, 256>>>(out + 966656);
}

// round 5
// speedup vs baseline: 1.6901x; 1.6344x over previous
#include <cuda_runtime.h>
#include <cuda_bf16.h>
#include <math.h>

typedef unsigned long long ull;
typedef unsigned int u32;

// ---------------- device scratch (allocations are forbidden) ----------------
__device__ float g_Pvis[1024*512];   // people  @ Wvis[0:1024]
__device__ float g_Ovis[1024*512];   // objects @ Wvis[1024:2048]
__device__ float g_Cvis[64*512];     // context @ Wvis[2048:3072] + Wvis_b
__device__ float g_HO[1024*1024];    // relu(people  @ Who + b)
__device__ float g_OH[1024*1024];    // relu(objects @ Woh + b)
__device__ float g_adj[16384];       // sigmoid(i_ho)
__device__ float g_Wcat[512*64];     // packed [Wip|Wref(29)|0,0 | Watt(29)|0,0,0]
__device__ float g_PR[1024*1024];    // people_r
__device__ float g_OBF[1024*1024];   // objects_full
__device__ float g_Gp[1024*29];
__device__ float g_Go[1024*29];

// bf16 hi/lo pre-converted operands for k1
__device__ __nv_bfloat16 g_peh[1024*1024], g_pel[1024*1024];
__device__ __nv_bfloat16 g_obh[1024*1024], g_obl[1024*1024];
__device__ __nv_bfloat16 g_cxh[128*1024],  g_cxl[128*1024];     // padded to 128 rows
__device__ __nv_bfloat16 g_Bv0h[512*1024], g_Bv0l[512*1024];    // Wvis[0:1024]^T  [n][k]
__device__ __nv_bfloat16 g_Bv1h[512*1024], g_Bv1l[512*1024];    // Wvis[1024:2048]^T
__device__ __nv_bfloat16 g_Bv2h[512*1024], g_Bv2l[512*1024];    // Wvis[2048:3072]^T
__device__ __nv_bfloat16 g_Whoh[1024*1024], g_Whol[1024*1024];  // Who^T
__device__ __nv_bfloat16 g_Wohh[1024*1024], g_Wohl[1024*1024];  // Woh^T

// ---------------- small helpers ----------------
__device__ __forceinline__ void ffma2(ull&d, ull a, ull b){ asm("fma.rn.f32x2 %0,%1,%2,%0;":"+l"(d):"l"(a),"l"(b)); }
__device__ __forceinline__ float2 upk(ull p){ float2 f; asm("mov.b64 {%0,%1},%2;":"=f"(f.x),"=f"(f.y):"l"(p)); return f; }
__device__ __forceinline__ u32 smem_u32(const void* p){
    u32 a; asm("{ .reg .u64 t; cvta.to.shared.u64 t, %1; cvt.u32.u64 %0, t; }":"=r"(a):"l"(p)); return a;
}
__device__ __forceinline__ void ldm_x4(u32* r, u32 addr){
    asm volatile("ldmatrix.sync.aligned.m8n8.x4.shared.b16 {%0,%1,%2,%3}, [%4];"
        :"=r"(r[0]),"=r"(r[1]),"=r"(r[2]),"=r"(r[3]):"r"(addr));
}
__device__ __forceinline__ void ldm_x2(u32* r, u32 addr){
    asm volatile("ldmatrix.sync.aligned.m8n8.x2.shared.b16 {%0,%1}, [%2];"
        :"=r"(r[0]),"=r"(r[1]):"r"(addr));
}
__device__ __forceinline__ void mma_bf16(float* c, const u32* a, const u32* b){
    asm volatile("mma.sync.aligned.m16n8k16.row.col.f32.bf16.bf16.f32 "
        "{%0,%1,%2,%3}, {%4,%5,%6,%7}, {%8,%9}, {%0,%1,%2,%3};"
        :"+f"(c[0]),"+f"(c[1]),"+f"(c[2]),"+f"(c[3])
        :"r"(a[0]),"r"(a[1]),"r"(a[2]),"r"(a[3]),"r"(b[0]),"r"(b[1]));
}

// ---------------- conv kernels: fp32 -> bf16 hi/lo ----------------
__global__ __launch_bounds__(256) void c_convA(const float* __restrict__ people,
                                               const float* __restrict__ objects,
                                               const float* __restrict__ context){
    int idx = blockIdx.x*256 + threadIdx.x;          // 2,228,224 total
    const float* src; __nv_bfloat16 *dh, *dl; int e;
    if (idx < 1048576)      { src = people;  dh = g_peh; dl = g_pel; e = idx; }
    else if (idx < 2097152) { src = objects; dh = g_obh; dl = g_obl; e = idx - 1048576; }
    else                    { src = context; dh = g_cxh; dl = g_cxl; e = idx - 2097152; }
    float v = 0.f;
    if (dh != g_cxh || (e >> 10) < 64) v = src[e];
    __nv_bfloat16 h = __float2bfloat16(v);
    dh[e] = h;
    dl[e] = __float2bfloat16(v - __bfloat162float(h));
}

__global__ __launch_bounds__(256) void c_convB(const float* __restrict__ Wvis_w,
                                               const float* __restrict__ Who_w,
                                               const float* __restrict__ Woh_w){
    __shared__ float t[32][33];
    int bid = blockIdx.x;                           // 3584 tiles
    const float* W; __nv_bfloat16 *dh, *dl; int N, local;
    if (bid < 512)        { W = Wvis_w;            dh = g_Bv0h; dl = g_Bv0l; N = 512;  local = bid;       }
    else if (bid < 1024)  { W = Wvis_w + 1024*512; dh = g_Bv1h; dl = g_Bv1l; N = 512;  local = bid - 512; }
    else if (bid < 1536)  { W = Wvis_w + 2048*512; dh = g_Bv2h; dl = g_Bv2l; N = 512;  local = bid - 1024;}
    else if (bid < 2560)  { W = Who_w;             dh = g_Whoh; dl = g_Whol; N = 1024; local = bid - 1536;}
    else                  { W = Woh_w;             dh = g_Wohh; dl = g_Wohl; N = 1024; local = bid - 2560;}
    int ntN = N >> 5;
    int k0 = (local / ntN) * 32, n0 = (local % ntN) * 32;
    int tid = threadIdx.x;
    #pragma unroll
    for (int i = 0; i < 4; i++) {
        int e = tid + i*256, r = e >> 5, c = e & 31;
        t[r][c] = W[(k0 + r)*N + n0 + c];
    }
    __syncthreads();
    #pragma unroll
    for (int i = 0; i < 4; i++) {
        int e = tid + i*256, r = e >> 5, c = e & 31;   // r = n within, c = k within
        float v = t[c][r];
        __nv_bfloat16 h = __float2bfloat16(v);
        dh[(n0 + r)*1024 + k0 + c] = h;
        dl[(n0 + r)*1024 + k0 + c] = __float2bfloat16(v - __bfloat162float(h));
    }
}

// ---------------- k0: pack head weights into [512,64] ----------------
__global__ __launch_bounds__(256) void k0_pack(const float* __restrict__ Wip_w,
                                               const float* __restrict__ Wref_w,
                                               const float* __restrict__ Watt_w) {
    int idx = blockIdx.x*256 + threadIdx.x;   // 32768 total
    int k = idx >> 6, c = idx & 63;
    float v = 0.f;
    if (c == 0)                  v = Wip_w[k];
    else if (c <= 29)            v = Wref_w[k*29 + c - 1];
    else if (c >= 32 && c <= 60) v = Watt_w[k*29 + c - 32];
    g_Wcat[idx] = v;
}

// ---------------- k1: warp-MMA bf16 3-term split GEMM, 128x128 tiles ----------------
#define KP 40                        // bf16 pitch per smem row (80B, conflict-free for ldmatrix)
#define TILE_B (128*KP*2)            // 10240 bytes per operand tile
#define K1_SMEM (4*TILE_B)           // Ah, Al, Bh, Bl

__global__ __launch_bounds__(256,2) void k1_mma(
    const float* __restrict__ Wvis_b,
    const float* __restrict__ Who_b,
    const float* __restrict__ Woh_b)
{
    extern __shared__ char smem[];
    u32 sb = smem_u32(smem);
    int tid = threadIdx.x, lane = tid & 31, wid = tid >> 5;
    int wm = wid & 1, wn = wid >> 1;                 // warp tile: rows wm*64, cols wn*32
    int bid = blockIdx.x;

    const __nv_bfloat16 *Ah, *Al, *Bh, *Bl;
    float* C; const float* bias = 0;
    int relu = 0, Mv = 1024, N, mt0, nt0, local;
    if (bid < 32)       { Ah=g_peh; Al=g_pel; Bh=g_Bv0h; Bl=g_Bv0l; C=g_Pvis; N=512;  local=bid;     mt0=local>>2; nt0=local&3; }
    else if (bid < 64)  { Ah=g_obh; Al=g_obl; Bh=g_Bv1h; Bl=g_Bv1l; C=g_Ovis; N=512;  local=bid-32;  mt0=local>>2; nt0=local&3; }
    else if (bid < 68)  { Ah=g_cxh; Al=g_cxl; Bh=g_Bv2h; Bl=g_Bv2l; C=g_Cvis; N=512;  local=bid-64;  mt0=0; nt0=local; bias=Wvis_b; Mv=64; }
    else if (bid < 132) { Ah=g_peh; Al=g_pel; Bh=g_Whoh; Bl=g_Whol; C=g_HO;   N=1024; local=bid-68;  mt0=local>>3; nt0=local&7; bias=Who_b; relu=1; }
    else                { Ah=g_obh; Al=g_obl; Bh=g_Wohh; Bl=g_Wohl; C=g_OH;   N=1024; local=bid-132; mt0=local>>3; nt0=local&7; bias=Woh_b; relu=1; }
    int m0 = mt0 * 128, n0 = nt0 * 128;

    u32 sAh = sb, sAl = sb + TILE_B, sBh = sb + 2*TILE_B, sBl = sb + 3*TILE_B;

    float acc[4][4][4];
    #pragma unroll
    for (int i = 0; i < 4; i++)
        #pragma unroll
        for (int j = 0; j < 4; j++)
            #pragma unroll
            for (int q = 0; q < 4; q++) acc[i][j][q] = 0.f;

    // ldmatrix lane address components
    int lg = lane >> 3, lr = lane & 7;
    // A x4: row = base_m + lr + (lg&1)*8 ; k = ks + (lg>>1)*8
    int a_row_off = lr + ((lg & 1) << 3);
    int a_k_off   = (lg >> 1) << 3;
    // B x2: row = base_n + lr ; k = ks + ((lg&1))*8   (lanes>=16 mirror 0-15)
    int b_row_off = lr;
    int b_k_off   = (lg & 1) << 3;

    for (int kt = 0; kt < 1024; kt += 32) {
        // ---- load 4 operand tiles [128 x 32 bf16] ----
        const __nv_bfloat16* srcs[4] = {Ah, Al, Bh, Bl};
        u32 dsts[4] = {sAh, sAl, sBh, sBl};
        int rbs[4] = {m0, m0, n0, n0};
        #pragma unroll
        for (int arr = 0; arr < 4; arr++) {
            const __nv_bfloat16* s = srcs[arr];
            #pragma unroll
            for (int i = 0; i < 2; i++) {
                int e = tid + i*256;                  // 0..511
                int row = e >> 2, seg = e & 3;
                uint4 v = *(const uint4*)&s[(rbs[arr] + row)*1024 + kt + seg*8];
                *(uint4*)(smem + (dsts[arr] - sb) + (row*KP + seg*8)*2) = v;
            }
        }
        __syncthreads();

        #pragma unroll
        for (int ks = 0; ks < 32; ks += 16) {
            u32 bh[4][2], bl[4][2];
            #pragma unroll
            for (int nt = 0; nt < 4; nt++) {
                u32 boff = ((wn*32 + nt*8 + b_row_off)*KP + ks + b_k_off) * 2;
                ldm_x2(bh[nt], sBh + boff);
                ldm_x2(bl[nt], sBl + boff);
            }
            #pragma unroll
            for (int mt = 0; mt < 4; mt++) {
                u32 aoff = ((wm*64 + mt*16 + a_row_off)*KP + ks + a_k_off) * 2;
                u32 ah[4], al[4];
                ldm_x4(ah, sAh + aoff);
                ldm_x4(al, sAl + aoff);
                #pragma unroll
                for (int nt = 0; nt < 4; nt++) {
                    mma_bf16(acc[mt][nt], ah, bh[nt]);
                    mma_bf16(acc[mt][nt], ah, bl[nt]);
                    mma_bf16(acc[mt][nt], al, bh[nt]);
                }
            }
        }
        __syncthreads();
    }

    // ---- epilogue ----
    int rq = lane >> 2, cq = (lane & 3) * 2;
    #pragma unroll
    for (int mt = 0; mt < 4; mt++) {
        int gmA = m0 + wm*64 + mt*16 + rq;
        int gmB = gmA + 8;
        #pragma unroll
        for (int nt = 0; nt < 4; nt++) {
            int gn = n0 + wn*32 + nt*8 + cq;
            float b0 = bias ? bias[gn]   : 0.f;
            float b1 = bias ? bias[gn+1] : 0.f;
            float v0 = acc[mt][nt][0] + b0, v1 = acc[mt][nt][1] + b1;
            float v2 = acc[mt][nt][2] + b0, v3 = acc[mt][nt][3] + b1;
            if (relu) { v0=fmaxf(v0,0.f); v1=fmaxf(v1,0.f); v2=fmaxf(v2,0.f); v3=fmaxf(v3,0.f); }
            if (gmA < Mv) *(float2*)&C[gmA*N + gn] = make_float2(v0, v1);
            if (gmB < Mv) *(float2*)&C[gmB*N + gn] = make_float2(v2, v3);
        }
    }
}

// ---------------- k2: fused per-(b,p) kernel: a_ho, f_ref, 3 heads ----------------
#define FA_PITCH 516
#define WT_PITCH 132
#define K2_SMEM ((512 + 32*FA_PITCH + 64*WT_PITCH) * 4)

__global__ __launch_bounds__(256,2) void k2_pairs(
    const float* __restrict__ spatial,
    const float* __restrict__ Wspat_w, const float* __restrict__ Wspat_b,
    const float* __restrict__ Wip_b,   const float* __restrict__ Wref_b,
    const float* __restrict__ Watt_b,  float* __restrict__ out)
{
    extern __shared__ float sm[];
    float* s_sp = sm;                    // 16 x 32
    float* s_fa = sm + 512;              // 32 x 516 (rows 0-15 f_ref, 16-31 a_ho)
    float* s_w  = s_fa + 32*FA_PITCH;    // [64 c][132] transposed weight chunk

    int tid = threadIdx.x;
    int bp = blockIdx.x;                 // (b,p) group, 1024 total
    int b = bp >> 4;

    #pragma unroll
    for (int i = 0; i < 2; i++) s_sp[tid + i*256] = spatial[bp*512 + tid + i*256];
    __syncthreads();

    // phase 1: a_ho + f_ref into smem; each thread owns 2 columns
    for (int jj = 0; jj < 2; jj++) {
        int j = tid + jj*256;
        float wk[32];
        #pragma unroll
        for (int k = 0; k < 32; k++) wk[k] = Wspat_w[k*512 + j];
        float bs = Wspat_b[j];
        float pv = g_Pvis[bp*512 + j];
        float cv = g_Cvis[b*512 + j];
        #pragma unroll 4
        for (int l = 0; l < 16; l++) {
            float acc = bs;
            #pragma unroll
            for (int k = 0; k < 32; k++) acc += s_sp[l*32 + k] * wk[k];
            float a = fmaxf(acc, 0.f);
            float ov = g_Ovis[(b*16 + l)*512 + j];
            float f = fmaxf(pv + ov + cv, 0.f) * a;
            s_fa[l*FA_PITCH + j]        = f;
            s_fa[(16 + l)*FA_PITCH + j] = a;
        }
    }

    // phase 2: rows r<16 (f_ref) need head cols 0..31; rows r>=16 (a_ho) cols 32..63
    int r = tid & 31, cg = tid >> 5;
    int cbase = ((r < 16) ? 0 : 32) + cg*4;
    ull acc2[4] = {0ull, 0ull, 0ull, 0ull};

    for (int kt = 0; kt < 512; kt += 128) {
        __syncthreads();
        #pragma unroll
        for (int i = 0; i < 8; i++) {
            int task = tid + i*256;            // 0..2047
            int cc = task & 63, kq = (task >> 6) << 2;
            float4 w;
            w.x = g_Wcat[(kt + kq + 0)*64 + cc];
            w.y = g_Wcat[(kt + kq + 1)*64 + cc];
            w.z = g_Wcat[(kt + kq + 2)*64 + cc];
            w.w = g_Wcat[(kt + kq + 3)*64 + cc];
            *(float4*)&s_w[cc*WT_PITCH + kq] = w;
        }
        __syncthreads();
        #pragma unroll 8
        for (int k = 0; k < 128; k += 4) {
            ulonglong2 sv = *(const ulonglong2*)&s_fa[r*FA_PITCH + kt + k];
            #pragma unroll
            for (int q = 0; q < 4; q++) {
                ulonglong2 wv = *(const ulonglong2*)&s_w[(cbase + q)*WT_PITCH + k];
                ffma2(acc2[q], sv.x, wv.x);
                ffma2(acc2[q], sv.y, wv.y);
            }
        }
    }

    float res[4];
    #pragma unroll
    for (int q = 0; q < 4; q++) { float2 v = upk(acc2[q]); res[q] = v.x + v.y; }

    if (r < 16) {                       // cols 0..31: i_ho (0) + p_ref (1..29)
        int cidx = bp*16 + r;
        #pragma unroll
        for (int q = 0; q < 4; q++) {
            int c = cbase + q;
            if (c == 0) {
                float v = res[q] + Wip_b[0];
                out[cidx] = v;
                g_adj[cidx] = 1.f / (1.f + expf(-v));
            } else if (c <= 29) {
                out[16384 + cidx*29 + (c - 1)] = res[q] + Wref_b[c - 1];
            }
        }
    } else {                            // cols 32..63: p_att (32..60)
        int cidx = bp*16 + (r - 16);
        #pragma unroll
        for (int q = 0; q < 4; q++) {
            int c32 = cbase + q - 32;
            if (c32 <= 28) {
                out[491520 + cidx*29 + c32] = res[q] + Watt_b[c32];
            }
        }
    }
}

// ---------------- k3a: message passing -> g_PR, g_OBF ----------------
__global__ __launch_bounds__(256) void k3a_msg(const float* __restrict__ people,
                                               const float* __restrict__ objects)
{
    __shared__ float adj[240];
    int b = blockIdx.x >> 2, ch = blockIdx.x & 3;
    int tid = threadIdx.x;
    if (tid < 240) adj[tid] = g_adj[(b*16 + tid/15)*16 + (tid % 15) + 1];
    __syncthreads();

    int d = ch*256 + tid;
    float oh[15], ho[16];
    #pragma unroll
    for (int o = 0; o < 15; o++) oh[o] = g_OH[(b*16 + o + 1)*1024 + d];
    #pragma unroll
    for (int p = 0; p < 16; p++) ho[p] = g_HO[(b*16 + p)*1024 + d];

    #pragma unroll
    for (int p = 0; p < 16; p++) {
        float acc = people[(b*16 + p)*1024 + d];
        #pragma unroll
        for (int o = 0; o < 15; o++) acc += adj[p*15 + o] * oh[o];
        g_PR[(b*16 + p)*1024 + d] = acc;
    }
    g_OBF[(b*16)*1024 + d] = objects[(b*16)*1024 + d];
    #pragma unroll
    for (int o = 0; o < 15; o++) {
        float acc = objects[(b*16 + o + 1)*1024 + d];
        #pragma unroll
        for (int p = 0; p < 16; p++) acc += adj[p*15 + o] * ho[p];
        g_OBF[(b*16 + o + 1)*1024 + d] = acc;
    }
}

// ---------------- k3b: skinny GEMM [2048,1024]@[1024,29] warp-per-row ----------------
__global__ __launch_bounds__(256) void k3b_gemm(const float* __restrict__ Wg_w,
                                                const float* __restrict__ Wg_b)
{
    __shared__ float Ws[256*33];
    int half = blockIdx.x >> 7;
    int row = (blockIdx.x & 127)*8 + (threadIdx.x >> 5);
    int lane = threadIdx.x & 31;
    const float* src = half ? g_OBF : g_PR;
    const float* W = Wg_w + half*1024*29;
    float* dst = half ? g_Go : g_Gp;

    float acc[29];
    #pragma unroll
    for (int a = 0; a < 29; a++) acc[a] = 0.f;

    for (int kt = 0; kt < 4; kt++) {
        __syncthreads();
        #pragma unroll
        for (int i = 0; i < 29; i++) {
            int idx = threadIdx.x + i*256;
            int k = idx / 29, a = idx - k*29;
            Ws[k*33 + a] = W[kt*7424 + idx];
        }
        __syncthreads();
        #pragma unroll
        for (int t = 0; t < 8; t++) {
            int k = t*32 + lane;
            float rv = src[row*1024 + kt*256 + k];
            #pragma unroll
            for (int a = 0; a < 29; a++) acc[a] += rv * Ws[k*33 + a];
        }
    }
    #pragma unroll
    for (int off = 16; off; off >>= 1)
        #pragma unroll
        for (int a = 0; a < 29; a++)
            acc[a] += __shfl_down_sync(0xffffffffu, acc[a], off);
    if (lane == 0) {
        #pragma unroll
        for (int a = 0; a < 29; a++)
            dst[row*29 + a] = acc[a] + (half ? Wg_b[a] : 0.f);
    }
}

// ---------------- k3c: broadcast add -> p_graph ----------------
__global__ __launch_bounds__(256) void k3c_add(float* __restrict__ out_pg)
{
    int idx = blockIdx.x*256 + threadIdx.x;        // 475136 total, exact
    int c = idx / 29;
    int a = idx - c*29;
    int prow = c >> 4;
    int lrow = (c >> 8)*16 + (c & 15);
    out_pg[idx] = g_Gp[prow*29 + a] + g_Go[lrow*29 + a];
}

// ---------------- launch ----------------
extern "C" void kernel_launch(void* const* d_in, const int* in_sizes, int n_in,
                              void* d_out, int out_size) {
    const float* people  = (const float*)d_in[0];
    const float* objects = (const float*)d_in[1];
    const float* context = (const float*)d_in[2];
    const float* spatial = (const float*)d_in[3];
    const float* Wvis_w  = (const float*)d_in[4];
    const float* Wvis_b  = (const float*)d_in[5];
    const float* Wspat_w = (const float*)d_in[6];
    const float* Wspat_b = (const float*)d_in[7];
    const float* Wip_w   = (const float*)d_in[8];
    const float* Wip_b   = (const float*)d_in[9];
    const float* Wref_w  = (const float*)d_in[10];
    const float* Wref_b  = (const float*)d_in[11];
    const float* Watt_w  = (const float*)d_in[12];
    const float* Watt_b  = (const float*)d_in[13];
    const float* Woh_w   = (const float*)d_in[14];
    const float* Woh_b   = (const float*)d_in[15];
    const float* Who_w   = (const float*)d_in[16];
    const float* Who_b   = (const float*)d_in[17];
    const float* Wg_w    = (const float*)d_in[18];
    const float* Wg_b    = (const float*)d_in[19];
    float* out = (float*)d_out;

    cudaFuncSetAttribute(k1_mma,  cudaFuncAttributeMaxDynamicSharedMemorySize, K1_SMEM);
    cudaFuncSetAttribute(k2_pairs, cudaFuncAttributeMaxDynamicSharedMemorySize, K2_SMEM);

    c_convA<<<8704, 256>>>(people, objects, context);
    c_convB<<<3584, 256>>>(Wvis_w, Who_w, Woh_w);
    k0_pack<<<128, 256>>>(Wip_w, Wref_w, Watt_w);
    k1_mma<<<196, 256, K1_SMEM>>>(Wvis_b, Who_b, Woh_b);
    k2_pairs<<<1024, 256, K2_SMEM>>>(spatial, Wspat_w, Wspat_b,
                                     Wip_b, Wref_b, Watt_b, out);
    k3a_msg<<<256, 256>>>(people, objects);
    k3b_gemm<<<256, 256>>>(Wg_w, Wg_b);
    k3c_add<<<1856, 256>>>(out + 966656);
}

// round 6
// speedup vs baseline: 1.7067x; 1.0098x over previous
#include <cuda_runtime.h>
#include <cuda_bf16.h>
#include <math.h>

typedef unsigned long long ull;
typedef unsigned int u32;

// ---------------- device scratch (allocations are forbidden) ----------------
__device__ float g_Pvis[1024*512];   // people  @ Wvis[0:1024]
__device__ float g_Ovis[1024*512];   // objects @ Wvis[1024:2048]
__device__ float g_Cvis[64*512];     // context @ Wvis[2048:3072] + Wvis_b
__device__ float g_HO[1024*1024];    // relu(people  @ Who + b)
__device__ float g_OH[1024*1024];    // relu(objects @ Woh + b)
__device__ float g_adj[16384];       // sigmoid(i_ho)
__device__ float g_Wcat[512*64];     // packed [Wip|Wref(29)|0,0 | Watt(29)|0,0,0]
__device__ float g_PR[1024*1024];    // people_r
__device__ float g_OBF[1024*1024];   // objects_full
__device__ float g_Gp[1024*29];
__device__ float g_Go[1024*29];

// bf16 hi/lo pre-converted operands for k1
__device__ __nv_bfloat16 g_peh[1024*1024], g_pel[1024*1024];
__device__ __nv_bfloat16 g_obh[1024*1024], g_obl[1024*1024];
__device__ __nv_bfloat16 g_cxh[128*1024],  g_cxl[128*1024];     // padded to 128 rows
__device__ __nv_bfloat16 g_Bv0h[512*1024], g_Bv0l[512*1024];    // Wvis[0:1024]^T  [n][k]
__device__ __nv_bfloat16 g_Bv1h[512*1024], g_Bv1l[512*1024];    // Wvis[1024:2048]^T
__device__ __nv_bfloat16 g_Bv2h[512*1024], g_Bv2l[512*1024];    // Wvis[2048:3072]^T
__device__ __nv_bfloat16 g_Whoh[1024*1024], g_Whol[1024*1024];  // Who^T
__device__ __nv_bfloat16 g_Wohh[1024*1024], g_Wohl[1024*1024];  // Woh^T

// ---------------- small helpers ----------------
__device__ __forceinline__ void ffma2(ull&d, ull a, ull b){ asm("fma.rn.f32x2 %0,%1,%2,%0;":"+l"(d):"l"(a),"l"(b)); }
__device__ __forceinline__ float2 upk(ull p){ float2 f; asm("mov.b64 {%0,%1},%2;":"=f"(f.x),"=f"(f.y):"l"(p)); return f; }
__device__ __forceinline__ u32 smem_u32(const void* p){
    u32 a; asm("{ .reg .u64 t; cvta.to.shared.u64 t, %1; cvt.u32.u64 %0, t; }":"=r"(a):"l"(p)); return a;
}
__device__ __forceinline__ void ldm_x4(u32* r, u32 addr){
    asm volatile("ldmatrix.sync.aligned.m8n8.x4.shared.b16 {%0,%1,%2,%3}, [%4];"
        :"=r"(r[0]),"=r"(r[1]),"=r"(r[2]),"=r"(r[3]):"r"(addr));
}
__device__ __forceinline__ void ldm_x2(u32* r, u32 addr){
    asm volatile("ldmatrix.sync.aligned.m8n8.x2.shared.b16 {%0,%1}, [%2];"
        :"=r"(r[0]),"=r"(r[1]):"r"(addr));
}
__device__ __forceinline__ void mma_bf16(float* c, const u32* a, const u32* b){
    asm volatile("mma.sync.aligned.m16n8k16.row.col.f32.bf16.bf16.f32 "
        "{%0,%1,%2,%3}, {%4,%5,%6,%7}, {%8,%9}, {%0,%1,%2,%3};"
        :"+f"(c[0]),"+f"(c[1]),"+f"(c[2]),"+f"(c[3])
        :"r"(a[0]),"r"(a[1]),"r"(a[2]),"r"(a[3]),"r"(b[0]),"r"(b[1]));
}
__device__ __forceinline__ void cp16(u32 dst, const void* src){
    asm volatile("cp.async.cg.shared.global [%0], [%1], 16;"::"r"(dst),"l"(src));
}

// ---------------- conv kernels: fp32 -> bf16 hi/lo ----------------
__global__ __launch_bounds__(256) void c_convA(const float* __restrict__ people,
                                               const float* __restrict__ objects,
                                               const float* __restrict__ context){
    int idx = blockIdx.x*256 + threadIdx.x;          // 2,228,224 total
    const float* src; __nv_bfloat16 *dh, *dl; int e;
    if (idx < 1048576)      { src = people;  dh = g_peh; dl = g_pel; e = idx; }
    else if (idx < 2097152) { src = objects; dh = g_obh; dl = g_obl; e = idx - 1048576; }
    else                    { src = context; dh = g_cxh; dl = g_cxl; e = idx - 2097152; }
    float v = 0.f;
    if (dh != g_cxh || (e >> 10) < 64) v = src[e];
    __nv_bfloat16 h = __float2bfloat16(v);
    dh[e] = h;
    dl[e] = __float2bfloat16(v - __bfloat162float(h));
}

__global__ __launch_bounds__(256) void c_convB(const float* __restrict__ Wvis_w,
                                               const float* __restrict__ Who_w,
                                               const float* __restrict__ Woh_w){
    __shared__ float t[32][33];
    int bid = blockIdx.x;                           // 3584 tiles
    const float* W; __nv_bfloat16 *dh, *dl; int N, local;
    if (bid < 512)        { W = Wvis_w;            dh = g_Bv0h; dl = g_Bv0l; N = 512;  local = bid;       }
    else if (bid < 1024)  { W = Wvis_w + 1024*512; dh = g_Bv1h; dl = g_Bv1l; N = 512;  local = bid - 512; }
    else if (bid < 1536)  { W = Wvis_w + 2048*512; dh = g_Bv2h; dl = g_Bv2l; N = 512;  local = bid - 1024;}
    else if (bid < 2560)  { W = Who_w;             dh = g_Whoh; dl = g_Whol; N = 1024; local = bid - 1536;}
    else                  { W = Woh_w;             dh = g_Wohh; dl = g_Wohl; N = 1024; local = bid - 2560;}
    int ntN = N >> 5;
    int k0 = (local / ntN) * 32, n0 = (local % ntN) * 32;
    int tid = threadIdx.x;
    #pragma unroll
    for (int i = 0; i < 4; i++) {
        int e = tid + i*256, r = e >> 5, c = e & 31;
        t[r][c] = W[(k0 + r)*N + n0 + c];
    }
    __syncthreads();
    #pragma unroll
    for (int i = 0; i < 4; i++) {
        int e = tid + i*256, r = e >> 5, c = e & 31;   // r = n within, c = k within
        float v = t[c][r];
        __nv_bfloat16 h = __float2bfloat16(v);
        dh[(n0 + r)*1024 + k0 + c] = h;
        dl[(n0 + r)*1024 + k0 + c] = __float2bfloat16(v - __bfloat162float(h));
    }
}

// ---------------- k0: pack head weights into [512,64] ----------------
__global__ __launch_bounds__(256) void k0_pack(const float* __restrict__ Wip_w,
                                               const float* __restrict__ Wref_w,
                                               const float* __restrict__ Watt_w) {
    int idx = blockIdx.x*256 + threadIdx.x;   // 32768 total
    int k = idx >> 6, c = idx & 63;
    float v = 0.f;
    if (c == 0)                  v = Wip_w[k];
    else if (c <= 29)            v = Wref_w[k*29 + c - 1];
    else if (c >= 32 && c <= 60) v = Watt_w[k*29 + c - 32];
    g_Wcat[idx] = v;
}

// ---------------- k1: warp-MMA bf16 3-term split GEMM, cp.async 2-stage ----------------
#define KP 40                        // bf16 pitch per smem row (80B, conflict-free for ldmatrix)
#define TILE_B (128*KP*2)            // 10240 bytes per operand tile
#define STAGE_B (4*TILE_B)           // Ah, Al, Bh, Bl  = 40960
#define K1_SMEM (2*STAGE_B)          // 2 pipeline stages = 81920

__global__ __launch_bounds__(256,2) void k1_mma(
    const float* __restrict__ Wvis_b,
    const float* __restrict__ Who_b,
    const float* __restrict__ Woh_b)
{
    extern __shared__ char smem[];
    u32 sb = smem_u32(smem);
    int tid = threadIdx.x, lane = tid & 31, wid = tid >> 5;
    int wm = wid & 1, wn = wid >> 1;                 // warp tile: rows wm*64, cols wn*32
    int bid = blockIdx.x;

    const __nv_bfloat16 *Ah, *Al, *Bh, *Bl;
    float* C; const float* bias = 0;
    int relu = 0, Mv = 1024, N, mt0, nt0, local;
    if (bid < 32)       { Ah=g_peh; Al=g_pel; Bh=g_Bv0h; Bl=g_Bv0l; C=g_Pvis; N=512;  local=bid;     mt0=local>>2; nt0=local&3; }
    else if (bid < 64)  { Ah=g_obh; Al=g_obl; Bh=g_Bv1h; Bl=g_Bv1l; C=g_Ovis; N=512;  local=bid-32;  mt0=local>>2; nt0=local&3; }
    else if (bid < 68)  { Ah=g_cxh; Al=g_cxl; Bh=g_Bv2h; Bl=g_Bv2l; C=g_Cvis; N=512;  local=bid-64;  mt0=0; nt0=local; bias=Wvis_b; Mv=64; }
    else if (bid < 132) { Ah=g_peh; Al=g_pel; Bh=g_Whoh; Bl=g_Whol; C=g_HO;   N=1024; local=bid-68;  mt0=local>>3; nt0=local&7; bias=Who_b; relu=1; }
    else                { Ah=g_obh; Al=g_obl; Bh=g_Wohh; Bl=g_Wohl; C=g_OH;   N=1024; local=bid-132; mt0=local>>3; nt0=local&7; bias=Woh_b; relu=1; }
    int m0 = mt0 * 128, n0 = nt0 * 128;

    // per-thread load slots (fixed across iterations)
    int l_row = (tid + 0) >> 2,   l_seg = tid & 3;           // slot 0: e = tid
    int l_row2 = (tid + 256) >> 2;                           // slot 1: e = tid+256 (same seg)

    float acc[4][4][4];
    #pragma unroll
    for (int i = 0; i < 4; i++)
        #pragma unroll
        for (int j = 0; j < 4; j++)
            #pragma unroll
            for (int q = 0; q < 4; q++) acc[i][j][q] = 0.f;

    // ldmatrix lane address components
    int lg = lane >> 3, lr = lane & 7;
    int a_row_off = lr + ((lg & 1) << 3);
    int a_k_off   = (lg >> 1) << 3;
    int b_row_off = lr;
    int b_k_off   = (lg & 1) << 3;

    const __nv_bfloat16* srcs[4] = {Ah, Al, Bh, Bl};
    int rbs[4] = {m0, m0, n0, n0};

    // ---- stage loader: issue 8 cp.async (16B each) for chunk kt into stage base ----
    #define LOAD_STAGE(KT, SBS) do {                                                   \
        u32 _s = (SBS);                                                                \
        _Pragma("unroll")                                                              \
        for (int arr = 0; arr < 4; arr++) {                                            \
            const __nv_bfloat16* _src = srcs[arr];                                     \
            int _rb = rbs[arr];                                                        \
            cp16(_s + arr*TILE_B + (l_row*KP + l_seg*8)*2,                             \
                 &_src[(_rb + l_row)*1024 + (KT) + l_seg*8]);                          \
            cp16(_s + arr*TILE_B + (l_row2*KP + l_seg*8)*2,                            \
                 &_src[(_rb + l_row2)*1024 + (KT) + l_seg*8]);                         \
        }                                                                              \
        asm volatile("cp.async.commit_group;");                                        \
    } while(0)

    LOAD_STAGE(0, sb);

    for (int c = 0; c < 32; c++) {
        if (c < 31) {
            LOAD_STAGE((c + 1)*32, sb + ((c + 1) & 1)*STAGE_B);
            asm volatile("cp.async.wait_group 1;");
        } else {
            asm volatile("cp.async.wait_group 0;");
        }
        __syncthreads();

        u32 st  = sb + (c & 1)*STAGE_B;
        u32 sAh = st, sAl = st + TILE_B, sBh = st + 2*TILE_B, sBl = st + 3*TILE_B;

        #pragma unroll
        for (int ks = 0; ks < 32; ks += 16) {
            u32 bh[4][2], bl[4][2];
            #pragma unroll
            for (int nt = 0; nt < 4; nt++) {
                u32 boff = ((wn*32 + nt*8 + b_row_off)*KP + ks + b_k_off) * 2;
                ldm_x2(bh[nt], sBh + boff);
                ldm_x2(bl[nt], sBl + boff);
            }
            #pragma unroll
            for (int mt = 0; mt < 4; mt++) {
                u32 aoff = ((wm*64 + mt*16 + a_row_off)*KP + ks + a_k_off) * 2;
                u32 ah[4], al[4];
                ldm_x4(ah, sAh + aoff);
                ldm_x4(al, sAl + aoff);
                #pragma unroll
                for (int nt = 0; nt < 4; nt++) {
                    mma_bf16(acc[mt][nt], ah, bh[nt]);
                    mma_bf16(acc[mt][nt], ah, bl[nt]);
                    mma_bf16(acc[mt][nt], al, bh[nt]);
                }
            }
        }
        __syncthreads();
    }

    // ---- epilogue ----
    int rq = lane >> 2, cq = (lane & 3) * 2;
    #pragma unroll
    for (int mt = 0; mt < 4; mt++) {
        int gmA = m0 + wm*64 + mt*16 + rq;
        int gmB = gmA + 8;
        #pragma unroll
        for (int nt = 0; nt < 4; nt++) {
            int gn = n0 + wn*32 + nt*8 + cq;
            float b0 = bias ? bias[gn]   : 0.f;
            float b1 = bias ? bias[gn+1] : 0.f;
            float v0 = acc[mt][nt][0] + b0, v1 = acc[mt][nt][1] + b1;
            float v2 = acc[mt][nt][2] + b0, v3 = acc[mt][nt][3] + b1;
            if (relu) { v0=fmaxf(v0,0.f); v1=fmaxf(v1,0.f); v2=fmaxf(v2,0.f); v3=fmaxf(v3,0.f); }
            if (gmA < Mv) *(float2*)&C[gmA*N + gn] = make_float2(v0, v1);
            if (gmB < Mv) *(float2*)&C[gmB*N + gn] = make_float2(v2, v3);
        }
    }
}

// ---------------- k2: fused per-(b,p) kernel: a_ho, f_ref, 3 heads ----------------
#define FA_PITCH 516
#define WT_PITCH 132
#define K2_SMEM ((512 + 32*FA_PITCH + 64*WT_PITCH) * 4)

__global__ __launch_bounds__(256,2) void k2_pairs(
    const float* __restrict__ spatial,
    const float* __restrict__ Wspat_w, const float* __restrict__ Wspat_b,
    const float* __restrict__ Wip_b,   const float* __restrict__ Wref_b,
    const float* __restrict__ Watt_b,  float* __restrict__ out)
{
    extern __shared__ float sm[];
    float* s_sp = sm;                    // 16 x 32
    float* s_fa = sm + 512;              // 32 x 516 (rows 0-15 f_ref, 16-31 a_ho)
    float* s_w  = s_fa + 32*FA_PITCH;    // [64 c][132] transposed weight chunk

    int tid = threadIdx.x;
    int bp = blockIdx.x;                 // (b,p) group, 1024 total
    int b = bp >> 4;

    #pragma unroll
    for (int i = 0; i < 2; i++) s_sp[tid + i*256] = spatial[bp*512 + tid + i*256];
    __syncthreads();

    // phase 1: a_ho + f_ref into smem; each thread owns 2 columns
    for (int jj = 0; jj < 2; jj++) {
        int j = tid + jj*256;
        float wk[32];
        #pragma unroll
        for (int k = 0; k < 32; k++) wk[k] = Wspat_w[k*512 + j];
        float bs = Wspat_b[j];
        float pv = g_Pvis[bp*512 + j];
        float cv = g_Cvis[b*512 + j];
        #pragma unroll 4
        for (int l = 0; l < 16; l++) {
            float acc = bs;
            #pragma unroll
            for (int k = 0; k < 32; k++) acc += s_sp[l*32 + k] * wk[k];
            float a = fmaxf(acc, 0.f);
            float ov = g_Ovis[(b*16 + l)*512 + j];
            float f = fmaxf(pv + ov + cv, 0.f) * a;
            s_fa[l*FA_PITCH + j]        = f;
            s_fa[(16 + l)*FA_PITCH + j] = a;
        }
    }

    // phase 2: rows r<16 (f_ref) need head cols 0..31; rows r>=16 (a_ho) cols 32..63
    int r = tid & 31, cg = tid >> 5;
    int cbase = ((r < 16) ? 0 : 32) + cg*4;
    ull acc2[4] = {0ull, 0ull, 0ull, 0ull};

    for (int kt = 0; kt < 512; kt += 128) {
        __syncthreads();
        #pragma unroll
        for (int i = 0; i < 8; i++) {
            int task = tid + i*256;            // 0..2047
            int cc = task & 63, kq = (task >> 6) << 2;
            float4 w;
            w.x = g_Wcat[(kt + kq + 0)*64 + cc];
            w.y = g_Wcat[(kt + kq + 1)*64 + cc];
            w.z = g_Wcat[(kt + kq + 2)*64 + cc];
            w.w = g_Wcat[(kt + kq + 3)*64 + cc];
            *(float4*)&s_w[cc*WT_PITCH + kq] = w;
        }
        __syncthreads();
        #pragma unroll 8
        for (int k = 0; k < 128; k += 4) {
            ulonglong2 sv = *(const ulonglong2*)&s_fa[r*FA_PITCH + kt + k];
            #pragma unroll
            for (int q = 0; q < 4; q++) {
                ulonglong2 wv = *(const ulonglong2*)&s_w[(cbase + q)*WT_PITCH + k];
                ffma2(acc2[q], sv.x, wv.x);
                ffma2(acc2[q], sv.y, wv.y);
            }
        }
    }

    float res[4];
    #pragma unroll
    for (int q = 0; q < 4; q++) { float2 v = upk(acc2[q]); res[q] = v.x + v.y; }

    if (r < 16) {                       // cols 0..31: i_ho (0) + p_ref (1..29)
        int cidx = bp*16 + r;
        #pragma unroll
        for (int q = 0; q < 4; q++) {
            int c = cbase + q;
            if (c == 0) {
                float v = res[q] + Wip_b[0];
                out[cidx] = v;
                g_adj[cidx] = 1.f / (1.f + expf(-v));
            } else if (c <= 29) {
                out[16384 + cidx*29 + (c - 1)] = res[q] + Wref_b[c - 1];
            }
        }
    } else {                            // cols 32..63: p_att (32..60)
        int cidx = bp*16 + (r - 16);
        #pragma unroll
        for (int q = 0; q < 4; q++) {
            int c32 = cbase + q - 32;
            if (c32 <= 28) {
                out[491520 + cidx*29 + c32] = res[q] + Watt_b[c32];
            }
        }
    }
}

// ---------------- k3a: message passing -> g_PR, g_OBF ----------------
__global__ __launch_bounds__(256) void k3a_msg(const float* __restrict__ people,
                                               const float* __restrict__ objects)
{
    __shared__ float adj[240];
    int b = blockIdx.x >> 2, ch = blockIdx.x & 3;
    int tid = threadIdx.x;
    if (tid < 240) adj[tid] = g_adj[(b*16 + tid/15)*16 + (tid % 15) + 1];
    __syncthreads();

    int d = ch*256 + tid;
    float oh[15], ho[16];
    #pragma unroll
    for (int o = 0; o < 15; o++) oh[o] = g_OH[(b*16 + o + 1)*1024 + d];
    #pragma unroll
    for (int p = 0; p < 16; p++) ho[p] = g_HO[(b*16 + p)*1024 + d];

    #pragma unroll
    for (int p = 0; p < 16; p++) {
        float acc = people[(b*16 + p)*1024 + d];
        #pragma unroll
        for (int o = 0; o < 15; o++) acc += adj[p*15 + o] * oh[o];
        g_PR[(b*16 + p)*1024 + d] = acc;
    }
    g_OBF[(b*16)*1024 + d] = objects[(b*16)*1024 + d];
    #pragma unroll
    for (int o = 0; o < 15; o++) {
        float acc = objects[(b*16 + o + 1)*1024 + d];
        #pragma unroll
        for (int p = 0; p < 16; p++) acc += adj[p*15 + o] * ho[p];
        g_OBF[(b*16 + o + 1)*1024 + d] = acc;
    }
}

// ---------------- k3b: skinny GEMM [2048,1024]@[1024,29] warp-per-row ----------------
__global__ __launch_bounds__(256) void k3b_gemm(const float* __restrict__ Wg_w,
                                                const float* __restrict__ Wg_b)
{
    __shared__ float Ws[256*33];
    int half = blockIdx.x >> 7;
    int row = (blockIdx.x & 127)*8 + (threadIdx.x >> 5);
    int lane = threadIdx.x & 31;
    const float* src = half ? g_OBF : g_PR;
    const float* W = Wg_w + half*1024*29;
    float* dst = half ? g_Go : g_Gp;

    float acc[29];
    #pragma unroll
    for (int a = 0; a < 29; a++) acc[a] = 0.f;

    for (int kt = 0; kt < 4; kt++) {
        __syncthreads();
        #pragma unroll
        for (int i = 0; i < 29; i++) {
            int idx = threadIdx.x + i*256;
            int k = idx / 29, a = idx - k*29;
            Ws[k*33 + a] = W[kt*7424 + idx];
        }
        __syncthreads();
        #pragma unroll
        for (int t = 0; t < 8; t++) {
            int k = t*32 + lane;
            float rv = src[row*1024 + kt*256 + k];
            #pragma unroll
            for (int a = 0; a < 29; a++) acc[a] += rv * Ws[k*33 + a];
        }
    }
    #pragma unroll
    for (int off = 16; off; off >>= 1)
        #pragma unroll
        for (int a = 0; a < 29; a++)
            acc[a] += __shfl_down_sync(0xffffffffu, acc[a], off);
    if (lane == 0) {
        #pragma unroll
        for (int a = 0; a < 29; a++)
            dst[row*29 + a] = acc[a] + (half ? Wg_b[a] : 0.f);
    }
}

// ---------------- k3c: broadcast add -> p_graph ----------------
__global__ __launch_bounds__(256) void k3c_add(float* __restrict__ out_pg)
{
    int idx = blockIdx.x*256 + threadIdx.x;        // 475136 total, exact
    int c = idx / 29;
    int a = idx - c*29;
    int prow = c >> 4;
    int lrow = (c >> 8)*16 + (c & 15);
    out_pg[idx] = g_Gp[prow*29 + a] + g_Go[lrow*29 + a];
}

// ---------------- launch ----------------
extern "C" void kernel_launch(void* const* d_in, const int* in_sizes, int n_in,
                              void* d_out, int out_size) {
    const float* people  = (const float*)d_in[0];
    const float* objects = (const float*)d_in[1];
    const float* context = (const float*)d_in[2];
    const float* spatial = (const float*)d_in[3];
    const float* Wvis_w  = (const float*)d_in[4];
    const float* Wvis_b  = (const float*)d_in[5];
    const float* Wspat_w = (const float*)d_in[6];
    const float* Wspat_b = (const float*)d_in[7];
    const float* Wip_w   = (const float*)d_in[8];
    const float* Wip_b   = (const float*)d_in[9];
    const float* Wref_w  = (const float*)d_in[10];
    const float* Wref_b  = (const float*)d_in[11];
    const float* Watt_w  = (const float*)d_in[12];
    const float* Watt_b  = (const float*)d_in[13];
    const float* Woh_w   = (const float*)d_in[14];
    const float* Woh_b   = (const float*)d_in[15];
    const float* Who_w   = (const float*)d_in[16];
    const float* Who_b   = (const float*)d_in[17];
    const float* Wg_w    = (const float*)d_in[18];
    const float* Wg_b    = (const float*)d_in[19];
    float* out = (float*)d_out;

    cudaFuncSetAttribute(k1_mma,  cudaFuncAttributeMaxDynamicSharedMemorySize, K1_SMEM);
    cudaFuncSetAttribute(k2_pairs, cudaFuncAttributeMaxDynamicSharedMemorySize, K2_SMEM);

    c_convA<<<8704, 256>>>(people, objects, context);
    c_convB<<<3584, 256>>>(Wvis_w, Who_w, Woh_w);
    k0_pack<<<128, 256>>>(Wip_w, Wref_w, Watt_w);
    k1_mma<<<196, 256, K1_SMEM>>>(Wvis_b, Who_b, Woh_b);
    k2_pairs<<<1024, 256, K2_SMEM>>>(spatial, Wspat_w, Wspat_b,
                                     Wip_b, Wref_b, Watt_b, out);
    k3a_msg<<<256, 256>>>(people, objects);
    k3b_gemm<<<256, 256>>>(Wg_w, Wg_b);
    k3c_add<<<1856, 256>>>(out + 966656);
}

// round 7
// speedup vs baseline: 2.1791x; 1.2768x over previous
#include <cuda_runtime.h>
#include <cuda_bf16.h>
#include <math.h>

typedef unsigned long long ull;
typedef unsigned int u32;

// ---------------- device scratch (allocations are forbidden) ----------------
__device__ float g_Pvis[1024*512];   // people  @ Wvis[0:1024]
__device__ float g_Ovis[1024*512];   // objects @ Wvis[1024:2048]
__device__ float g_Cvis[64*512];     // context @ Wvis[2048:3072] + Wvis_b
__device__ float g_HO[1024*1024];    // relu(people  @ Who + b)
__device__ float g_OH[1024*1024];    // relu(objects @ Woh + b)
__device__ float g_adj[16384];       // sigmoid(i_ho)
__device__ float g_PR[1024*1024];    // people_r
__device__ float g_OBF[1024*1024];   // objects_full
__device__ float g_Gp[1024*29];
__device__ float g_Go[1024*29];

// packed head weights, bf16 hi/lo, [c=64][k=512]
__device__ __nv_bfloat16 g_Wcath[64*512], g_Wcatl[64*512];

// bf16 hi/lo pre-converted operands for k1
__device__ __nv_bfloat16 g_peh[1024*1024], g_pel[1024*1024];
__device__ __nv_bfloat16 g_obh[1024*1024], g_obl[1024*1024];
__device__ __nv_bfloat16 g_cxh[128*1024],  g_cxl[128*1024];     // padded to 128 rows
__device__ __nv_bfloat16 g_Bv0h[512*1024], g_Bv0l[512*1024];    // Wvis[0:1024]^T  [n][k]
__device__ __nv_bfloat16 g_Bv1h[512*1024], g_Bv1l[512*1024];    // Wvis[1024:2048]^T
__device__ __nv_bfloat16 g_Bv2h[512*1024], g_Bv2l[512*1024];    // Wvis[2048:3072]^T
__device__ __nv_bfloat16 g_Whoh[1024*1024], g_Whol[1024*1024];  // Who^T
__device__ __nv_bfloat16 g_Wohh[1024*1024], g_Wohl[1024*1024];  // Woh^T

// ---------------- small helpers ----------------
__device__ __forceinline__ u32 smem_u32(const void* p){
    u32 a; asm("{ .reg .u64 t; cvta.to.shared.u64 t, %1; cvt.u32.u64 %0, t; }":"=r"(a):"l"(p)); return a;
}
__device__ __forceinline__ void ldm_x4(u32* r, u32 addr){
    asm volatile("ldmatrix.sync.aligned.m8n8.x4.shared.b16 {%0,%1,%2,%3}, [%4];"
        :"=r"(r[0]),"=r"(r[1]),"=r"(r[2]),"=r"(r[3]):"r"(addr));
}
__device__ __forceinline__ void ldm_x2(u32* r, u32 addr){
    asm volatile("ldmatrix.sync.aligned.m8n8.x2.shared.b16 {%0,%1}, [%2];"
        :"=r"(r[0]),"=r"(r[1]):"r"(addr));
}
__device__ __forceinline__ void mma_bf16(float* c, const u32* a, const u32* b){
    asm volatile("mma.sync.aligned.m16n8k16.row.col.f32.bf16.bf16.f32 "
        "{%0,%1,%2,%3}, {%4,%5,%6,%7}, {%8,%9}, {%0,%1,%2,%3};"
        :"+f"(c[0]),"+f"(c[1]),"+f"(c[2]),"+f"(c[3])
        :"r"(a[0]),"r"(a[1]),"r"(a[2]),"r"(a[3]),"r"(b[0]),"r"(b[1]));
}
__device__ __forceinline__ void cp16(u32 dst, const void* src){
    asm volatile("cp.async.cg.shared.global [%0], [%1], 16;"::"r"(dst),"l"(src));
}

// ---------------- conv kernels: fp32 -> bf16 hi/lo ----------------
__global__ __launch_bounds__(256) void c_convA(const float* __restrict__ people,
                                               const float* __restrict__ objects,
                                               const float* __restrict__ context){
    int idx = blockIdx.x*256 + threadIdx.x;          // 2,228,224 total
    const float* src; __nv_bfloat16 *dh, *dl; int e;
    if (idx < 1048576)      { src = people;  dh = g_peh; dl = g_pel; e = idx; }
    else if (idx < 2097152) { src = objects; dh = g_obh; dl = g_obl; e = idx - 1048576; }
    else                    { src = context; dh = g_cxh; dl = g_cxl; e = idx - 2097152; }
    float v = 0.f;
    if (dh != g_cxh || (e >> 10) < 64) v = src[e];
    __nv_bfloat16 h = __float2bfloat16(v);
    dh[e] = h;
    dl[e] = __float2bfloat16(v - __bfloat162float(h));
}

__global__ __launch_bounds__(256) void c_convB(const float* __restrict__ Wvis_w,
                                               const float* __restrict__ Who_w,
                                               const float* __restrict__ Woh_w){
    __shared__ float t[32][33];
    int bid = blockIdx.x;                           // 3584 tiles
    const float* W; __nv_bfloat16 *dh, *dl; int N, local;
    if (bid < 512)        { W = Wvis_w;            dh = g_Bv0h; dl = g_Bv0l; N = 512;  local = bid;       }
    else if (bid < 1024)  { W = Wvis_w + 1024*512; dh = g_Bv1h; dl = g_Bv1l; N = 512;  local = bid - 512; }
    else if (bid < 1536)  { W = Wvis_w + 2048*512; dh = g_Bv2h; dl = g_Bv2l; N = 512;  local = bid - 1024;}
    else if (bid < 2560)  { W = Who_w;             dh = g_Whoh; dl = g_Whol; N = 1024; local = bid - 1536;}
    else                  { W = Woh_w;             dh = g_Wohh; dl = g_Wohl; N = 1024; local = bid - 2560;}
    int ntN = N >> 5;
    int k0 = (local / ntN) * 32, n0 = (local % ntN) * 32;
    int tid = threadIdx.x;
    #pragma unroll
    for (int i = 0; i < 4; i++) {
        int e = tid + i*256, r = e >> 5, c = e & 31;
        t[r][c] = W[(k0 + r)*N + n0 + c];
    }
    __syncthreads();
    #pragma unroll
    for (int i = 0; i < 4; i++) {
        int e = tid + i*256, r = e >> 5, c = e & 31;   // r = n within, c = k within
        float v = t[c][r];
        __nv_bfloat16 h = __float2bfloat16(v);
        dh[(n0 + r)*1024 + k0 + c] = h;
        dl[(n0 + r)*1024 + k0 + c] = __float2bfloat16(v - __bfloat162float(h));
    }
}

// ---------------- k0: pack head weights -> bf16 hi/lo [c=64][k=512] ----------------
__global__ __launch_bounds__(256) void k0_pack(const float* __restrict__ Wip_w,
                                               const float* __restrict__ Wref_w,
                                               const float* __restrict__ Watt_w) {
    int idx = blockIdx.x*256 + threadIdx.x;   // 32768 total
    int c = idx >> 9, k = idx & 511;
    float v = 0.f;
    if (c == 0)                  v = Wip_w[k];
    else if (c <= 29)            v = Wref_w[k*29 + c - 1];
    else if (c >= 32 && c <= 60) v = Watt_w[k*29 + c - 32];
    __nv_bfloat16 h = __float2bfloat16(v);
    g_Wcath[idx] = h;
    g_Wcatl[idx] = __float2bfloat16(v - __bfloat162float(h));
}

// ---------------- k1: warp-MMA bf16 3-term split GEMM, 128x64 tiles ----------------
#define KP 40                        // bf16 pitch per smem row (80B, conflict-free)
#define TA (128*KP*2)                // 10240 bytes (A tile, one of h/l)
#define TB (64*KP*2)                 // 5120 bytes  (B tile, one of h/l)
#define STAGE_B (2*TA + 2*TB)        // 30720
#define K1_SMEM (2*STAGE_B)          // 61440

__global__ __launch_bounds__(128,3) void k1_mma(
    const float* __restrict__ Wvis_b,
    const float* __restrict__ Who_b,
    const float* __restrict__ Woh_b)
{
    extern __shared__ char smem[];
    u32 sb = smem_u32(smem);
    int tid = threadIdx.x, lane = tid & 31, wid = tid >> 5;
    int wm = wid & 1, wn = wid >> 1;                 // warp tile: rows wm*64, cols wn*32
    int bid = blockIdx.x;                            // 392 tiles of 128x64

    const __nv_bfloat16 *Ah, *Al, *Bh, *Bl;
    float* C; const float* bias = 0;
    int relu = 0, Mv = 1024, N, mt0, nt0, local;
    if (bid < 64)       { Ah=g_peh; Al=g_pel; Bh=g_Bv0h; Bl=g_Bv0l; C=g_Pvis; N=512;  local=bid;     mt0=local>>3; nt0=local&7; }
    else if (bid < 128) { Ah=g_obh; Al=g_obl; Bh=g_Bv1h; Bl=g_Bv1l; C=g_Ovis; N=512;  local=bid-64;  mt0=local>>3; nt0=local&7; }
    else if (bid < 136) { Ah=g_cxh; Al=g_cxl; Bh=g_Bv2h; Bl=g_Bv2l; C=g_Cvis; N=512;  local=bid-128; mt0=0; nt0=local; bias=Wvis_b; Mv=64; }
    else if (bid < 264) { Ah=g_peh; Al=g_pel; Bh=g_Whoh; Bl=g_Whol; C=g_HO;   N=1024; local=bid-136; mt0=local>>4; nt0=local&15; bias=Who_b; relu=1; }
    else                { Ah=g_obh; Al=g_obl; Bh=g_Wohh; Bl=g_Wohl; C=g_OH;   N=1024; local=bid-264; mt0=local>>4; nt0=local&15; bias=Woh_b; relu=1; }
    int m0 = mt0 * 128, n0 = nt0 * 64;

    float acc[4][4][4];
    #pragma unroll
    for (int i = 0; i < 4; i++)
        #pragma unroll
        for (int j = 0; j < 4; j++)
            #pragma unroll
            for (int q = 0; q < 4; q++) acc[i][j][q] = 0.f;

    // ldmatrix lane address components
    int lg = lane >> 3, lr = lane & 7;
    int a_row_off = lr + ((lg & 1) << 3);
    int a_k_off   = (lg >> 1) << 3;
    int b_row_off = lr;
    int b_k_off   = (lg & 1) << 3;

    // stage loader: A 128x32 (h,l) + B 64x32 (h,l), 12 cp16 per thread
    #define LOAD_STAGE(KT, S) do {                                                    \
        u32 _s = (S); int _kt = (KT);                                                 \
        _Pragma("unroll")                                                             \
        for (int i = 0; i < 4; i++) {                                                 \
            int e = tid + i*128, row = e >> 2, sg = (e & 3) * 8;                      \
            cp16(_s      + (row*KP + sg)*2, &Ah[(m0 + row)*1024 + _kt + sg]);         \
            cp16(_s + TA + (row*KP + sg)*2, &Al[(m0 + row)*1024 + _kt + sg]);         \
        }                                                                             \
        _Pragma("unroll")                                                             \
        for (int i = 0; i < 2; i++) {                                                 \
            int e = tid + i*128, row = e >> 2, sg = (e & 3) * 8;                      \
            cp16(_s + 2*TA      + (row*KP + sg)*2, &Bh[(n0 + row)*1024 + _kt + sg]);  \
            cp16(_s + 2*TA + TB + (row*KP + sg)*2, &Bl[(n0 + row)*1024 + _kt + sg]);  \
        }                                                                             \
        asm volatile("cp.async.commit_group;");                                       \
    } while(0)

    LOAD_STAGE(0, sb);

    for (int c = 0; c < 32; c++) {
        if (c < 31) {
            LOAD_STAGE((c + 1)*32, sb + ((c + 1) & 1)*STAGE_B);
            asm volatile("cp.async.wait_group 1;");
        } else {
            asm volatile("cp.async.wait_group 0;");
        }
        __syncthreads();

        u32 st  = sb + (c & 1)*STAGE_B;
        u32 sAh = st, sAl = st + TA, sBh = st + 2*TA, sBl = st + 2*TA + TB;

        #pragma unroll
        for (int ks = 0; ks < 32; ks += 16) {
            u32 bh[4][2], bl[4][2];
            #pragma unroll
            for (int nt = 0; nt < 4; nt++) {
                u32 boff = ((wn*32 + nt*8 + b_row_off)*KP + ks + b_k_off) * 2;
                ldm_x2(bh[nt], sBh + boff);
                ldm_x2(bl[nt], sBl + boff);
            }
            #pragma unroll
            for (int mt = 0; mt < 4; mt++) {
                u32 aoff = ((wm*64 + mt*16 + a_row_off)*KP + ks + a_k_off) * 2;
                u32 ah[4], al[4];
                ldm_x4(ah, sAh + aoff);
                ldm_x4(al, sAl + aoff);
                #pragma unroll
                for (int nt = 0; nt < 4; nt++) {
                    mma_bf16(acc[mt][nt], ah, bh[nt]);
                    mma_bf16(acc[mt][nt], ah, bl[nt]);
                    mma_bf16(acc[mt][nt], al, bh[nt]);
                }
            }
        }
        __syncthreads();
    }

    // ---- epilogue ----
    int rq = lane >> 2, cq = (lane & 3) * 2;
    #pragma unroll
    for (int mt = 0; mt < 4; mt++) {
        int gmA = m0 + wm*64 + mt*16 + rq;
        int gmB = gmA + 8;
        #pragma unroll
        for (int nt = 0; nt < 4; nt++) {
            int gn = n0 + wn*32 + nt*8 + cq;
            float b0 = bias ? bias[gn]   : 0.f;
            float b1 = bias ? bias[gn+1] : 0.f;
            float v0 = acc[mt][nt][0] + b0, v1 = acc[mt][nt][1] + b1;
            float v2 = acc[mt][nt][2] + b0, v3 = acc[mt][nt][3] + b1;
            if (relu) { v0=fmaxf(v0,0.f); v1=fmaxf(v1,0.f); v2=fmaxf(v2,0.f); v3=fmaxf(v3,0.f); }
            if (gmA < Mv) *(float2*)&C[gmA*N + gn] = make_float2(v0, v1);
            if (gmB < Mv) *(float2*)&C[gmB*N + gn] = make_float2(v2, v3);
        }
    }
}

// ---------------- k2: fused per-(b,p): scalar a_ho/f_ref + MMA heads ----------------
#define K2P 520                       // bf16 pitch of s_fa rows (conflict-free ldmatrix)
#define K2_OFF_FAH 2048
#define K2_OFF_FAL 35328
#define K2_OFF_WH  68608
#define K2_OFF_WL  86016
#define K2_SMEM    103424

__global__ __launch_bounds__(256,2) void k2_pairs(
    const float* __restrict__ spatial,
    const float* __restrict__ Wspat_w, const float* __restrict__ Wspat_b,
    const float* __restrict__ Wip_b,   const float* __restrict__ Wref_b,
    const float* __restrict__ Watt_b,  float* __restrict__ out)
{
    extern __shared__ char sm2[];
    float* s_sp = (float*)sm2;                                   // 512 floats
    __nv_bfloat16* s_fah = (__nv_bfloat16*)(sm2 + K2_OFF_FAH);   // [32][520]
    __nv_bfloat16* s_fal = (__nv_bfloat16*)(sm2 + K2_OFF_FAL);
    __nv_bfloat16* s_wh  = (__nv_bfloat16*)(sm2 + K2_OFF_WH);    // [64][136]
    __nv_bfloat16* s_wl  = (__nv_bfloat16*)(sm2 + K2_OFF_WL);

    int tid = threadIdx.x;
    int bp = blockIdx.x;                 // (b,p), 1024 blocks
    int b = bp >> 4;

    #pragma unroll
    for (int i = 0; i < 2; i++) s_sp[tid + i*256] = spatial[bp*512 + tid + i*256];
    __syncthreads();

    // ---- phase 1: scalar a_ho + f_ref, written as bf16 hi/lo ----
    for (int jj = 0; jj < 2; jj++) {
        int j = tid + jj*256;
        float wk[32];
        #pragma unroll
        for (int k = 0; k < 32; k++) wk[k] = Wspat_w[k*512 + j];
        float bs = Wspat_b[j];
        float pv = g_Pvis[bp*512 + j];
        float cv = g_Cvis[b*512 + j];
        #pragma unroll 4
        for (int l = 0; l < 16; l++) {
            float acc = bs;
            #pragma unroll
            for (int k = 0; k < 32; k++) acc += s_sp[l*32 + k] * wk[k];
            float a = fmaxf(acc, 0.f);
            float ov = g_Ovis[(b*16 + l)*512 + j];
            float f = fmaxf(pv + ov + cv, 0.f) * a;
            __nv_bfloat16 fh = __float2bfloat16(f);
            __nv_bfloat16 ah = __float2bfloat16(a);
            s_fah[l*K2P + j]        = fh;
            s_fal[l*K2P + j]        = __float2bfloat16(f - __bfloat162float(fh));
            s_fah[(16 + l)*K2P + j] = ah;
            s_fal[(16 + l)*K2P + j] = __float2bfloat16(a - __bfloat162float(ah));
        }
    }

    // ---- phase 2: [32 rows] @ heads via bf16 3-term MMA ----
    int lane = tid & 31, wid = tid >> 5;
    int mt = wid >> 2;                   // 0: f_ref rows 0..15, 1: a_ho rows 16..31
    int ntile = (wid & 3) + mt*4;        // cols ntile*8 .. +7  (f_ref -> 0..31, a_ho -> 32..63)

    u32 base_fah = smem_u32(s_fah), base_fal = smem_u32(s_fal);
    u32 base_wh  = smem_u32(s_wh),  base_wl  = smem_u32(s_wl);

    int lg = lane >> 3, lr = lane & 7;
    int a_row = mt*16 + lr + ((lg & 1) << 3);
    int a_koff = (lg >> 1) << 3;
    int b_row = ntile*8 + lr;
    int b_koff = (lg & 1) << 3;

    float acc2[4] = {0.f, 0.f, 0.f, 0.f};

    for (int kc = 0; kc < 4; kc++) {
        __syncthreads();
        // load head-weight chunk [64 c][128 k] h/l
        #pragma unroll
        for (int i = 0; i < 4; i++) {
            int e = tid + i*256;            // 0..1023
            int c = e >> 4, k8 = (e & 15) << 3;
            *(uint4*)&s_wh[c*136 + k8] = *(const uint4*)&g_Wcath[c*512 + kc*128 + k8];
            *(uint4*)&s_wl[c*136 + k8] = *(const uint4*)&g_Wcatl[c*512 + kc*128 + k8];
        }
        __syncthreads();
        #pragma unroll
        for (int ks = 0; ks < 128; ks += 16) {
            u32 ah[4], al[4], bh[2], bl[2];
            ldm_x4(ah, base_fah + (a_row*K2P + kc*128 + ks + a_koff)*2);
            ldm_x4(al, base_fal + (a_row*K2P + kc*128 + ks + a_koff)*2);
            ldm_x2(bh, base_wh + (b_row*136 + ks + b_koff)*2);
            ldm_x2(bl, base_wl + (b_row*136 + ks + b_koff)*2);
            mma_bf16(acc2, ah, bh);
            mma_bf16(acc2, ah, bl);
            mma_bf16(acc2, al, bh);
        }
    }

    // ---- outputs ----
    int r0 = mt*16 + (lane >> 2);
    int c0 = ntile*8 + (lane & 3)*2;
    #pragma unroll
    for (int q = 0; q < 4; q++) {
        int r = r0 + ((q >> 1) << 3);    // +8 for q=2,3
        int c = c0 + (q & 1);
        float v = acc2[q];
        if (r < 16) {                    // f_ref rows: i_ho + p_ref
            int cidx = bp*16 + r;
            if (c == 0) {
                v += Wip_b[0];
                out[cidx] = v;
                g_adj[cidx] = 1.f / (1.f + expf(-v));
            } else if (c <= 29) {
                out[16384 + cidx*29 + (c - 1)] = v + Wref_b[c - 1];
            }
        } else {                         // a_ho rows: p_att (cols 32..60)
            int cidx = bp*16 + (r - 16);
            int cc = c - 32;
            if (cc >= 0 && cc <= 28) {
                out[491520 + cidx*29 + cc] = v + Watt_b[cc];
            }
        }
    }
}

// ---------------- k3a: message passing -> g_PR, g_OBF ----------------
__global__ __launch_bounds__(256) void k3a_msg(const float* __restrict__ people,
                                               const float* __restrict__ objects)
{
    __shared__ float adj[240];
    int b = blockIdx.x >> 2, ch = blockIdx.x & 3;
    int tid = threadIdx.x;
    if (tid < 240) adj[tid] = g_adj[(b*16 + tid/15)*16 + (tid % 15) + 1];
    __syncthreads();

    int d = ch*256 + tid;
    float oh[15], ho[16];
    #pragma unroll
    for (int o = 0; o < 15; o++) oh[o] = g_OH[(b*16 + o + 1)*1024 + d];
    #pragma unroll
    for (int p = 0; p < 16; p++) ho[p] = g_HO[(b*16 + p)*1024 + d];

    #pragma unroll
    for (int p = 0; p < 16; p++) {
        float acc = people[(b*16 + p)*1024 + d];
        #pragma unroll
        for (int o = 0; o < 15; o++) acc += adj[p*15 + o] * oh[o];
        g_PR[(b*16 + p)*1024 + d] = acc;
    }
    g_OBF[(b*16)*1024 + d] = objects[(b*16)*1024 + d];
    #pragma unroll
    for (int o = 0; o < 15; o++) {
        float acc = objects[(b*16 + o + 1)*1024 + d];
        #pragma unroll
        for (int p = 0; p < 16; p++) acc += adj[p*15 + o] * ho[p];
        g_OBF[(b*16 + o + 1)*1024 + d] = acc;
    }
}

// ---------------- k3b: skinny GEMM [2048,1024]@[1024,29] warp-per-row ----------------
__global__ __launch_bounds__(256) void k3b_gemm(const float* __restrict__ Wg_w,
                                                const float* __restrict__ Wg_b)
{
    __shared__ float Ws[256*33];
    int half = blockIdx.x >> 7;
    int row = (blockIdx.x & 127)*8 + (threadIdx.x >> 5);
    int lane = threadIdx.x & 31;
    const float* src = half ? g_OBF : g_PR;
    const float* W = Wg_w + half*1024*29;
    float* dst = half ? g_Go : g_Gp;

    float acc[29];
    #pragma unroll
    for (int a = 0; a < 29; a++) acc[a] = 0.f;

    for (int kt = 0; kt < 4; kt++) {
        __syncthreads();
        #pragma unroll
        for (int i = 0; i < 29; i++) {
            int idx = threadIdx.x + i*256;
            int k = idx / 29, a = idx - k*29;
            Ws[k*33 + a] = W[kt*7424 + idx];
        }
        __syncthreads();
        #pragma unroll
        for (int t = 0; t < 8; t++) {
            int k = t*32 + lane;
            float rv = src[row*1024 + kt*256 + k];
            #pragma unroll
            for (int a = 0; a < 29; a++) acc[a] += rv * Ws[k*33 + a];
        }
    }
    #pragma unroll
    for (int off = 16; off; off >>= 1)
        #pragma unroll
        for (int a = 0; a < 29; a++)
            acc[a] += __shfl_down_sync(0xffffffffu, acc[a], off);
    if (lane == 0) {
        #pragma unroll
        for (int a = 0; a < 29; a++)
            dst[row*29 + a] = acc[a] + (half ? Wg_b[a] : 0.f);
    }
}

// ---------------- k3c: broadcast add -> p_graph ----------------
__global__ __launch_bounds__(256) void k3c_add(float* __restrict__ out_pg)
{
    int idx = blockIdx.x*256 + threadIdx.x;        // 475136 total, exact
    int c = idx / 29;
    int a = idx - c*29;
    int prow = c >> 4;
    int lrow = (c >> 8)*16 + (c & 15);
    out_pg[idx] = g_Gp[prow*29 + a] + g_Go[lrow*29 + a];
}

// ---------------- launch ----------------
extern "C" void kernel_launch(void* const* d_in, const int* in_sizes, int n_in,
                              void* d_out, int out_size) {
    const float* people  = (const float*)d_in[0];
    const float* objects = (const float*)d_in[1];
    const float* context = (const float*)d_in[2];
    const float* spatial = (const float*)d_in[3];
    const float* Wvis_w  = (const float*)d_in[4];
    const float* Wvis_b  = (const float*)d_in[5];
    const float* Wspat_w = (const float*)d_in[6];
    const float* Wspat_b = (const float*)d_in[7];
    const float* Wip_w   = (const float*)d_in[8];
    const float* Wip_b   = (const float*)d_in[9];
    const float* Wref_w  = (const float*)d_in[10];
    const float* Wref_b  = (const float*)d_in[11];
    const float* Watt_w  = (const float*)d_in[12];
    const float* Watt_b  = (const float*)d_in[13];
    const float* Woh_w   = (const float*)d_in[14];
    const float* Woh_b   = (const float*)d_in[15];
    const float* Who_w   = (const float*)d_in[16];
    const float* Who_b   = (const float*)d_in[17];
    const float* Wg_w    = (const float*)d_in[18];
    const float* Wg_b    = (const float*)d_in[19];
    float* out = (float*)d_out;

    cudaFuncSetAttribute(k1_mma,  cudaFuncAttributeMaxDynamicSharedMemorySize, K1_SMEM);
    cudaFuncSetAttribute(k2_pairs, cudaFuncAttributeMaxDynamicSharedMemorySize, K2_SMEM);

    c_convA<<<8704, 256>>>(people, objects, context);
    c_convB<<<3584, 256>>>(Wvis_w, Who_w, Woh_w);
    k0_pack<<<128, 256>>>(Wip_w, Wref_w, Watt_w);
    k1_mma<<<392, 128, K1_SMEM>>>(Wvis_b, Who_b, Woh_b);
    k2_pairs<<<1024, 256, K2_SMEM>>>(spatial, Wspat_w, Wspat_b,
                                     Wip_b, Wref_b, Watt_b, out);
    k3a_msg<<<256, 256>>>(people, objects);
    k3b_gemm<<<256, 256>>>(Wg_w, Wg_b);
    k3c_add<<<1856, 256>>>(out + 966656);
}

// round 8
// speedup vs baseline: 2.2453x; 1.0303x over previous
#include <cuda_runtime.h>
#include <cuda_bf16.h>
#include <math.h>

typedef unsigned long long ull;
typedef unsigned int u32;

// ---------------- device scratch (allocations are forbidden) ----------------
__device__ float g_Pvis[1024*512];   // people  @ Wvis[0:1024]
__device__ float g_Ovis[1024*512];   // objects @ Wvis[1024:2048]
__device__ float g_Cvis[64*512];     // context @ Wvis[2048:3072] + Wvis_b
__device__ float g_HO[1024*1024];    // relu(people  @ Who + b)
__device__ float g_OH[1024*1024];    // relu(objects @ Woh + b)
__device__ float g_adj[16384];       // sigmoid(i_ho)
__device__ float g_PR[1024*1024];    // people_r
__device__ float g_OBF[1024*1024];   // objects_full
__device__ float g_Gp[1024*29];
__device__ float g_Go[1024*29];

// packed head weights, bf16 hi/lo, [c=64][k=512]
__device__ __nv_bfloat16 g_Wcath[64*512], g_Wcatl[64*512];

// bf16 hi/lo pre-converted operands for k1
__device__ __nv_bfloat16 g_peh[1024*1024], g_pel[1024*1024];
__device__ __nv_bfloat16 g_obh[1024*1024], g_obl[1024*1024];
__device__ __nv_bfloat16 g_cxh[128*1024],  g_cxl[128*1024];     // padded to 128 rows
__device__ __nv_bfloat16 g_Bv0h[512*1024], g_Bv0l[512*1024];    // Wvis[0:1024]^T  [n][k]
__device__ __nv_bfloat16 g_Bv1h[512*1024], g_Bv1l[512*1024];    // Wvis[1024:2048]^T
__device__ __nv_bfloat16 g_Bv2h[512*1024], g_Bv2l[512*1024];    // Wvis[2048:3072]^T
__device__ __nv_bfloat16 g_Whoh[1024*1024], g_Whol[1024*1024];  // Who^T
__device__ __nv_bfloat16 g_Wohh[1024*1024], g_Wohl[1024*1024];  // Woh^T

// ---------------- small helpers ----------------
__device__ __forceinline__ u32 smem_u32(const void* p){
    u32 a; asm("{ .reg .u64 t; cvta.to.shared.u64 t, %1; cvt.u32.u64 %0, t; }":"=r"(a):"l"(p)); return a;
}
__device__ __forceinline__ void ldm_x4(u32* r, u32 addr){
    asm volatile("ldmatrix.sync.aligned.m8n8.x4.shared.b16 {%0,%1,%2,%3}, [%4];"
        :"=r"(r[0]),"=r"(r[1]),"=r"(r[2]),"=r"(r[3]):"r"(addr));
}
__device__ __forceinline__ void ldm_x2(u32* r, u32 addr){
    asm volatile("ldmatrix.sync.aligned.m8n8.x2.shared.b16 {%0,%1}, [%2];"
        :"=r"(r[0]),"=r"(r[1]):"r"(addr));
}
__device__ __forceinline__ void mma_bf16(float* c, const u32* a, const u32* b){
    asm volatile("mma.sync.aligned.m16n8k16.row.col.f32.bf16.bf16.f32 "
        "{%0,%1,%2,%3}, {%4,%5,%6,%7}, {%8,%9}, {%0,%1,%2,%3};"
        :"+f"(c[0]),"+f"(c[1]),"+f"(c[2]),"+f"(c[3])
        :"r"(a[0]),"r"(a[1]),"r"(a[2]),"r"(a[3]),"r"(b[0]),"r"(b[1]));
}
__device__ __forceinline__ void cp16(u32 dst, const void* src){
    asm volatile("cp.async.cg.shared.global [%0], [%1], 16;"::"r"(dst),"l"(src));
}

// ---------------- c_prep: fused convA + convB + head-weight pack ----------------
__global__ __launch_bounds__(256) void c_prep(
    const float* __restrict__ people, const float* __restrict__ objects,
    const float* __restrict__ context,
    const float* __restrict__ Wvis_w, const float* __restrict__ Who_w,
    const float* __restrict__ Woh_w,
    const float* __restrict__ Wip_w,  const float* __restrict__ Wref_w,
    const float* __restrict__ Watt_w)
{
    __shared__ float t[32][33];
    int bid = blockIdx.x;
    int tid = threadIdx.x;

    if (bid < 8704) {                                 // ---- convA ----
        int idx = bid*256 + tid;
        const float* src; __nv_bfloat16 *dh, *dl; int e;
        if (idx < 1048576)      { src = people;  dh = g_peh; dl = g_pel; e = idx; }
        else if (idx < 2097152) { src = objects; dh = g_obh; dl = g_obl; e = idx - 1048576; }
        else                    { src = context; dh = g_cxh; dl = g_cxl; e = idx - 2097152; }
        float v = 0.f;
        if (dh != g_cxh || (e >> 10) < 64) v = src[e];
        __nv_bfloat16 h = __float2bfloat16(v);
        dh[e] = h;
        dl[e] = __float2bfloat16(v - __bfloat162float(h));
    } else if (bid < 12288) {                         // ---- convB (transpose) ----
        int lb = bid - 8704;                          // 3584 tiles
        const float* W; __nv_bfloat16 *dh, *dl; int N, local;
        if (lb < 512)        { W = Wvis_w;            dh = g_Bv0h; dl = g_Bv0l; N = 512;  local = lb;       }
        else if (lb < 1024)  { W = Wvis_w + 1024*512; dh = g_Bv1h; dl = g_Bv1l; N = 512;  local = lb - 512; }
        else if (lb < 1536)  { W = Wvis_w + 2048*512; dh = g_Bv2h; dl = g_Bv2l; N = 512;  local = lb - 1024;}
        else if (lb < 2560)  { W = Who_w;             dh = g_Whoh; dl = g_Whol; N = 1024; local = lb - 1536;}
        else                 { W = Woh_w;             dh = g_Wohh; dl = g_Wohl; N = 1024; local = lb - 2560;}
        int ntN = N >> 5;
        int k0 = (local / ntN) * 32, n0 = (local % ntN) * 32;
        #pragma unroll
        for (int i = 0; i < 4; i++) {
            int e = tid + i*256, r = e >> 5, c = e & 31;
            t[r][c] = W[(k0 + r)*N + n0 + c];
        }
        __syncthreads();
        #pragma unroll
        for (int i = 0; i < 4; i++) {
            int e = tid + i*256, r = e >> 5, c = e & 31;
            float v = t[c][r];
            __nv_bfloat16 h = __float2bfloat16(v);
            dh[(n0 + r)*1024 + k0 + c] = h;
            dl[(n0 + r)*1024 + k0 + c] = __float2bfloat16(v - __bfloat162float(h));
        }
    } else {                                          // ---- head-weight pack ----
        int idx = (bid - 12288)*256 + tid;            // 32768 total
        int c = idx >> 9, k = idx & 511;
        float v = 0.f;
        if (c == 0)                  v = Wip_w[k];
        else if (c <= 29)            v = Wref_w[k*29 + c - 1];
        else if (c >= 32 && c <= 60) v = Watt_w[k*29 + c - 32];
        __nv_bfloat16 h = __float2bfloat16(v);
        g_Wcath[idx] = h;
        g_Wcatl[idx] = __float2bfloat16(v - __bfloat162float(h));
    }
}

// ---------------- k1: warp-MMA bf16 3-term split GEMM, 128x64 tiles ----------------
#define KP 40
#define TA (128*KP*2)
#define TB (64*KP*2)
#define STAGE_B (2*TA + 2*TB)
#define K1_SMEM (2*STAGE_B)

__global__ __launch_bounds__(128,3) void k1_mma(
    const float* __restrict__ Wvis_b,
    const float* __restrict__ Who_b,
    const float* __restrict__ Woh_b)
{
    extern __shared__ char smem[];
    u32 sb = smem_u32(smem);
    int tid = threadIdx.x, lane = tid & 31, wid = tid >> 5;
    int wm = wid & 1, wn = wid >> 1;
    int bid = blockIdx.x;

    const __nv_bfloat16 *Ah, *Al, *Bh, *Bl;
    float* C; const float* bias = 0;
    int relu = 0, Mv = 1024, N, mt0, nt0, local;
    if (bid < 64)       { Ah=g_peh; Al=g_pel; Bh=g_Bv0h; Bl=g_Bv0l; C=g_Pvis; N=512;  local=bid;     mt0=local>>3; nt0=local&7; }
    else if (bid < 128) { Ah=g_obh; Al=g_obl; Bh=g_Bv1h; Bl=g_Bv1l; C=g_Ovis; N=512;  local=bid-64;  mt0=local>>3; nt0=local&7; }
    else if (bid < 136) { Ah=g_cxh; Al=g_cxl; Bh=g_Bv2h; Bl=g_Bv2l; C=g_Cvis; N=512;  local=bid-128; mt0=0; nt0=local; bias=Wvis_b; Mv=64; }
    else if (bid < 264) { Ah=g_peh; Al=g_pel; Bh=g_Whoh; Bl=g_Whol; C=g_HO;   N=1024; local=bid-136; mt0=local>>4; nt0=local&15; bias=Who_b; relu=1; }
    else                { Ah=g_obh; Al=g_obl; Bh=g_Wohh; Bl=g_Wohl; C=g_OH;   N=1024; local=bid-264; mt0=local>>4; nt0=local&15; bias=Woh_b; relu=1; }
    int m0 = mt0 * 128, n0 = nt0 * 64;

    float acc[4][4][4];
    #pragma unroll
    for (int i = 0; i < 4; i++)
        #pragma unroll
        for (int j = 0; j < 4; j++)
            #pragma unroll
            for (int q = 0; q < 4; q++) acc[i][j][q] = 0.f;

    // A x4 lane addressing (proven)
    int lg = lane >> 3, lr = lane & 7;
    int a_row_off = lr + ((lg & 1) << 3);
    int a_k_off   = (lg >> 1) << 3;
    // B x4 over n-pairs: lanes 0-15 -> n-tile j*2, lanes 16-31 -> n-tile j*2+1
    int b4_row_off = ((lane >> 4) << 3) + lr;
    int b4_k_off   = ((lane >> 3) & 1) << 3;

    #define LOAD_STAGE(KT, S) do {                                                    \
        u32 _s = (S); int _kt = (KT);                                                 \
        _Pragma("unroll")                                                             \
        for (int i = 0; i < 4; i++) {                                                 \
            int e = tid + i*128, row = e >> 2, sg = (e & 3) * 8;                      \
            cp16(_s      + (row*KP + sg)*2, &Ah[(m0 + row)*1024 + _kt + sg]);         \
            cp16(_s + TA + (row*KP + sg)*2, &Al[(m0 + row)*1024 + _kt + sg]);         \
        }                                                                             \
        _Pragma("unroll")                                                             \
        for (int i = 0; i < 2; i++) {                                                 \
            int e = tid + i*128, row = e >> 2, sg = (e & 3) * 8;                      \
            cp16(_s + 2*TA      + (row*KP + sg)*2, &Bh[(n0 + row)*1024 + _kt + sg]);  \
            cp16(_s + 2*TA + TB + (row*KP + sg)*2, &Bl[(n0 + row)*1024 + _kt + sg]);  \
        }                                                                             \
        asm volatile("cp.async.commit_group;");                                       \
    } while(0)

    LOAD_STAGE(0, sb);

    for (int c = 0; c < 32; c++) {
        asm volatile("cp.async.wait_group 0;");
        __syncthreads();                 // stage c visible to all; all warps past compute c-1
        if (c < 31) LOAD_STAGE((c + 1)*32, sb + ((c + 1) & 1)*STAGE_B);

        u32 st  = sb + (c & 1)*STAGE_B;
        u32 sAh = st, sAl = st + TA, sBh = st + 2*TA, sBl = st + 2*TA + TB;

        #pragma unroll
        for (int ks = 0; ks < 32; ks += 16) {
            u32 bh[4][2], bl[4][2];
            #pragma unroll
            for (int j = 0; j < 2; j++) {                    // two n-pairs
                u32 boff = ((wn*32 + j*16 + b4_row_off)*KP + ks + b4_k_off) * 2;
                u32 r4[4];
                ldm_x4(r4, sBh + boff);
                bh[j*2][0] = r4[0]; bh[j*2][1] = r4[1]; bh[j*2+1][0] = r4[2]; bh[j*2+1][1] = r4[3];
                ldm_x4(r4, sBl + boff);
                bl[j*2][0] = r4[0]; bl[j*2][1] = r4[1]; bl[j*2+1][0] = r4[2]; bl[j*2+1][1] = r4[3];
            }
            #pragma unroll
            for (int mt = 0; mt < 4; mt++) {
                u32 aoff = ((wm*64 + mt*16 + a_row_off)*KP + ks + a_k_off) * 2;
                u32 ah[4], al[4];
                ldm_x4(ah, sAh + aoff);
                ldm_x4(al, sAl + aoff);
                #pragma unroll
                for (int nt = 0; nt < 4; nt++) {
                    mma_bf16(acc[mt][nt], ah, bh[nt]);
                    mma_bf16(acc[mt][nt], ah, bl[nt]);
                    mma_bf16(acc[mt][nt], al, bh[nt]);
                }
            }
        }
    }

    // ---- epilogue ----
    int rq = lane >> 2, cq = (lane & 3) * 2;
    #pragma unroll
    for (int mt = 0; mt < 4; mt++) {
        int gmA = m0 + wm*64 + mt*16 + rq;
        int gmB = gmA + 8;
        #pragma unroll
        for (int nt = 0; nt < 4; nt++) {
            int gn = n0 + wn*32 + nt*8 + cq;
            float b0 = bias ? bias[gn]   : 0.f;
            float b1 = bias ? bias[gn+1] : 0.f;
            float v0 = acc[mt][nt][0] + b0, v1 = acc[mt][nt][1] + b1;
            float v2 = acc[mt][nt][2] + b0, v3 = acc[mt][nt][3] + b1;
            if (relu) { v0=fmaxf(v0,0.f); v1=fmaxf(v1,0.f); v2=fmaxf(v2,0.f); v3=fmaxf(v3,0.f); }
            if (gmA < Mv) *(float2*)&C[gmA*N + gn] = make_float2(v0, v1);
            if (gmB < Mv) *(float2*)&C[gmB*N + gn] = make_float2(v2, v3);
        }
    }
}

// ---------------- k2: fused per-(b,p): scalar a_ho/f_ref + MMA heads ----------------
#define K2P 520
#define K2_OFF_FAH 2048
#define K2_OFF_FAL 35328
#define K2_OFF_WH  68608
#define K2_OFF_WL  86016
#define K2_SMEM    103424

__global__ __launch_bounds__(256,2) void k2_pairs(
    const float* __restrict__ spatial,
    const float* __restrict__ Wspat_w, const float* __restrict__ Wspat_b,
    const float* __restrict__ Wip_b,   const float* __restrict__ Wref_b,
    const float* __restrict__ Watt_b,  float* __restrict__ out)
{
    extern __shared__ char sm2[];
    float* s_sp = (float*)sm2;
    __nv_bfloat16* s_fah = (__nv_bfloat16*)(sm2 + K2_OFF_FAH);   // [32][520]
    __nv_bfloat16* s_fal = (__nv_bfloat16*)(sm2 + K2_OFF_FAL);
    __nv_bfloat16* s_wh  = (__nv_bfloat16*)(sm2 + K2_OFF_WH);    // [64][136]
    __nv_bfloat16* s_wl  = (__nv_bfloat16*)(sm2 + K2_OFF_WL);

    int tid = threadIdx.x;
    int bp = blockIdx.x;
    int b = bp >> 4;

    #pragma unroll
    for (int i = 0; i < 2; i++) s_sp[tid + i*256] = spatial[bp*512 + tid + i*256];
    __syncthreads();

    // ---- phase 1: scalar a_ho + f_ref, written as bf16 hi/lo ----
    for (int jj = 0; jj < 2; jj++) {
        int j = tid + jj*256;
        float wk[32];
        #pragma unroll
        for (int k = 0; k < 32; k++) wk[k] = Wspat_w[k*512 + j];
        float bs = Wspat_b[j];
        float pv = g_Pvis[bp*512 + j];
        float cv = g_Cvis[b*512 + j];
        #pragma unroll 4
        for (int l = 0; l < 16; l++) {
            float acc = bs;
            #pragma unroll
            for (int k = 0; k < 32; k++) acc += s_sp[l*32 + k] * wk[k];
            float a = fmaxf(acc, 0.f);
            float ov = g_Ovis[(b*16 + l)*512 + j];
            float f = fmaxf(pv + ov + cv, 0.f) * a;
            __nv_bfloat16 fh = __float2bfloat16(f);
            __nv_bfloat16 ah = __float2bfloat16(a);
            s_fah[l*K2P + j]        = fh;
            s_fal[l*K2P + j]        = __float2bfloat16(f - __bfloat162float(fh));
            s_fah[(16 + l)*K2P + j] = ah;
            s_fal[(16 + l)*K2P + j] = __float2bfloat16(a - __bfloat162float(ah));
        }
    }

    // ---- phase 2: [32 rows] @ heads via bf16 3-term MMA ----
    int lane = tid & 31, wid = tid >> 5;
    int mt = wid >> 2;
    int ntile = (wid & 3) + mt*4;

    u32 base_fah = smem_u32(s_fah), base_fal = smem_u32(s_fal);
    u32 base_wh  = smem_u32(s_wh),  base_wl  = smem_u32(s_wl);

    int lg = lane >> 3, lr = lane & 7;
    int a_row = mt*16 + lr + ((lg & 1) << 3);
    int a_koff = (lg >> 1) << 3;
    int b_row = ntile*8 + lr;                 // same row for all lanes' quads
    int b4_koff = (lane >> 3) << 3;           // 0,8,16,24 -> k-pair x4

    float acc2[4] = {0.f, 0.f, 0.f, 0.f};

    for (int kc = 0; kc < 4; kc++) {
        __syncthreads();
        #pragma unroll
        for (int i = 0; i < 4; i++) {
            int e = tid + i*256;
            int c = e >> 4, k8 = (e & 15) << 3;
            *(uint4*)&s_wh[c*136 + k8] = *(const uint4*)&g_Wcath[c*512 + kc*128 + k8];
            *(uint4*)&s_wl[c*136 + k8] = *(const uint4*)&g_Wcatl[c*512 + kc*128 + k8];
        }
        __syncthreads();
        #pragma unroll
        for (int ks = 0; ks < 128; ks += 32) {
            u32 bh4[4], bl4[4];
            ldm_x4(bh4, base_wh + (b_row*136 + ks + b4_koff)*2);
            ldm_x4(bl4, base_wl + (b_row*136 + ks + b4_koff)*2);
            u32 ah0[4], al0[4], ah1[4], al1[4];
            ldm_x4(ah0, base_fah + (a_row*K2P + kc*128 + ks + a_koff)*2);
            ldm_x4(al0, base_fal + (a_row*K2P + kc*128 + ks + a_koff)*2);
            ldm_x4(ah1, base_fah + (a_row*K2P + kc*128 + ks + 16 + a_koff)*2);
            ldm_x4(al1, base_fal + (a_row*K2P + kc*128 + ks + 16 + a_koff)*2);
            mma_bf16(acc2, ah0, bh4);       // k 0-15: frag {r0,r1}
            mma_bf16(acc2, ah0, bl4);
            mma_bf16(acc2, al0, bh4);
            mma_bf16(acc2, ah1, bh4 + 2);   // k 16-31: frag {r2,r3}
            mma_bf16(acc2, ah1, bl4 + 2);
            mma_bf16(acc2, al1, bh4 + 2);
        }
    }

    // ---- outputs ----
    int r0 = mt*16 + (lane >> 2);
    int c0 = ntile*8 + (lane & 3)*2;
    #pragma unroll
    for (int q = 0; q < 4; q++) {
        int r = r0 + ((q >> 1) << 3);
        int c = c0 + (q & 1);
        float v = acc2[q];
        if (r < 16) {
            int cidx = bp*16 + r;
            if (c == 0) {
                v += Wip_b[0];
                out[cidx] = v;
                g_adj[cidx] = 1.f / (1.f + expf(-v));
            } else if (c <= 29) {
                out[16384 + cidx*29 + (c - 1)] = v + Wref_b[c - 1];
            }
        } else {
            int cidx = bp*16 + (r - 16);
            int cc = c - 32;
            if (cc >= 0 && cc <= 28) {
                out[491520 + cidx*29 + cc] = v + Watt_b[cc];
            }
        }
    }
}

// ---------------- k3a: message passing, split by role ----------------
__global__ __launch_bounds__(256) void k3a_msg(const float* __restrict__ people,
                                               const float* __restrict__ objects)
{
    __shared__ float adj[240];
    int bid = blockIdx.x;                 // 512
    int b = bid >> 3, ch = (bid >> 1) & 3, role = bid & 1;
    int tid = threadIdx.x;
    if (tid < 240) adj[tid] = g_adj[(b*16 + tid/15)*16 + (tid % 15) + 1];
    __syncthreads();

    int d = ch*256 + tid;
    if (role == 0) {
        float oh[15];
        #pragma unroll
        for (int o = 0; o < 15; o++) oh[o] = g_OH[(b*16 + o + 1)*1024 + d];
        #pragma unroll
        for (int p = 0; p < 16; p++) {
            float acc = people[(b*16 + p)*1024 + d];
            #pragma unroll
            for (int o = 0; o < 15; o++) acc += adj[p*15 + o] * oh[o];
            g_PR[(b*16 + p)*1024 + d] = acc;
        }
    } else {
        float ho[16];
        #pragma unroll
        for (int p = 0; p < 16; p++) ho[p] = g_HO[(b*16 + p)*1024 + d];
        g_OBF[(b*16)*1024 + d] = objects[(b*16)*1024 + d];
        #pragma unroll
        for (int o = 0; o < 15; o++) {
            float acc = objects[(b*16 + o + 1)*1024 + d];
            #pragma unroll
            for (int p = 0; p < 16; p++) acc += adj[p*15 + o] * ho[p];
            g_OBF[(b*16 + o + 1)*1024 + d] = acc;
        }
    }
}

// ---------------- k3b: skinny GEMM [2048,1024]@[1024,29] warp-per-row ----------------
__global__ __launch_bounds__(256) void k3b_gemm(const float* __restrict__ Wg_w,
                                                const float* __restrict__ Wg_b)
{
    __shared__ float Ws[256*33];
    int half = blockIdx.x >> 7;
    int row = (blockIdx.x & 127)*8 + (threadIdx.x >> 5);
    int lane = threadIdx.x & 31;
    const float* src = half ? g_OBF : g_PR;
    const float* W = Wg_w + half*1024*29;
    float* dst = half ? g_Go : g_Gp;

    float acc[29];
    #pragma unroll
    for (int a = 0; a < 29; a++) acc[a] = 0.f;

    for (int kt = 0; kt < 4; kt++) {
        __syncthreads();
        #pragma unroll
        for (int i = 0; i < 29; i++) {
            int idx = threadIdx.x + i*256;
            int k = idx / 29, a = idx - k*29;
            Ws[k*33 + a] = W[kt*7424 + idx];
        }
        __syncthreads();
        #pragma unroll
        for (int t = 0; t < 8; t++) {
            int k = t*32 + lane;
            float rv = src[row*1024 + kt*256 + k];
            #pragma unroll
            for (int a = 0; a < 29; a++) acc[a] += rv * Ws[k*33 + a];
        }
    }
    #pragma unroll
    for (int off = 16; off; off >>= 1)
        #pragma unroll
        for (int a = 0; a < 29; a++)
            acc[a] += __shfl_down_sync(0xffffffffu, acc[a], off);
    if (lane == 0) {
        #pragma unroll
        for (int a = 0; a < 29; a++)
            dst[row*29 + a] = acc[a] + (half ? Wg_b[a] : 0.f);
    }
}

// ---------------- k3c: broadcast add -> p_graph ----------------
__global__ __launch_bounds__(256) void k3c_add(float* __restrict__ out_pg)
{
    int idx = blockIdx.x*256 + threadIdx.x;
    int c = idx / 29;
    int a = idx - c*29;
    int prow = c >> 4;
    int lrow = (c >> 8)*16 + (c & 15);
    out_pg[idx] = g_Gp[prow*29 + a] + g_Go[lrow*29 + a];
}

// ---------------- launch ----------------
extern "C" void kernel_launch(void* const* d_in, const int* in_sizes, int n_in,
                              void* d_out, int out_size) {
    const float* people  = (const float*)d_in[0];
    const float* objects = (const float*)d_in[1];
    const float* context = (const float*)d_in[2];
    const float* spatial = (const float*)d_in[3];
    const float* Wvis_w  = (const float*)d_in[4];
    const float* Wvis_b  = (const float*)d_in[5];
    const float* Wspat_w = (const float*)d_in[6];
    const float* Wspat_b = (const float*)d_in[7];
    const float* Wip_w   = (const float*)d_in[8];
    const float* Wip_b   = (const float*)d_in[9];
    const float* Wref_w  = (const float*)d_in[10];
    const float* Wref_b  = (const float*)d_in[11];
    const float* Watt_w  = (const float*)d_in[12];
    const float* Watt_b  = (const float*)d_in[13];
    const float* Woh_w   = (const float*)d_in[14];
    const float* Woh_b   = (const float*)d_in[15];
    const float* Who_w   = (const float*)d_in[16];
    const float* Who_b   = (const float*)d_in[17];
    const float* Wg_w    = (const float*)d_in[18];
    const float* Wg_b    = (const float*)d_in[19];
    float* out = (float*)d_out;

    cudaFuncSetAttribute(k1_mma,  cudaFuncAttributeMaxDynamicSharedMemorySize, K1_SMEM);
    cudaFuncSetAttribute(k2_pairs, cudaFuncAttributeMaxDynamicSharedMemorySize, K2_SMEM);

    c_prep<<<12416, 256>>>(people, objects, context, Wvis_w, Who_w, Woh_w,
                           Wip_w, Wref_w, Watt_w);
    k1_mma<<<392, 128, K1_SMEM>>>(Wvis_b, Who_b, Woh_b);
    k2_pairs<<<1024, 256, K2_SMEM>>>(spatial, Wspat_w, Wspat_b,
                                     Wip_b, Wref_b, Watt_b, out);
    k3a_msg<<<512, 256>>>(people, objects);
    k3b_gemm<<<256, 256>>>(Wg_w, Wg_b);
    k3c_add<<<1856, 256>>>(out + 966656);
}

// round 9
// speedup vs baseline: 2.3574x; 1.0499x over previous
#include <cuda_runtime.h>
#include <cuda_bf16.h>
#include <math.h>

typedef unsigned long long ull;
typedef unsigned int u32;

// ---------------- device scratch (allocations are forbidden) ----------------
__device__ float g_Pvis[1024*512];   // people  @ Wvis[0:1024]
__device__ float g_Ovis[1024*512];   // objects @ Wvis[1024:2048]
__device__ float g_Cvis[64*512];     // context @ Wvis[2048:3072] + Wvis_b
__device__ float g_HO[1024*1024];    // relu(people  @ Who + b)
__device__ float g_OH[1024*1024];    // relu(objects @ Woh + b)
__device__ float g_adj[16384];       // sigmoid(i_ho)
__device__ float g_PR[1024*1024];    // people_r
__device__ float g_OBF[1024*1024];   // objects_full
__device__ float g_Gp[1024*29];
__device__ float g_Go[1024*29];

// packed head weights, bf16 hi/lo, [c=64][k=512]
__device__ __nv_bfloat16 g_Wcath[64*512], g_Wcatl[64*512];

// bf16 hi/lo pre-converted operands
__device__ __nv_bfloat16 g_peh[1024*1024], g_pel[1024*1024];
__device__ __nv_bfloat16 g_obh[1024*1024], g_obl[1024*1024];
__device__ __nv_bfloat16 g_cxh[128*1024],  g_cxl[128*1024];
__device__ __nv_bfloat16 g_Bv0h[512*1024], g_Bv0l[512*1024];
__device__ __nv_bfloat16 g_Bv1h[512*1024], g_Bv1l[512*1024];
__device__ __nv_bfloat16 g_Bv2h[512*1024], g_Bv2l[512*1024];
__device__ __nv_bfloat16 g_Whoh[1024*1024], g_Whol[1024*1024];
__device__ __nv_bfloat16 g_Wohh[1024*1024], g_Wohl[1024*1024];
__device__ __nv_bfloat16 g_sph[16384*32], g_spl[16384*32];   // spatial h/l
__device__ __nv_bfloat16 g_Wsh[512*32],  g_Wsl[512*32];      // Wspat^T [n][k] h/l

// ---------------- small helpers ----------------
__device__ __forceinline__ u32 smem_u32(const void* p){
    u32 a; asm("{ .reg .u64 t; cvta.to.shared.u64 t, %1; cvt.u32.u64 %0, t; }":"=r"(a):"l"(p)); return a;
}
__device__ __forceinline__ void ldm_x4(u32* r, u32 addr){
    asm volatile("ldmatrix.sync.aligned.m8n8.x4.shared.b16 {%0,%1,%2,%3}, [%4];"
        :"=r"(r[0]),"=r"(r[1]),"=r"(r[2]),"=r"(r[3]):"r"(addr));
}
__device__ __forceinline__ void mma_bf16(float* c, const u32* a, const u32* b){
    asm volatile("mma.sync.aligned.m16n8k16.row.col.f32.bf16.bf16.f32 "
        "{%0,%1,%2,%3}, {%4,%5,%6,%7}, {%8,%9}, {%0,%1,%2,%3};"
        :"+f"(c[0]),"+f"(c[1]),"+f"(c[2]),"+f"(c[3])
        :"r"(a[0]),"r"(a[1]),"r"(a[2]),"r"(a[3]),"r"(b[0]),"r"(b[1]));
}
__device__ __forceinline__ void cp16(u32 dst, const void* src){
    asm volatile("cp.async.cg.shared.global [%0], [%1], 16;"::"r"(dst),"l"(src));
}
// pack (x,y) -> bf16x2 hi word + residual lo word
__device__ __forceinline__ u32 pack_hi(float x, float y, u32& lo){
    __nv_bfloat16 hx = __float2bfloat16(x), hy = __float2bfloat16(y);
    float rx = x - __bfloat162float(hx), ry = y - __bfloat162float(hy);
    __nv_bfloat16 lx = __float2bfloat16(rx), ly = __float2bfloat16(ry);
    unsigned short ux = *(unsigned short*)&hx, uy = *(unsigned short*)&hy;
    unsigned short vx = *(unsigned short*)&lx, vy = *(unsigned short*)&ly;
    lo = ((u32)vy << 16) | vx;
    return ((u32)uy << 16) | ux;
}

// ---------------- c_prep: all fp32->bf16 h/l conversions + packs ----------------
__global__ __launch_bounds__(256) void c_prep(
    const float* __restrict__ people, const float* __restrict__ objects,
    const float* __restrict__ context, const float* __restrict__ spatial,
    const float* __restrict__ Wvis_w, const float* __restrict__ Who_w,
    const float* __restrict__ Woh_w,  const float* __restrict__ Wspat_w,
    const float* __restrict__ Wip_w,  const float* __restrict__ Wref_w,
    const float* __restrict__ Watt_w)
{
    __shared__ float t[32][33];
    int bid = blockIdx.x;
    int tid = threadIdx.x;

    if (bid < 8704) {                                 // ---- convA ----
        int idx = bid*256 + tid;
        const float* src; __nv_bfloat16 *dh, *dl; int e;
        if (idx < 1048576)      { src = people;  dh = g_peh; dl = g_pel; e = idx; }
        else if (idx < 2097152) { src = objects; dh = g_obh; dl = g_obl; e = idx - 1048576; }
        else                    { src = context; dh = g_cxh; dl = g_cxl; e = idx - 2097152; }
        float v = 0.f;
        if (dh != g_cxh || (e >> 10) < 64) v = src[e];
        __nv_bfloat16 h = __float2bfloat16(v);
        dh[e] = h;
        dl[e] = __float2bfloat16(v - __bfloat162float(h));
    } else if (bid < 12288) {                         // ---- convB (transpose) ----
        int lb = bid - 8704;
        const float* W; __nv_bfloat16 *dh, *dl; int N, local;
        if (lb < 512)        { W = Wvis_w;            dh = g_Bv0h; dl = g_Bv0l; N = 512;  local = lb;       }
        else if (lb < 1024)  { W = Wvis_w + 1024*512; dh = g_Bv1h; dl = g_Bv1l; N = 512;  local = lb - 512; }
        else if (lb < 1536)  { W = Wvis_w + 2048*512; dh = g_Bv2h; dl = g_Bv2l; N = 512;  local = lb - 1024;}
        else if (lb < 2560)  { W = Who_w;             dh = g_Whoh; dl = g_Whol; N = 1024; local = lb - 1536;}
        else                 { W = Woh_w;             dh = g_Wohh; dl = g_Wohl; N = 1024; local = lb - 2560;}
        int ntN = N >> 5;
        int k0 = (local / ntN) * 32, n0 = (local % ntN) * 32;
        #pragma unroll
        for (int i = 0; i < 4; i++) {
            int e = tid + i*256, r = e >> 5, c = e & 31;
            t[r][c] = W[(k0 + r)*N + n0 + c];
        }
        __syncthreads();
        #pragma unroll
        for (int i = 0; i < 4; i++) {
            int e = tid + i*256, r = e >> 5, c = e & 31;
            float v = t[c][r];
            __nv_bfloat16 h = __float2bfloat16(v);
            dh[(n0 + r)*1024 + k0 + c] = h;
            dl[(n0 + r)*1024 + k0 + c] = __float2bfloat16(v - __bfloat162float(h));
        }
    } else if (bid < 12416) {                         // ---- head-weight pack ----
        int idx = (bid - 12288)*256 + tid;
        int c = idx >> 9, k = idx & 511;
        float v = 0.f;
        if (c == 0)                  v = Wip_w[k];
        else if (c <= 29)            v = Wref_w[k*29 + c - 1];
        else if (c >= 32 && c <= 60) v = Watt_w[k*29 + c - 32];
        __nv_bfloat16 h = __float2bfloat16(v);
        g_Wcath[idx] = h;
        g_Wcatl[idx] = __float2bfloat16(v - __bfloat162float(h));
    } else if (bid < 14464) {                         // ---- spatial conv ----
        int idx = (bid - 12416)*256 + tid;            // 524288
        float v = spatial[idx];
        __nv_bfloat16 h = __float2bfloat16(v);
        g_sph[idx] = h;
        g_spl[idx] = __float2bfloat16(v - __bfloat162float(h));
    } else {                                          // ---- Wspat^T ----
        int idx = (bid - 14464)*256 + tid;            // 16384: n = idx>>5, k = idx&31
        float v = Wspat_w[(idx & 31)*512 + (idx >> 5)];
        __nv_bfloat16 h = __float2bfloat16(v);
        g_Wsh[idx] = h;
        g_Wsl[idx] = __float2bfloat16(v - __bfloat162float(h));
    }
}

// ---------------- k1: warp-MMA bf16 3-term split GEMM, 128x64 tiles ----------------
#define KP 40
#define TA (128*KP*2)
#define TB (64*KP*2)
#define STAGE_B (2*TA + 2*TB)
#define K1_SMEM (2*STAGE_B)

__global__ __launch_bounds__(128,3) void k1_mma(
    const float* __restrict__ Wvis_b,
    const float* __restrict__ Who_b,
    const float* __restrict__ Woh_b)
{
    extern __shared__ char smem[];
    u32 sb = smem_u32(smem);
    int tid = threadIdx.x, lane = tid & 31, wid = tid >> 5;
    int wm = wid & 1, wn = wid >> 1;
    int bid = blockIdx.x;

    const __nv_bfloat16 *Ah, *Al, *Bh, *Bl;
    float* C; const float* bias = 0;
    int relu = 0, Mv = 1024, N, mt0, nt0, local;
    if (bid < 64)       { Ah=g_peh; Al=g_pel; Bh=g_Bv0h; Bl=g_Bv0l; C=g_Pvis; N=512;  local=bid;     mt0=local>>3; nt0=local&7; }
    else if (bid < 128) { Ah=g_obh; Al=g_obl; Bh=g_Bv1h; Bl=g_Bv1l; C=g_Ovis; N=512;  local=bid-64;  mt0=local>>3; nt0=local&7; }
    else if (bid < 136) { Ah=g_cxh; Al=g_cxl; Bh=g_Bv2h; Bl=g_Bv2l; C=g_Cvis; N=512;  local=bid-128; mt0=0; nt0=local; bias=Wvis_b; Mv=64; }
    else if (bid < 264) { Ah=g_peh; Al=g_pel; Bh=g_Whoh; Bl=g_Whol; C=g_HO;   N=1024; local=bid-136; mt0=local>>4; nt0=local&15; bias=Who_b; relu=1; }
    else                { Ah=g_obh; Al=g_obl; Bh=g_Wohh; Bl=g_Wohl; C=g_OH;   N=1024; local=bid-264; mt0=local>>4; nt0=local&15; bias=Woh_b; relu=1; }
    int m0 = mt0 * 128, n0 = nt0 * 64;

    float acc[4][4][4];
    #pragma unroll
    for (int i = 0; i < 4; i++)
        #pragma unroll
        for (int j = 0; j < 4; j++)
            #pragma unroll
            for (int q = 0; q < 4; q++) acc[i][j][q] = 0.f;

    int lg = lane >> 3, lr = lane & 7;
    int a_row_off = lr + ((lg & 1) << 3);
    int a_k_off   = (lg >> 1) << 3;
    int b4_row_off = ((lane >> 4) << 3) + lr;
    int b4_k_off   = ((lane >> 3) & 1) << 3;

    #define LOAD_STAGE(KT, S) do {                                                    \
        u32 _s = (S); int _kt = (KT);                                                 \
        _Pragma("unroll")                                                             \
        for (int i = 0; i < 4; i++) {                                                 \
            int e = tid + i*128, row = e >> 2, sg = (e & 3) * 8;                      \
            cp16(_s      + (row*KP + sg)*2, &Ah[(m0 + row)*1024 + _kt + sg]);         \
            cp16(_s + TA + (row*KP + sg)*2, &Al[(m0 + row)*1024 + _kt + sg]);         \
        }                                                                             \
        _Pragma("unroll")                                                             \
        for (int i = 0; i < 2; i++) {                                                 \
            int e = tid + i*128, row = e >> 2, sg = (e & 3) * 8;                      \
            cp16(_s + 2*TA      + (row*KP + sg)*2, &Bh[(n0 + row)*1024 + _kt + sg]);  \
            cp16(_s + 2*TA + TB + (row*KP + sg)*2, &Bl[(n0 + row)*1024 + _kt + sg]);  \
        }                                                                             \
        asm volatile("cp.async.commit_group;");                                       \
    } while(0)

    LOAD_STAGE(0, sb);

    for (int c = 0; c < 32; c++) {
        asm volatile("cp.async.wait_group 0;");
        __syncthreads();
        if (c < 31) LOAD_STAGE((c + 1)*32, sb + ((c + 1) & 1)*STAGE_B);

        u32 st  = sb + (c & 1)*STAGE_B;
        u32 sAh = st, sAl = st + TA, sBh = st + 2*TA, sBl = st + 2*TA + TB;

        #pragma unroll
        for (int ks = 0; ks < 32; ks += 16) {
            u32 bh[4][2], bl[4][2];
            #pragma unroll
            for (int j = 0; j < 2; j++) {
                u32 boff = ((wn*32 + j*16 + b4_row_off)*KP + ks + b4_k_off) * 2;
                u32 r4[4];
                ldm_x4(r4, sBh + boff);
                bh[j*2][0] = r4[0]; bh[j*2][1] = r4[1]; bh[j*2+1][0] = r4[2]; bh[j*2+1][1] = r4[3];
                ldm_x4(r4, sBl + boff);
                bl[j*2][0] = r4[0]; bl[j*2][1] = r4[1]; bl[j*2+1][0] = r4[2]; bl[j*2+1][1] = r4[3];
            }
            #pragma unroll
            for (int mt = 0; mt < 4; mt++) {
                u32 aoff = ((wm*64 + mt*16 + a_row_off)*KP + ks + a_k_off) * 2;
                u32 ah[4], al[4];
                ldm_x4(ah, sAh + aoff);
                ldm_x4(al, sAl + aoff);
                #pragma unroll
                for (int nt = 0; nt < 4; nt++) {
                    mma_bf16(acc[mt][nt], ah, bh[nt]);
                    mma_bf16(acc[mt][nt], ah, bl[nt]);
                    mma_bf16(acc[mt][nt], al, bh[nt]);
                }
            }
        }
    }

    int rq = lane >> 2, cq = (lane & 3) * 2;
    #pragma unroll
    for (int mt = 0; mt < 4; mt++) {
        int gmA = m0 + wm*64 + mt*16 + rq;
        int gmB = gmA + 8;
        #pragma unroll
        for (int nt = 0; nt < 4; nt++) {
            int gn = n0 + wn*32 + nt*8 + cq;
            float b0 = bias ? bias[gn]   : 0.f;
            float b1 = bias ? bias[gn+1] : 0.f;
            float v0 = acc[mt][nt][0] + b0, v1 = acc[mt][nt][1] + b1;
            float v2 = acc[mt][nt][2] + b0, v3 = acc[mt][nt][3] + b1;
            if (relu) { v0=fmaxf(v0,0.f); v1=fmaxf(v1,0.f); v2=fmaxf(v2,0.f); v3=fmaxf(v3,0.f); }
            if (gmA < Mv) *(float2*)&C[gmA*N + gn] = make_float2(v0, v1);
            if (gmB < Mv) *(float2*)&C[gmB*N + gn] = make_float2(v2, v3);
        }
    }
}

// ---------------- k2: per-(b,p) MMA phase1 (a_ho/f_ref) + MMA heads ----------------
#define K2P 520
#define OFF_AH  0
#define OFF_AL  1280
#define OFF_FAH 2560
#define OFF_FAL 35840
#define OFF_WH  69120
#define OFF_WL  86528
#define K2_SMEM 103936

__global__ __launch_bounds__(256,2) void k2_pairs(
    const float* __restrict__ Wspat_b,
    const float* __restrict__ Wip_b,   const float* __restrict__ Wref_b,
    const float* __restrict__ Watt_b,  float* __restrict__ out)
{
    extern __shared__ char sm2[];
    __nv_bfloat16* s_fah = (__nv_bfloat16*)(sm2 + OFF_FAH);   // [32][520]
    __nv_bfloat16* s_fal = (__nv_bfloat16*)(sm2 + OFF_FAL);
    __nv_bfloat16* s_wh  = (__nv_bfloat16*)(sm2 + OFF_WH);    // [64][136]
    __nv_bfloat16* s_wl  = (__nv_bfloat16*)(sm2 + OFF_WL);

    int tid = threadIdx.x;
    int bp = blockIdx.x;
    int b = bp >> 4;
    int lane = tid & 31, wid = tid >> 5;

    // ---- phase 1: load spatial tile [16][32] bf16 h/l into smem (pitch 40) ----
    {
        int l = tid >> 4, kq = tid & 15;
        ((u32*)(sm2 + OFF_AH))[l*20 + kq] = ((const u32*)g_sph)[(bp*16 + l)*16 + kq];
        ((u32*)(sm2 + OFF_AL))[l*20 + kq] = ((const u32*)g_spl)[(bp*16 + l)*16 + kq];
    }
    __syncthreads();

    // A fragments (rows = object slots 0..15, k = 0..31)
    int lg = lane >> 3, lr = lane & 7;
    int a_row_off = lr + ((lg & 1) << 3);
    int a_koff = (lg >> 1) << 3;
    u32 ah0[4], ah1[4], al0[4], al1[4];
    {
        u32 bah = smem_u32(sm2 + OFF_AH), bal = smem_u32(sm2 + OFF_AL);
        u32 aoff = (a_row_off*40 + a_koff)*2;
        ldm_x4(ah0, bah + aoff);
        ldm_x4(ah1, bah + aoff + 32);
        ldm_x4(al0, bal + aoff);
        ldm_x4(al1, bal + aoff + 32);
    }

    // phase1 MMA: warp w covers n-cols w*64..+63
    int lq = lane & 3, ln = lane >> 2;
    const u32* WshU = (const u32*)g_Wsh;
    const u32* WslU = (const u32*)g_Wsl;
    #pragma unroll
    for (int nt = 0; nt < 8; nt++) {
        int n = wid*64 + nt*8 + ln;
        u32 bh[4], bl[4];
        bh[0] = WshU[n*16 + lq];      bh[1] = WshU[n*16 + lq + 4];
        bh[2] = WshU[n*16 + lq + 8];  bh[3] = WshU[n*16 + lq + 12];
        bl[0] = WslU[n*16 + lq];      bl[1] = WslU[n*16 + lq + 4];
        bl[2] = WslU[n*16 + lq + 8];  bl[3] = WslU[n*16 + lq + 12];
        float c[4] = {0.f, 0.f, 0.f, 0.f};
        mma_bf16(c, ah0, bh);
        mma_bf16(c, ah0, bl);
        mma_bf16(c, al0, bh);
        mma_bf16(c, ah1, bh + 2);
        mma_bf16(c, ah1, bl + 2);
        mma_bf16(c, al1, bh + 2);

        // fused epilogue -> s_fah/s_fal
        int j0 = wid*64 + nt*8 + lq*2;
        int l0 = ln, l1 = ln + 8;
        float2 bs = *(const float2*)&Wspat_b[j0];
        float2 pv = *(const float2*)&g_Pvis[bp*512 + j0];
        float2 cv = *(const float2*)&g_Cvis[b*512 + j0];
        float2 o0 = *(const float2*)&g_Ovis[(b*16 + l0)*512 + j0];
        float2 o1 = *(const float2*)&g_Ovis[(b*16 + l1)*512 + j0];
        float a0 = fmaxf(c[0] + bs.x, 0.f), a1 = fmaxf(c[1] + bs.y, 0.f);
        float a2 = fmaxf(c[2] + bs.x, 0.f), a3 = fmaxf(c[3] + bs.y, 0.f);
        float f0 = fmaxf(pv.x + o0.x + cv.x, 0.f) * a0;
        float f1 = fmaxf(pv.y + o0.y + cv.y, 0.f) * a1;
        float f2 = fmaxf(pv.x + o1.x + cv.x, 0.f) * a2;
        float f3 = fmaxf(pv.y + o1.y + cv.y, 0.f) * a3;
        u32 lo;
        u32 hi;
        hi = pack_hi(f0, f1, lo);
        *(u32*)&s_fah[l0*K2P + j0] = hi;        *(u32*)&s_fal[l0*K2P + j0] = lo;
        hi = pack_hi(f2, f3, lo);
        *(u32*)&s_fah[l1*K2P + j0] = hi;        *(u32*)&s_fal[l1*K2P + j0] = lo;
        hi = pack_hi(a0, a1, lo);
        *(u32*)&s_fah[(16 + l0)*K2P + j0] = hi; *(u32*)&s_fal[(16 + l0)*K2P + j0] = lo;
        hi = pack_hi(a2, a3, lo);
        *(u32*)&s_fah[(16 + l1)*K2P + j0] = hi; *(u32*)&s_fal[(16 + l1)*K2P + j0] = lo;
    }

    // ---- phase 2: [32 rows] @ heads via bf16 3-term MMA ----
    int mt = wid >> 2;
    int ntile = (wid & 3) + mt*4;

    u32 base_fah = smem_u32(s_fah), base_fal = smem_u32(s_fal);
    u32 base_wh  = smem_u32(s_wh),  base_wl  = smem_u32(s_wl);

    int a_row = mt*16 + lr + ((lg & 1) << 3);
    int b_row = ntile*8 + lr;
    int b4_koff = (lane >> 3) << 3;

    float acc2[4] = {0.f, 0.f, 0.f, 0.f};

    for (int kc = 0; kc < 4; kc++) {
        __syncthreads();
        #pragma unroll
        for (int i = 0; i < 4; i++) {
            int e = tid + i*256;
            int c = e >> 4, k8 = (e & 15) << 3;
            *(uint4*)&s_wh[c*136 + k8] = *(const uint4*)&g_Wcath[c*512 + kc*128 + k8];
            *(uint4*)&s_wl[c*136 + k8] = *(const uint4*)&g_Wcatl[c*512 + kc*128 + k8];
        }
        __syncthreads();
        #pragma unroll
        for (int ks = 0; ks < 128; ks += 32) {
            u32 bh4[4], bl4[4];
            ldm_x4(bh4, base_wh + (b_row*136 + ks + b4_koff)*2);
            ldm_x4(bl4, base_wl + (b_row*136 + ks + b4_koff)*2);
            u32 xh0[4], xl0[4], xh1[4], xl1[4];
            ldm_x4(xh0, base_fah + (a_row*K2P + kc*128 + ks + a_koff)*2);
            ldm_x4(xl0, base_fal + (a_row*K2P + kc*128 + ks + a_koff)*2);
            ldm_x4(xh1, base_fah + (a_row*K2P + kc*128 + ks + 16 + a_koff)*2);
            ldm_x4(xl1, base_fal + (a_row*K2P + kc*128 + ks + 16 + a_koff)*2);
            mma_bf16(acc2, xh0, bh4);
            mma_bf16(acc2, xh0, bl4);
            mma_bf16(acc2, xl0, bh4);
            mma_bf16(acc2, xh1, bh4 + 2);
            mma_bf16(acc2, xh1, bl4 + 2);
            mma_bf16(acc2, xl1, bh4 + 2);
        }
    }

    // ---- outputs ----
    int r0 = mt*16 + (lane >> 2);
    int c0 = ntile*8 + (lane & 3)*2;
    #pragma unroll
    for (int q = 0; q < 4; q++) {
        int r = r0 + ((q >> 1) << 3);
        int c = c0 + (q & 1);
        float v = acc2[q];
        if (r < 16) {
            int cidx = bp*16 + r;
            if (c == 0) {
                v += Wip_b[0];
                out[cidx] = v;
                g_adj[cidx] = 1.f / (1.f + expf(-v));
            } else if (c <= 29) {
                out[16384 + cidx*29 + (c - 1)] = v + Wref_b[c - 1];
            }
        } else {
            int cidx = bp*16 + (r - 16);
            int cc = c - 32;
            if (cc >= 0 && cc <= 28) {
                out[491520 + cidx*29 + cc] = v + Watt_b[cc];
            }
        }
    }
}

// ---------------- k3a: message passing, 1024 blocks ----------------
__global__ __launch_bounds__(256) void k3a_msg(const float* __restrict__ people,
                                               const float* __restrict__ objects)
{
    __shared__ float adj[240];
    int bid = blockIdx.x;                 // 1024
    int b = bid >> 4, ch = (bid >> 2) & 3, role = (bid >> 1) & 1, half = bid & 1;
    int tid = threadIdx.x;
    if (tid < 240) adj[tid] = g_adj[(b*16 + tid/15)*16 + (tid % 15) + 1];
    __syncthreads();

    int d = ch*256 + tid;
    if (role == 0) {
        float oh[15];
        #pragma unroll
        for (int o = 0; o < 15; o++) oh[o] = g_OH[(b*16 + o + 1)*1024 + d];
        #pragma unroll
        for (int pi = 0; pi < 8; pi++) {
            int p = half*8 + pi;
            float acc = people[(b*16 + p)*1024 + d];
            #pragma unroll
            for (int o = 0; o < 15; o++) acc += adj[p*15 + o] * oh[o];
            g_PR[(b*16 + p)*1024 + d] = acc;
        }
    } else {
        float ho[16];
        #pragma unroll
        for (int p = 0; p < 16; p++) ho[p] = g_HO[(b*16 + p)*1024 + d];
        if (half == 0) g_OBF[(b*16)*1024 + d] = objects[(b*16)*1024 + d];
        #pragma unroll
        for (int oi = 0; oi < 8; oi++) {
            int o = half*8 + oi;
            if (o < 15) {
                float acc = objects[(b*16 + o + 1)*1024 + d];
                #pragma unroll
                for (int p = 0; p < 16; p++) acc += adj[p*15 + o] * ho[p];
                g_OBF[(b*16 + o + 1)*1024 + d] = acc;
            }
        }
    }
}

// ---------------- k3b: skinny GEMM [2048,1024]@[1024,29] warp-per-row ----------------
__global__ __launch_bounds__(256) void k3b_gemm(const float* __restrict__ Wg_w,
                                                const float* __restrict__ Wg_b)
{
    __shared__ float Ws[256*33];
    int half = blockIdx.x >> 7;
    int row = (blockIdx.x & 127)*8 + (threadIdx.x >> 5);
    int lane = threadIdx.x & 31;
    const float* src = half ? g_OBF : g_PR;
    const float* W = Wg_w + half*1024*29;
    float* dst = half ? g_Go : g_Gp;

    float acc[29];
    #pragma unroll
    for (int a = 0; a < 29; a++) acc[a] = 0.f;

    for (int kt = 0; kt < 4; kt++) {
        __syncthreads();
        #pragma unroll
        for (int i = 0; i < 29; i++) {
            int idx = threadIdx.x + i*256;
            int k = idx / 29, a = idx - k*29;
            Ws[k*33 + a] = W[kt*7424 + idx];
        }
        __syncthreads();
        #pragma unroll
        for (int t = 0; t < 8; t++) {
            int k = t*32 + lane;
            float rv = src[row*1024 + kt*256 + k];
            #pragma unroll
            for (int a = 0; a < 29; a++) acc[a] += rv * Ws[k*33 + a];
        }
    }
    #pragma unroll
    for (int off = 16; off; off >>= 1)
        #pragma unroll
        for (int a = 0; a < 29; a++)
            acc[a] += __shfl_down_sync(0xffffffffu, acc[a], off);
    if (lane == 0) {
        #pragma unroll
        for (int a = 0; a < 29; a++)
            dst[row*29 + a] = acc[a] + (half ? Wg_b[a] : 0.f);
    }
}

// ---------------- k3c: broadcast add -> p_graph ----------------
__global__ __launch_bounds__(256) void k3c_add(float* __restrict__ out_pg)
{
    int idx = blockIdx.x*256 + threadIdx.x;
    int c = idx / 29;
    int a = idx - c*29;
    int prow = c >> 4;
    int lrow = (c >> 8)*16 + (c & 15);
    out_pg[idx] = g_Gp[prow*29 + a] + g_Go[lrow*29 + a];
}

// ---------------- launch ----------------
extern "C" void kernel_launch(void* const* d_in, const int* in_sizes, int n_in,
                              void* d_out, int out_size) {
    const float* people  = (const float*)d_in[0];
    const float* objects = (const float*)d_in[1];
    const float* context = (const float*)d_in[2];
    const float* spatial = (const float*)d_in[3];
    const float* Wvis_w  = (const float*)d_in[4];
    const float* Wvis_b  = (const float*)d_in[5];
    const float* Wspat_w = (const float*)d_in[6];
    const float* Wspat_b = (const float*)d_in[7];
    const float* Wip_w   = (const float*)d_in[8];
    const float* Wip_b   = (const float*)d_in[9];
    const float* Wref_w  = (const float*)d_in[10];
    const float* Wref_b  = (const float*)d_in[11];
    const float* Watt_w  = (const float*)d_in[12];
    const float* Watt_b  = (const float*)d_in[13];
    const float* Woh_w   = (const float*)d_in[14];
    const float* Woh_b   = (const float*)d_in[15];
    const float* Who_w   = (const float*)d_in[16];
    const float* Who_b   = (const float*)d_in[17];
    const float* Wg_w    = (const float*)d_in[18];
    const float* Wg_b    = (const float*)d_in[19];
    float* out = (float*)d_out;

    cudaFuncSetAttribute(k1_mma,  cudaFuncAttributeMaxDynamicSharedMemorySize, K1_SMEM);
    cudaFuncSetAttribute(k2_pairs, cudaFuncAttributeMaxDynamicSharedMemorySize, K2_SMEM);

    c_prep<<<14528, 256>>>(people, objects, context, spatial,
                           Wvis_w, Who_w, Woh_w, Wspat_w,
                           Wip_w, Wref_w, Watt_w);
    k1_mma<<<392, 128, K1_SMEM>>>(Wvis_b, Who_b, Woh_b);
    k2_pairs<<<1024, 256, K2_SMEM>>>(Wspat_b, Wip_b, Wref_b, Watt_b, out);
    k3a_msg<<<1024, 256>>>(people, objects);
    k3b_gemm<<<256, 256>>>(Wg_w, Wg_b);
    k3c_add<<<1856, 256>>>(out + 966656);
}

// round 10
// speedup vs baseline: 2.8793x; 1.2214x over previous
#include <cuda_runtime.h>
#include <cuda_fp16.h>
#include <math.h>

typedef unsigned long long ull;
typedef unsigned int u32;

// ---------------- device scratch (allocations are forbidden) ----------------
__device__ float g_Pvis[1024*512];   // people  @ Wvis[0:1024]
__device__ float g_Ovis[1024*512];   // objects @ Wvis[1024:2048]
__device__ float g_Cvis[64*512];     // context @ Wvis[2048:3072] + Wvis_b
__device__ float g_HO[1024*1024];    // relu(people  @ Who + b)
__device__ float g_OH[1024*1024];    // relu(objects @ Woh + b)
__device__ float g_adj[16384];       // sigmoid(i_ho)
__device__ float g_PR[1024*1024];    // people_r
__device__ float g_OBF[1024*1024];   // objects_full
__device__ float g_Gp[1024*29];
__device__ float g_Go[1024*29];

// packed head weights, fp16 hi only, [c=64][k=512]
__device__ __half g_Wcath[64*512];

// fp16 pre-converted operands (A side hi/lo, B side hi only)
__device__ __half g_peh[1024*1024], g_pel[1024*1024];
__device__ __half g_obh[1024*1024], g_obl[1024*1024];
__device__ __half g_cxh[128*1024],  g_cxl[128*1024];
__device__ __half g_Bv0h[512*1024];
__device__ __half g_Bv1h[512*1024];
__device__ __half g_Bv2h[512*1024];
__device__ __half g_Whoh[1024*1024];
__device__ __half g_Wohh[1024*1024];
__device__ __half g_sph[16384*32], g_spl[16384*32];   // spatial h/l
__device__ __half g_Wsh[512*32];                      // Wspat^T [n][k] hi

// ---------------- small helpers ----------------
__device__ __forceinline__ u32 smem_u32(const void* p){
    u32 a; asm("{ .reg .u64 t; cvta.to.shared.u64 t, %1; cvt.u32.u64 %0, t; }":"=r"(a):"l"(p)); return a;
}
__device__ __forceinline__ void ldm_x4(u32* r, u32 addr){
    asm volatile("ldmatrix.sync.aligned.m8n8.x4.shared.b16 {%0,%1,%2,%3}, [%4];"
        :"=r"(r[0]),"=r"(r[1]),"=r"(r[2]),"=r"(r[3]):"r"(addr));
}
__device__ __forceinline__ void mma_f16(float* c, const u32* a, const u32* b){
    asm volatile("mma.sync.aligned.m16n8k16.row.col.f32.f16.f16.f32 "
        "{%0,%1,%2,%3}, {%4,%5,%6,%7}, {%8,%9}, {%0,%1,%2,%3};"
        :"+f"(c[0]),"+f"(c[1]),"+f"(c[2]),"+f"(c[3])
        :"r"(a[0]),"r"(a[1]),"r"(a[2]),"r"(a[3]),"r"(b[0]),"r"(b[1]));
}
__device__ __forceinline__ void cp16(u32 dst, const void* src){
    asm volatile("cp.async.cg.shared.global [%0], [%1], 16;"::"r"(dst),"l"(src));
}
// pack (x,y) -> fp16x2 hi word + residual lo word
__device__ __forceinline__ u32 pack_hi(float x, float y, u32& lo){
    __half hx = __float2half(x), hy = __float2half(y);
    float rx = x - __half2float(hx), ry = y - __half2float(hy);
    __half lx = __float2half(rx), ly = __float2half(ry);
    unsigned short ux = *(unsigned short*)&hx, uy = *(unsigned short*)&hy;
    unsigned short vx = *(unsigned short*)&lx, vy = *(unsigned short*)&ly;
    lo = ((u32)vy << 16) | vx;
    return ((u32)uy << 16) | ux;
}

// ---------------- c_prep: all fp32->fp16 conversions + packs ----------------
__global__ __launch_bounds__(256) void c_prep(
    const float* __restrict__ people, const float* __restrict__ objects,
    const float* __restrict__ context, const float* __restrict__ spatial,
    const float* __restrict__ Wvis_w, const float* __restrict__ Who_w,
    const float* __restrict__ Woh_w,  const float* __restrict__ Wspat_w,
    const float* __restrict__ Wip_w,  const float* __restrict__ Wref_w,
    const float* __restrict__ Watt_w)
{
    __shared__ float t[32][33];
    int bid = blockIdx.x;
    int tid = threadIdx.x;

    if (bid < 8704) {                                 // ---- convA (hi/lo) ----
        int idx = bid*256 + tid;
        const float* src; __half *dh, *dl; int e;
        if (idx < 1048576)      { src = people;  dh = g_peh; dl = g_pel; e = idx; }
        else if (idx < 2097152) { src = objects; dh = g_obh; dl = g_obl; e = idx - 1048576; }
        else                    { src = context; dh = g_cxh; dl = g_cxl; e = idx - 2097152; }
        float v = 0.f;
        if (dh != g_cxh || (e >> 10) < 64) v = src[e];
        __half h = __float2half(v);
        dh[e] = h;
        dl[e] = __float2half(v - __half2float(h));
    } else if (bid < 12288) {                         // ---- convB (transpose, hi only) ----
        int lb = bid - 8704;
        const float* W; __half *dh; int N, local;
        if (lb < 512)        { W = Wvis_w;            dh = g_Bv0h; N = 512;  local = lb;       }
        else if (lb < 1024)  { W = Wvis_w + 1024*512; dh = g_Bv1h; N = 512;  local = lb - 512; }
        else if (lb < 1536)  { W = Wvis_w + 2048*512; dh = g_Bv2h; N = 512;  local = lb - 1024;}
        else if (lb < 2560)  { W = Who_w;             dh = g_Whoh; N = 1024; local = lb - 1536;}
        else                 { W = Woh_w;             dh = g_Wohh; N = 1024; local = lb - 2560;}
        int ntN = N >> 5;
        int k0 = (local / ntN) * 32, n0 = (local % ntN) * 32;
        #pragma unroll
        for (int i = 0; i < 4; i++) {
            int e = tid + i*256, r = e >> 5, c = e & 31;
            t[r][c] = W[(k0 + r)*N + n0 + c];
        }
        __syncthreads();
        #pragma unroll
        for (int i = 0; i < 4; i++) {
            int e = tid + i*256, r = e >> 5, c = e & 31;
            dh[(n0 + r)*1024 + k0 + c] = __float2half(t[c][r]);
        }
    } else if (bid < 12416) {                         // ---- head-weight pack (hi only) ----
        int idx = (bid - 12288)*256 + tid;
        int c = idx >> 9, k = idx & 511;
        float v = 0.f;
        if (c == 0)                  v = Wip_w[k];
        else if (c <= 29)            v = Wref_w[k*29 + c - 1];
        else if (c >= 32 && c <= 60) v = Watt_w[k*29 + c - 32];
        g_Wcath[idx] = __float2half(v);
    } else if (bid < 14464) {                         // ---- spatial conv (hi/lo) ----
        int idx = (bid - 12416)*256 + tid;            // 524288
        float v = spatial[idx];
        __half h = __float2half(v);
        g_sph[idx] = h;
        g_spl[idx] = __float2half(v - __half2float(h));
    } else {                                          // ---- Wspat^T (hi only) ----
        int idx = (bid - 14464)*256 + tid;            // 16384
        g_Wsh[idx] = __float2half(Wspat_w[(idx & 31)*512 + (idx >> 5)]);
    }
}

// ---------------- k1: warp-MMA fp16 2-term split GEMM, 128x64 tiles ----------------
#define KP 40
#define TA (128*KP*2)
#define TB (64*KP*2)
#define STAGE_B (2*TA + TB)          // Ah, Al, Bh = 25600
#define K1_SMEM (2*STAGE_B)          // 51200

__global__ __launch_bounds__(128,3) void k1_mma(
    const float* __restrict__ Wvis_b,
    const float* __restrict__ Who_b,
    const float* __restrict__ Woh_b)
{
    extern __shared__ char smem[];
    u32 sb = smem_u32(smem);
    int tid = threadIdx.x, lane = tid & 31, wid = tid >> 5;
    int wm = wid & 1, wn = wid >> 1;
    int bid = blockIdx.x;

    const __half *Ah, *Al, *Bh;
    float* C; const float* bias = 0;
    int relu = 0, Mv = 1024, N, mt0, nt0, local;
    if (bid < 64)       { Ah=g_peh; Al=g_pel; Bh=g_Bv0h; C=g_Pvis; N=512;  local=bid;     mt0=local>>3; nt0=local&7; }
    else if (bid < 128) { Ah=g_obh; Al=g_obl; Bh=g_Bv1h; C=g_Ovis; N=512;  local=bid-64;  mt0=local>>3; nt0=local&7; }
    else if (bid < 136) { Ah=g_cxh; Al=g_cxl; Bh=g_Bv2h; C=g_Cvis; N=512;  local=bid-128; mt0=0; nt0=local; bias=Wvis_b; Mv=64; }
    else if (bid < 264) { Ah=g_peh; Al=g_pel; Bh=g_Whoh; C=g_HO;   N=1024; local=bid-136; mt0=local>>4; nt0=local&15; bias=Who_b; relu=1; }
    else                { Ah=g_obh; Al=g_obl; Bh=g_Wohh; C=g_OH;   N=1024; local=bid-264; mt0=local>>4; nt0=local&15; bias=Woh_b; relu=1; }
    int m0 = mt0 * 128, n0 = nt0 * 64;

    float acc[4][4][4];
    #pragma unroll
    for (int i = 0; i < 4; i++)
        #pragma unroll
        for (int j = 0; j < 4; j++)
            #pragma unroll
            for (int q = 0; q < 4; q++) acc[i][j][q] = 0.f;

    int lg = lane >> 3, lr = lane & 7;
    int a_row_off = lr + ((lg & 1) << 3);
    int a_k_off   = (lg >> 1) << 3;
    int b4_row_off = ((lane >> 4) << 3) + lr;
    int b4_k_off   = ((lane >> 3) & 1) << 3;

    #define LOAD_STAGE(KT, S) do {                                                    \
        u32 _s = (S); int _kt = (KT);                                                 \
        _Pragma("unroll")                                                             \
        for (int i = 0; i < 4; i++) {                                                 \
            int e = tid + i*128, row = e >> 2, sg = (e & 3) * 8;                      \
            cp16(_s      + (row*KP + sg)*2, &Ah[(m0 + row)*1024 + _kt + sg]);         \
            cp16(_s + TA + (row*KP + sg)*2, &Al[(m0 + row)*1024 + _kt + sg]);         \
        }                                                                             \
        _Pragma("unroll")                                                             \
        for (int i = 0; i < 2; i++) {                                                 \
            int e = tid + i*128, row = e >> 2, sg = (e & 3) * 8;                      \
            cp16(_s + 2*TA + (row*KP + sg)*2, &Bh[(n0 + row)*1024 + _kt + sg]);       \
        }                                                                             \
        asm volatile("cp.async.commit_group;");                                       \
    } while(0)

    LOAD_STAGE(0, sb);

    for (int c = 0; c < 32; c++) {
        asm volatile("cp.async.wait_group 0;");
        __syncthreads();
        if (c < 31) LOAD_STAGE((c + 1)*32, sb + ((c + 1) & 1)*STAGE_B);

        u32 st  = sb + (c & 1)*STAGE_B;
        u32 sAh = st, sAl = st + TA, sBh = st + 2*TA;

        #pragma unroll
        for (int ks = 0; ks < 32; ks += 16) {
            u32 bh[4][2];
            #pragma unroll
            for (int j = 0; j < 2; j++) {
                u32 boff = ((wn*32 + j*16 + b4_row_off)*KP + ks + b4_k_off) * 2;
                u32 r4[4];
                ldm_x4(r4, sBh + boff);
                bh[j*2][0] = r4[0]; bh[j*2][1] = r4[1]; bh[j*2+1][0] = r4[2]; bh[j*2+1][1] = r4[3];
            }
            #pragma unroll
            for (int mt = 0; mt < 4; mt++) {
                u32 aoff = ((wm*64 + mt*16 + a_row_off)*KP + ks + a_k_off) * 2;
                u32 ah[4], al[4];
                ldm_x4(ah, sAh + aoff);
                ldm_x4(al, sAl + aoff);
                #pragma unroll
                for (int nt = 0; nt < 4; nt++) {
                    mma_f16(acc[mt][nt], ah, bh[nt]);
                    mma_f16(acc[mt][nt], al, bh[nt]);
                }
            }
        }
    }

    int rq = lane >> 2, cq = (lane & 3) * 2;
    #pragma unroll
    for (int mt = 0; mt < 4; mt++) {
        int gmA = m0 + wm*64 + mt*16 + rq;
        int gmB = gmA + 8;
        #pragma unroll
        for (int nt = 0; nt < 4; nt++) {
            int gn = n0 + wn*32 + nt*8 + cq;
            float b0 = bias ? bias[gn]   : 0.f;
            float b1 = bias ? bias[gn+1] : 0.f;
            float v0 = acc[mt][nt][0] + b0, v1 = acc[mt][nt][1] + b1;
            float v2 = acc[mt][nt][2] + b0, v3 = acc[mt][nt][3] + b1;
            if (relu) { v0=fmaxf(v0,0.f); v1=fmaxf(v1,0.f); v2=fmaxf(v2,0.f); v3=fmaxf(v3,0.f); }
            if (gmA < Mv) *(float2*)&C[gmA*N + gn] = make_float2(v0, v1);
            if (gmB < Mv) *(float2*)&C[gmB*N + gn] = make_float2(v2, v3);
        }
    }
}

// ---------------- k2: per-(b,p) MMA phase1 (a_ho/f_ref) + MMA heads ----------------
#define K2P 520
#define OFF_AH  0
#define OFF_AL  1280
#define OFF_FAH 2560
#define OFF_FAL 35840
#define OFF_WH  69120
#define K2_SMEM 86528

__global__ __launch_bounds__(256,2) void k2_pairs(
    const float* __restrict__ Wspat_b,
    const float* __restrict__ Wip_b,   const float* __restrict__ Wref_b,
    const float* __restrict__ Watt_b,  float* __restrict__ out)
{
    extern __shared__ char sm2[];
    __half* s_fah = (__half*)(sm2 + OFF_FAH);   // [32][520]
    __half* s_fal = (__half*)(sm2 + OFF_FAL);
    __half* s_wh  = (__half*)(sm2 + OFF_WH);    // [64][136]

    int tid = threadIdx.x;
    int bp = blockIdx.x;
    int b = bp >> 4;
    int lane = tid & 31, wid = tid >> 5;

    // ---- phase 1: load spatial tile [16][32] fp16 h/l into smem (pitch 40) ----
    {
        int l = tid >> 4, kq = tid & 15;
        ((u32*)(sm2 + OFF_AH))[l*20 + kq] = ((const u32*)g_sph)[(bp*16 + l)*16 + kq];
        ((u32*)(sm2 + OFF_AL))[l*20 + kq] = ((const u32*)g_spl)[(bp*16 + l)*16 + kq];
    }
    __syncthreads();

    int lg = lane >> 3, lr = lane & 7;
    int a_row_off = lr + ((lg & 1) << 3);
    int a_koff = (lg >> 1) << 3;
    u32 ah0[4], ah1[4], al0[4], al1[4];
    {
        u32 bah = smem_u32(sm2 + OFF_AH), bal = smem_u32(sm2 + OFF_AL);
        u32 aoff = (a_row_off*40 + a_koff)*2;
        ldm_x4(ah0, bah + aoff);
        ldm_x4(ah1, bah + aoff + 32);
        ldm_x4(al0, bal + aoff);
        ldm_x4(al1, bal + aoff + 32);
    }

    // phase1 MMA: warp w covers n-cols w*64..+63 (2-term: B hi only)
    int lq = lane & 3, ln = lane >> 2;
    const u32* WshU = (const u32*)g_Wsh;
    #pragma unroll
    for (int nt = 0; nt < 8; nt++) {
        int n = wid*64 + nt*8 + ln;
        u32 bh[4];
        bh[0] = WshU[n*16 + lq];      bh[1] = WshU[n*16 + lq + 4];
        bh[2] = WshU[n*16 + lq + 8];  bh[3] = WshU[n*16 + lq + 12];
        float c[4] = {0.f, 0.f, 0.f, 0.f};
        mma_f16(c, ah0, bh);
        mma_f16(c, al0, bh);
        mma_f16(c, ah1, bh + 2);
        mma_f16(c, al1, bh + 2);

        // fused epilogue -> s_fah/s_fal
        int j0 = wid*64 + nt*8 + lq*2;
        int l0 = ln, l1 = ln + 8;
        float2 bs = *(const float2*)&Wspat_b[j0];
        float2 pv = *(const float2*)&g_Pvis[bp*512 + j0];
        float2 cv = *(const float2*)&g_Cvis[b*512 + j0];
        float2 o0 = *(const float2*)&g_Ovis[(b*16 + l0)*512 + j0];
        float2 o1 = *(const float2*)&g_Ovis[(b*16 + l1)*512 + j0];
        float a0 = fmaxf(c[0] + bs.x, 0.f), a1 = fmaxf(c[1] + bs.y, 0.f);
        float a2 = fmaxf(c[2] + bs.x, 0.f), a3 = fmaxf(c[3] + bs.y, 0.f);
        float f0 = fmaxf(pv.x + o0.x + cv.x, 0.f) * a0;
        float f1 = fmaxf(pv.y + o0.y + cv.y, 0.f) * a1;
        float f2 = fmaxf(pv.x + o1.x + cv.x, 0.f) * a2;
        float f3 = fmaxf(pv.y + o1.y + cv.y, 0.f) * a3;
        u32 lo, hi;
        hi = pack_hi(f0, f1, lo);
        *(u32*)&s_fah[l0*K2P + j0] = hi;        *(u32*)&s_fal[l0*K2P + j0] = lo;
        hi = pack_hi(f2, f3, lo);
        *(u32*)&s_fah[l1*K2P + j0] = hi;        *(u32*)&s_fal[l1*K2P + j0] = lo;
        hi = pack_hi(a0, a1, lo);
        *(u32*)&s_fah[(16 + l0)*K2P + j0] = hi; *(u32*)&s_fal[(16 + l0)*K2P + j0] = lo;
        hi = pack_hi(a2, a3, lo);
        *(u32*)&s_fah[(16 + l1)*K2P + j0] = hi; *(u32*)&s_fal[(16 + l1)*K2P + j0] = lo;
    }

    // ---- phase 2: [32 rows] @ heads via fp16 2-term MMA ----
    int mt = wid >> 2;
    int ntile = (wid & 3) + mt*4;

    u32 base_fah = smem_u32(s_fah), base_fal = smem_u32(s_fal);
    u32 base_wh  = smem_u32(s_wh);

    int a_row = mt*16 + lr + ((lg & 1) << 3);
    int b_row = ntile*8 + lr;
    int b4_koff = (lane >> 3) << 3;

    float acc2[4] = {0.f, 0.f, 0.f, 0.f};

    for (int kc = 0; kc < 4; kc++) {
        __syncthreads();
        #pragma unroll
        for (int i = 0; i < 4; i++) {
            int e = tid + i*256;
            int c = e >> 4, k8 = (e & 15) << 3;
            *(uint4*)&s_wh[c*136 + k8] = *(const uint4*)&g_Wcath[c*512 + kc*128 + k8];
        }
        __syncthreads();
        #pragma unroll
        for (int ks = 0; ks < 128; ks += 32) {
            u32 bh4[4];
            ldm_x4(bh4, base_wh + (b_row*136 + ks + b4_koff)*2);
            u32 xh0[4], xl0[4], xh1[4], xl1[4];
            ldm_x4(xh0, base_fah + (a_row*K2P + kc*128 + ks + a_koff)*2);
            ldm_x4(xl0, base_fal + (a_row*K2P + kc*128 + ks + a_koff)*2);
            ldm_x4(xh1, base_fah + (a_row*K2P + kc*128 + ks + 16 + a_koff)*2);
            ldm_x4(xl1, base_fal + (a_row*K2P + kc*128 + ks + 16 + a_koff)*2);
            mma_f16(acc2, xh0, bh4);
            mma_f16(acc2, xl0, bh4);
            mma_f16(acc2, xh1, bh4 + 2);
            mma_f16(acc2, xl1, bh4 + 2);
        }
    }

    // ---- outputs ----
    int r0 = mt*16 + (lane >> 2);
    int c0 = ntile*8 + (lane & 3)*2;
    #pragma unroll
    for (int q = 0; q < 4; q++) {
        int r = r0 + ((q >> 1) << 3);
        int c = c0 + (q & 1);
        float v = acc2[q];
        if (r < 16) {
            int cidx = bp*16 + r;
            if (c == 0) {
                v += Wip_b[0];
                out[cidx] = v;
                g_adj[cidx] = 1.f / (1.f + expf(-v));
            } else if (c <= 29) {
                out[16384 + cidx*29 + (c - 1)] = v + Wref_b[c - 1];
            }
        } else {
            int cidx = bp*16 + (r - 16);
            int cc = c - 32;
            if (cc >= 0 && cc <= 28) {
                out[491520 + cidx*29 + cc] = v + Watt_b[cc];
            }
        }
    }
}

// ---------------- k3a: message passing ----------------
__global__ __launch_bounds__(256) void k3a_msg(const float* __restrict__ people,
                                               const float* __restrict__ objects)
{
    __shared__ float adj[240];
    int bid = blockIdx.x;                 // 512
    int b = bid >> 3, ch = (bid >> 1) & 3, role = bid & 1;
    int tid = threadIdx.x;
    if (tid < 240) adj[tid] = g_adj[(b*16 + tid/15)*16 + (tid % 15) + 1];
    __syncthreads();

    int d = ch*256 + tid;
    if (role == 0) {
        float oh[15];
        #pragma unroll
        for (int o = 0; o < 15; o++) oh[o] = g_OH[(b*16 + o + 1)*1024 + d];
        #pragma unroll
        for (int p = 0; p < 16; p++) {
            float acc = people[(b*16 + p)*1024 + d];
            #pragma unroll
            for (int o = 0; o < 15; o++) acc += adj[p*15 + o] * oh[o];
            g_PR[(b*16 + p)*1024 + d] = acc;
        }
    } else {
        float ho[16];
        #pragma unroll
        for (int p = 0; p < 16; p++) ho[p] = g_HO[(b*16 + p)*1024 + d];
        g_OBF[(b*16)*1024 + d] = objects[(b*16)*1024 + d];
        #pragma unroll
        for (int o = 0; o < 15; o++) {
            float acc = objects[(b*16 + o + 1)*1024 + d];
            #pragma unroll
            for (int p = 0; p < 16; p++) acc += adj[p*15 + o] * ho[p];
            g_OBF[(b*16 + o + 1)*1024 + d] = acc;
        }
    }
}

// ---------------- k3b: skinny GEMM [2048,1024]@[1024,29] warp-per-row ----------------
__global__ __launch_bounds__(256) void k3b_gemm(const float* __restrict__ Wg_w,
                                                const float* __restrict__ Wg_b)
{
    __shared__ float Ws[256*33];
    int half = blockIdx.x >> 7;
    int row = (blockIdx.x & 127)*8 + (threadIdx.x >> 5);
    int lane = threadIdx.x & 31;
    const float* src = half ? g_OBF : g_PR;
    const float* W = Wg_w + half*1024*29;
    float* dst = half ? g_Go : g_Gp;

    float acc[29];
    #pragma unroll
    for (int a = 0; a < 29; a++) acc[a] = 0.f;

    for (int kt = 0; kt < 4; kt++) {
        __syncthreads();
        #pragma unroll
        for (int i = 0; i < 29; i++) {
            int idx = threadIdx.x + i*256;
            int k = idx / 29, a = idx - k*29;
            Ws[k*33 + a] = W[kt*7424 + idx];
        }
        __syncthreads();
        #pragma unroll
        for (int t = 0; t < 8; t++) {
            int k = t*32 + lane;
            float rv = src[row*1024 + kt*256 + k];
            #pragma unroll
            for (int a = 0; a < 29; a++) acc[a] += rv * Ws[k*33 + a];
        }
    }
    #pragma unroll
    for (int off = 16; off; off >>= 1)
        #pragma unroll
        for (int a = 0; a < 29; a++)
            acc[a] += __shfl_down_sync(0xffffffffu, acc[a], off);
    if (lane == 0) {
        #pragma unroll
        for (int a = 0; a < 29; a++)
            dst[row*29 + a] = acc[a] + (half ? Wg_b[a] : 0.f);
    }
}

// ---------------- k3c: broadcast add -> p_graph ----------------
__global__ __launch_bounds__(256) void k3c_add(float* __restrict__ out_pg)
{
    int idx = blockIdx.x*256 + threadIdx.x;
    int c = idx / 29;
    int a = idx - c*29;
    int prow = c >> 4;
    int lrow = (c >> 8)*16 + (c & 15);
    out_pg[idx] = g_Gp[prow*29 + a] + g_Go[lrow*29 + a];
}

// ---------------- launch ----------------
extern "C" void kernel_launch(void* const* d_in, const int* in_sizes, int n_in,
                              void* d_out, int out_size) {
    const float* people  = (const float*)d_in[0];
    const float* objects = (const float*)d_in[1];
    const float* context = (const float*)d_in[2];
    const float* spatial = (const float*)d_in[3];
    const float* Wvis_w  = (const float*)d_in[4];
    const float* Wvis_b  = (const float*)d_in[5];
    const float* Wspat_w = (const float*)d_in[6];
    const float* Wspat_b = (const float*)d_in[7];
    const float* Wip_w   = (const float*)d_in[8];
    const float* Wip_b   = (const float*)d_in[9];
    const float* Wref_w  = (const float*)d_in[10];
    const float* Wref_b  = (const float*)d_in[11];
    const float* Watt_w  = (const float*)d_in[12];
    const float* Watt_b  = (const float*)d_in[13];
    const float* Woh_w   = (const float*)d_in[14];
    const float* Woh_b   = (const float*)d_in[15];
    const float* Who_w   = (const float*)d_in[16];
    const float* Who_b   = (const float*)d_in[17];
    const float* Wg_w    = (const float*)d_in[18];
    const float* Wg_b    = (const float*)d_in[19];
    float* out = (float*)d_out;

    cudaFuncSetAttribute(k1_mma,  cudaFuncAttributeMaxDynamicSharedMemorySize, K1_SMEM);
    cudaFuncSetAttribute(k2_pairs, cudaFuncAttributeMaxDynamicSharedMemorySize, K2_SMEM);

    c_prep<<<14528, 256>>>(people, objects, context, spatial,
                           Wvis_w, Who_w, Woh_w, Wspat_w,
                           Wip_w, Wref_w, Watt_w);
    k1_mma<<<392, 128, K1_SMEM>>>(Wvis_b, Who_b, Woh_b);
    k2_pairs<<<1024, 256, K2_SMEM>>>(Wspat_b, Wip_b, Wref_b, Watt_b, out);
    k3a_msg<<<512, 256>>>(people, objects);
    k3b_gemm<<<256, 256>>>(Wg_w, Wg_b);
    k3c_add<<<1856, 256>>>(out + 966656);
}

// round 11
// speedup vs baseline: 2.9270x; 1.0166x over previous
#include <cuda_runtime.h>
#include <cuda_fp16.h>
#include <math.h>

typedef unsigned long long ull;
typedef unsigned int u32;

// ---------------- device scratch (allocations are forbidden) ----------------
__device__ float g_Pvis[1024*512];   // people  @ Wvis[0:1024]
__device__ float g_Ovis[1024*512];   // objects @ Wvis[1024:2048]
__device__ float g_Cvis[64*512];     // context @ Wvis[2048:3072] + Wvis_b
__device__ float g_HO[1024*1024];    // relu(people  @ Who + b)
__device__ float g_OH[1024*1024];    // relu(objects @ Woh + b)
__device__ float g_adj[16384];       // sigmoid(i_ho)
__device__ float g_PR[1024*1024];    // people_r
__device__ float g_OBF[1024*1024];   // objects_full
__device__ float g_Gp[1024*29];
__device__ float g_Go[1024*29];

// packed head weights, fp16 hi only, [c=64][k=512]
__device__ __half g_Wcath[64*512];

// fp16 pre-converted operands (A side hi/lo, B side hi only)
__device__ __half g_peh[1024*1024], g_pel[1024*1024];
__device__ __half g_obh[1024*1024], g_obl[1024*1024];
__device__ __half g_cxh[128*1024],  g_cxl[128*1024];
__device__ __half g_Bv0h[512*1024];
__device__ __half g_Bv1h[512*1024];
__device__ __half g_Bv2h[512*1024];
__device__ __half g_Whoh[1024*1024];
__device__ __half g_Wohh[1024*1024];
__device__ __half g_sph[16384*32], g_spl[16384*32];   // spatial h/l
__device__ __half g_Wsh[512*32];                      // Wspat^T [n][k] hi

// ---------------- small helpers ----------------
__device__ __forceinline__ u32 smem_u32(const void* p){
    u32 a; asm("{ .reg .u64 t; cvta.to.shared.u64 t, %1; cvt.u32.u64 %0, t; }":"=r"(a):"l"(p)); return a;
}
__device__ __forceinline__ void ldm_x4(u32* r, u32 addr){
    asm volatile("ldmatrix.sync.aligned.m8n8.x4.shared.b16 {%0,%1,%2,%3}, [%4];"
        :"=r"(r[0]),"=r"(r[1]),"=r"(r[2]),"=r"(r[3]):"r"(addr));
}
__device__ __forceinline__ void mma_f16(float* c, const u32* a, const u32* b){
    asm volatile("mma.sync.aligned.m16n8k16.row.col.f32.f16.f16.f32 "
        "{%0,%1,%2,%3}, {%4,%5,%6,%7}, {%8,%9}, {%0,%1,%2,%3};"
        :"+f"(c[0]),"+f"(c[1]),"+f"(c[2]),"+f"(c[3])
        :"r"(a[0]),"r"(a[1]),"r"(a[2]),"r"(a[3]),"r"(b[0]),"r"(b[1]));
}
__device__ __forceinline__ void cp16(u32 dst, const void* src){
    asm volatile("cp.async.cg.shared.global [%0], [%1], 16;"::"r"(dst),"l"(src));
}
// pack (x,y) -> fp16x2 hi word + residual lo word
__device__ __forceinline__ u32 pack_hi(float x, float y, u32& lo){
    __half hx = __float2half(x), hy = __float2half(y);
    float rx = x - __half2float(hx), ry = y - __half2float(hy);
    __half lx = __float2half(rx), ly = __float2half(ry);
    unsigned short ux = *(unsigned short*)&hx, uy = *(unsigned short*)&hy;
    unsigned short vx = *(unsigned short*)&lx, vy = *(unsigned short*)&ly;
    lo = ((u32)vy << 16) | vx;
    return ((u32)uy << 16) | ux;
}

// ---------------- c_prep: all fp32->fp16 conversions + packs ----------------
__global__ __launch_bounds__(256) void c_prep(
    const float* __restrict__ people, const float* __restrict__ objects,
    const float* __restrict__ context, const float* __restrict__ spatial,
    const float* __restrict__ Wvis_w, const float* __restrict__ Who_w,
    const float* __restrict__ Woh_w,  const float* __restrict__ Wspat_w,
    const float* __restrict__ Wip_w,  const float* __restrict__ Wref_w,
    const float* __restrict__ Watt_w)
{
    __shared__ float t[32][33];
    int bid = blockIdx.x;
    int tid = threadIdx.x;

    if (bid < 8704) {                                 // ---- convA (hi/lo) ----
        int idx = bid*256 + tid;
        const float* src; __half *dh, *dl; int e;
        if (idx < 1048576)      { src = people;  dh = g_peh; dl = g_pel; e = idx; }
        else if (idx < 2097152) { src = objects; dh = g_obh; dl = g_obl; e = idx - 1048576; }
        else                    { src = context; dh = g_cxh; dl = g_cxl; e = idx - 2097152; }
        float v = 0.f;
        if (dh != g_cxh || (e >> 10) < 64) v = src[e];
        __half h = __float2half(v);
        dh[e] = h;
        dl[e] = __float2half(v - __half2float(h));
    } else if (bid < 12288) {                         // ---- convB (transpose, hi only) ----
        int lb = bid - 8704;
        const float* W; __half *dh; int N, local;
        if (lb < 512)        { W = Wvis_w;            dh = g_Bv0h; N = 512;  local = lb;       }
        else if (lb < 1024)  { W = Wvis_w + 1024*512; dh = g_Bv1h; N = 512;  local = lb - 512; }
        else if (lb < 1536)  { W = Wvis_w + 2048*512; dh = g_Bv2h; N = 512;  local = lb - 1024;}
        else if (lb < 2560)  { W = Who_w;             dh = g_Whoh; N = 1024; local = lb - 1536;}
        else                 { W = Woh_w;             dh = g_Wohh; N = 1024; local = lb - 2560;}
        int ntN = N >> 5;
        int k0 = (local / ntN) * 32, n0 = (local % ntN) * 32;
        #pragma unroll
        for (int i = 0; i < 4; i++) {
            int e = tid + i*256, r = e >> 5, c = e & 31;
            t[r][c] = W[(k0 + r)*N + n0 + c];
        }
        __syncthreads();
        #pragma unroll
        for (int i = 0; i < 4; i++) {
            int e = tid + i*256, r = e >> 5, c = e & 31;
            dh[(n0 + r)*1024 + k0 + c] = __float2half(t[c][r]);
        }
    } else if (bid < 12416) {                         // ---- head-weight pack (hi only) ----
        int idx = (bid - 12288)*256 + tid;
        int c = idx >> 9, k = idx & 511;
        float v = 0.f;
        if (c == 0)                  v = Wip_w[k];
        else if (c <= 29)            v = Wref_w[k*29 + c - 1];
        else if (c >= 32 && c <= 60) v = Watt_w[k*29 + c - 32];
        g_Wcath[idx] = __float2half(v);
    } else if (bid < 14464) {                         // ---- spatial conv (hi/lo) ----
        int idx = (bid - 12416)*256 + tid;            // 524288
        float v = spatial[idx];
        __half h = __float2half(v);
        g_sph[idx] = h;
        g_spl[idx] = __float2half(v - __half2float(h));
    } else {                                          // ---- Wspat^T (hi only) ----
        int idx = (bid - 14464)*256 + tid;            // 16384
        g_Wsh[idx] = __float2half(Wspat_w[(idx & 31)*512 + (idx >> 5)]);
    }
}

// ---------------- k1: warp-MMA fp16 2-term split GEMM, 128x64 tiles ----------------
#define KP 40
#define TA (128*KP*2)
#define TB (64*KP*2)
#define STAGE_B (2*TA + TB)          // Ah, Al, Bh = 25600
#define K1_SMEM (2*STAGE_B)          // 51200

__global__ __launch_bounds__(128,3) void k1_mma(
    const float* __restrict__ Wvis_b,
    const float* __restrict__ Who_b,
    const float* __restrict__ Woh_b,
    int boff)
{
    extern __shared__ char smem[];
    u32 sb = smem_u32(smem);
    int tid = threadIdx.x, lane = tid & 31, wid = tid >> 5;
    int wm = wid & 1, wn = wid >> 1;
    int bid = blockIdx.x + boff;

    const __half *Ah, *Al, *Bh;
    float* C; const float* bias = 0;
    int relu = 0, Mv = 1024, N, mt0, nt0, local;
    if (bid < 64)       { Ah=g_peh; Al=g_pel; Bh=g_Bv0h; C=g_Pvis; N=512;  local=bid;     mt0=local>>3; nt0=local&7; }
    else if (bid < 128) { Ah=g_obh; Al=g_obl; Bh=g_Bv1h; C=g_Ovis; N=512;  local=bid-64;  mt0=local>>3; nt0=local&7; }
    else if (bid < 136) { Ah=g_cxh; Al=g_cxl; Bh=g_Bv2h; C=g_Cvis; N=512;  local=bid-128; mt0=0; nt0=local; bias=Wvis_b; Mv=64; }
    else if (bid < 264) { Ah=g_peh; Al=g_pel; Bh=g_Whoh; C=g_HO;   N=1024; local=bid-136; mt0=local>>4; nt0=local&15; bias=Who_b; relu=1; }
    else                { Ah=g_obh; Al=g_obl; Bh=g_Wohh; C=g_OH;   N=1024; local=bid-264; mt0=local>>4; nt0=local&15; bias=Woh_b; relu=1; }
    int m0 = mt0 * 128, n0 = nt0 * 64;

    float acc[4][4][4];
    #pragma unroll
    for (int i = 0; i < 4; i++)
        #pragma unroll
        for (int j = 0; j < 4; j++)
            #pragma unroll
            for (int q = 0; q < 4; q++) acc[i][j][q] = 0.f;

    int lg = lane >> 3, lr = lane & 7;
    int a_row_off = lr + ((lg & 1) << 3);
    int a_k_off   = (lg >> 1) << 3;
    int b4_row_off = ((lane >> 4) << 3) + lr;
    int b4_k_off   = ((lane >> 3) & 1) << 3;

    #define LOAD_STAGE(KT, S) do {                                                    \
        u32 _s = (S); int _kt = (KT);                                                 \
        _Pragma("unroll")                                                             \
        for (int i = 0; i < 4; i++) {                                                 \
            int e = tid + i*128, row = e >> 2, sg = (e & 3) * 8;                      \
            cp16(_s      + (row*KP + sg)*2, &Ah[(m0 + row)*1024 + _kt + sg]);         \
            cp16(_s + TA + (row*KP + sg)*2, &Al[(m0 + row)*1024 + _kt + sg]);         \
        }                                                                             \
        _Pragma("unroll")                                                             \
        for (int i = 0; i < 2; i++) {                                                 \
            int e = tid + i*128, row = e >> 2, sg = (e & 3) * 8;                      \
            cp16(_s + 2*TA + (row*KP + sg)*2, &Bh[(n0 + row)*1024 + _kt + sg]);       \
        }                                                                             \
        asm volatile("cp.async.commit_group;");                                       \
    } while(0)

    LOAD_STAGE(0, sb);

    for (int c = 0; c < 32; c++) {
        asm volatile("cp.async.wait_group 0;");
        __syncthreads();
        if (c < 31) LOAD_STAGE((c + 1)*32, sb + ((c + 1) & 1)*STAGE_B);

        u32 st  = sb + (c & 1)*STAGE_B;
        u32 sAh = st, sAl = st + TA, sBh = st + 2*TA;

        #pragma unroll
        for (int ks = 0; ks < 32; ks += 16) {
            u32 bh[4][2];
            #pragma unroll
            for (int j = 0; j < 2; j++) {
                u32 boff2 = ((wn*32 + j*16 + b4_row_off)*KP + ks + b4_k_off) * 2;
                u32 r4[4];
                ldm_x4(r4, sBh + boff2);
                bh[j*2][0] = r4[0]; bh[j*2][1] = r4[1]; bh[j*2+1][0] = r4[2]; bh[j*2+1][1] = r4[3];
            }
            #pragma unroll
            for (int mt = 0; mt < 4; mt++) {
                u32 aoff = ((wm*64 + mt*16 + a_row_off)*KP + ks + a_k_off) * 2;
                u32 ah[4], al[4];
                ldm_x4(ah, sAh + aoff);
                ldm_x4(al, sAl + aoff);
                #pragma unroll
                for (int nt = 0; nt < 4; nt++) {
                    mma_f16(acc[mt][nt], ah, bh[nt]);
                    mma_f16(acc[mt][nt], al, bh[nt]);
                }
            }
        }
    }

    int rq = lane >> 2, cq = (lane & 3) * 2;
    #pragma unroll
    for (int mt = 0; mt < 4; mt++) {
        int gmA = m0 + wm*64 + mt*16 + rq;
        int gmB = gmA + 8;
        #pragma unroll
        for (int nt = 0; nt < 4; nt++) {
            int gn = n0 + wn*32 + nt*8 + cq;
            float b0 = bias ? bias[gn]   : 0.f;
            float b1 = bias ? bias[gn+1] : 0.f;
            float v0 = acc[mt][nt][0] + b0, v1 = acc[mt][nt][1] + b1;
            float v2 = acc[mt][nt][2] + b0, v3 = acc[mt][nt][3] + b1;
            if (relu) { v0=fmaxf(v0,0.f); v1=fmaxf(v1,0.f); v2=fmaxf(v2,0.f); v3=fmaxf(v3,0.f); }
            if (gmA < Mv) *(float2*)&C[gmA*N + gn] = make_float2(v0, v1);
            if (gmB < Mv) *(float2*)&C[gmB*N + gn] = make_float2(v2, v3);
        }
    }
}

// ---------------- k2: per-(b,p) MMA phase1 (a_ho/f_ref) + MMA heads ----------------
#define K2P 520
#define OFF_AH  0
#define OFF_AL  1280
#define OFF_FAH 2560
#define OFF_FAL 35840
#define OFF_WH  69120
#define K2_SMEM 86528

__global__ __launch_bounds__(256,2) void k2_pairs(
    const float* __restrict__ Wspat_b,
    const float* __restrict__ Wip_b,   const float* __restrict__ Wref_b,
    const float* __restrict__ Watt_b,  float* __restrict__ out)
{
    extern __shared__ char sm2[];
    __half* s_fah = (__half*)(sm2 + OFF_FAH);   // [32][520]
    __half* s_fal = (__half*)(sm2 + OFF_FAL);
    __half* s_wh  = (__half*)(sm2 + OFF_WH);    // [64][136]

    int tid = threadIdx.x;
    int bp = blockIdx.x;
    int b = bp >> 4;
    int lane = tid & 31, wid = tid >> 5;

    // ---- phase 1: load spatial tile [16][32] fp16 h/l into smem (pitch 40) ----
    {
        int l = tid >> 4, kq = tid & 15;
        ((u32*)(sm2 + OFF_AH))[l*20 + kq] = ((const u32*)g_sph)[(bp*16 + l)*16 + kq];
        ((u32*)(sm2 + OFF_AL))[l*20 + kq] = ((const u32*)g_spl)[(bp*16 + l)*16 + kq];
    }
    __syncthreads();

    int lg = lane >> 3, lr = lane & 7;
    int a_row_off = lr + ((lg & 1) << 3);
    int a_koff = (lg >> 1) << 3;
    u32 ah0[4], ah1[4], al0[4], al1[4];
    {
        u32 bah = smem_u32(sm2 + OFF_AH), bal = smem_u32(sm2 + OFF_AL);
        u32 aoff = (a_row_off*40 + a_koff)*2;
        ldm_x4(ah0, bah + aoff);
        ldm_x4(ah1, bah + aoff + 32);
        ldm_x4(al0, bal + aoff);
        ldm_x4(al1, bal + aoff + 32);
    }

    // phase1 MMA: warp w covers n-cols w*64..+63 (2-term: B hi only)
    int lq = lane & 3, ln = lane >> 2;
    const u32* WshU = (const u32*)g_Wsh;
    #pragma unroll
    for (int nt = 0; nt < 8; nt++) {
        int n = wid*64 + nt*8 + ln;
        u32 bh[4];
        bh[0] = WshU[n*16 + lq];      bh[1] = WshU[n*16 + lq + 4];
        bh[2] = WshU[n*16 + lq + 8];  bh[3] = WshU[n*16 + lq + 12];
        float c[4] = {0.f, 0.f, 0.f, 0.f};
        mma_f16(c, ah0, bh);
        mma_f16(c, al0, bh);
        mma_f16(c, ah1, bh + 2);
        mma_f16(c, al1, bh + 2);

        // fused epilogue -> s_fah/s_fal
        int j0 = wid*64 + nt*8 + lq*2;
        int l0 = ln, l1 = ln + 8;
        float2 bs = *(const float2*)&Wspat_b[j0];
        float2 pv = *(const float2*)&g_Pvis[bp*512 + j0];
        float2 cv = *(const float2*)&g_Cvis[b*512 + j0];
        float2 o0 = *(const float2*)&g_Ovis[(b*16 + l0)*512 + j0];
        float2 o1 = *(const float2*)&g_Ovis[(b*16 + l1)*512 + j0];
        float a0 = fmaxf(c[0] + bs.x, 0.f), a1 = fmaxf(c[1] + bs.y, 0.f);
        float a2 = fmaxf(c[2] + bs.x, 0.f), a3 = fmaxf(c[3] + bs.y, 0.f);
        float f0 = fmaxf(pv.x + o0.x + cv.x, 0.f) * a0;
        float f1 = fmaxf(pv.y + o0.y + cv.y, 0.f) * a1;
        float f2 = fmaxf(pv.x + o1.x + cv.x, 0.f) * a2;
        float f3 = fmaxf(pv.y + o1.y + cv.y, 0.f) * a3;
        u32 lo, hi;
        hi = pack_hi(f0, f1, lo);
        *(u32*)&s_fah[l0*K2P + j0] = hi;        *(u32*)&s_fal[l0*K2P + j0] = lo;
        hi = pack_hi(f2, f3, lo);
        *(u32*)&s_fah[l1*K2P + j0] = hi;        *(u32*)&s_fal[l1*K2P + j0] = lo;
        hi = pack_hi(a0, a1, lo);
        *(u32*)&s_fah[(16 + l0)*K2P + j0] = hi; *(u32*)&s_fal[(16 + l0)*K2P + j0] = lo;
        hi = pack_hi(a2, a3, lo);
        *(u32*)&s_fah[(16 + l1)*K2P + j0] = hi; *(u32*)&s_fal[(16 + l1)*K2P + j0] = lo;
    }

    // ---- phase 2: [32 rows] @ heads via fp16 2-term MMA ----
    int mt = wid >> 2;
    int ntile = (wid & 3) + mt*4;

    u32 base_fah = smem_u32(s_fah), base_fal = smem_u32(s_fal);
    u32 base_wh  = smem_u32(s_wh);

    int a_row = mt*16 + lr + ((lg & 1) << 3);
    int b_row = ntile*8 + lr;
    int b4_koff = (lane >> 3) << 3;

    float acc2[4] = {0.f, 0.f, 0.f, 0.f};

    for (int kc = 0; kc < 4; kc++) {
        __syncthreads();
        #pragma unroll
        for (int i = 0; i < 4; i++) {
            int e = tid + i*256;
            int c = e >> 4, k8 = (e & 15) << 3;
            *(uint4*)&s_wh[c*136 + k8] = *(const uint4*)&g_Wcath[c*512 + kc*128 + k8];
        }
        __syncthreads();
        #pragma unroll
        for (int ks = 0; ks < 128; ks += 32) {
            u32 bh4[4];
            ldm_x4(bh4, base_wh + (b_row*136 + ks + b4_koff)*2);
            u32 xh0[4], xl0[4], xh1[4], xl1[4];
            ldm_x4(xh0, base_fah + (a_row*K2P + kc*128 + ks + a_koff)*2);
            ldm_x4(xl0, base_fal + (a_row*K2P + kc*128 + ks + a_koff)*2);
            ldm_x4(xh1, base_fah + (a_row*K2P + kc*128 + ks + 16 + a_koff)*2);
            ldm_x4(xl1, base_fal + (a_row*K2P + kc*128 + ks + 16 + a_koff)*2);
            mma_f16(acc2, xh0, bh4);
            mma_f16(acc2, xl0, bh4);
            mma_f16(acc2, xh1, bh4 + 2);
            mma_f16(acc2, xl1, bh4 + 2);
        }
    }

    // ---- outputs ----
    int r0 = mt*16 + (lane >> 2);
    int c0 = ntile*8 + (lane & 3)*2;
    #pragma unroll
    for (int q = 0; q < 4; q++) {
        int r = r0 + ((q >> 1) << 3);
        int c = c0 + (q & 1);
        float v = acc2[q];
        if (r < 16) {
            int cidx = bp*16 + r;
            if (c == 0) {
                v += Wip_b[0];
                out[cidx] = v;
                g_adj[cidx] = 1.f / (1.f + expf(-v));
            } else if (c <= 29) {
                out[16384 + cidx*29 + (c - 1)] = v + Wref_b[c - 1];
            }
        } else {
            int cidx = bp*16 + (r - 16);
            int cc = c - 32;
            if (cc >= 0 && cc <= 28) {
                out[491520 + cidx*29 + cc] = v + Watt_b[cc];
            }
        }
    }
}

// ---------------- k3a: message passing ----------------
__global__ __launch_bounds__(256) void k3a_msg(const float* __restrict__ people,
                                               const float* __restrict__ objects)
{
    __shared__ float adj[240];
    int bid = blockIdx.x;                 // 512
    int b = bid >> 3, ch = (bid >> 1) & 3, role = bid & 1;
    int tid = threadIdx.x;
    if (tid < 240) adj[tid] = g_adj[(b*16 + tid/15)*16 + (tid % 15) + 1];
    __syncthreads();

    int d = ch*256 + tid;
    if (role == 0) {
        float oh[15];
        #pragma unroll
        for (int o = 0; o < 15; o++) oh[o] = g_OH[(b*16 + o + 1)*1024 + d];
        #pragma unroll
        for (int p = 0; p < 16; p++) {
            float acc = people[(b*16 + p)*1024 + d];
            #pragma unroll
            for (int o = 0; o < 15; o++) acc += adj[p*15 + o] * oh[o];
            g_PR[(b*16 + p)*1024 + d] = acc;
        }
    } else {
        float ho[16];
        #pragma unroll
        for (int p = 0; p < 16; p++) ho[p] = g_HO[(b*16 + p)*1024 + d];
        g_OBF[(b*16)*1024 + d] = objects[(b*16)*1024 + d];
        #pragma unroll
        for (int o = 0; o < 15; o++) {
            float acc = objects[(b*16 + o + 1)*1024 + d];
            #pragma unroll
            for (int p = 0; p < 16; p++) acc += adj[p*15 + o] * ho[p];
            g_OBF[(b*16 + o + 1)*1024 + d] = acc;
        }
    }
}

// ---------------- k3b: skinny GEMM [2048,1024]@[1024,29] warp-per-row ----------------
__global__ __launch_bounds__(256) void k3b_gemm(const float* __restrict__ Wg_w,
                                                const float* __restrict__ Wg_b)
{
    __shared__ float Ws[256*33];
    int half = blockIdx.x >> 7;
    int row = (blockIdx.x & 127)*8 + (threadIdx.x >> 5);
    int lane = threadIdx.x & 31;
    const float* src = half ? g_OBF : g_PR;
    const float* W = Wg_w + half*1024*29;
    float* dst = half ? g_Go : g_Gp;

    float acc[29];
    #pragma unroll
    for (int a = 0; a < 29; a++) acc[a] = 0.f;

    for (int kt = 0; kt < 4; kt++) {
        __syncthreads();
        #pragma unroll
        for (int i = 0; i < 29; i++) {
            int idx = threadIdx.x + i*256;
            int k = idx / 29, a = idx - k*29;
            Ws[k*33 + a] = W[kt*7424 + idx];
        }
        __syncthreads();
        #pragma unroll
        for (int t = 0; t < 8; t++) {
            int k = t*32 + lane;
            float rv = src[row*1024 + kt*256 + k];
            #pragma unroll
            for (int a = 0; a < 29; a++) acc[a] += rv * Ws[k*33 + a];
        }
    }
    #pragma unroll
    for (int off = 16; off; off >>= 1)
        #pragma unroll
        for (int a = 0; a < 29; a++)
            acc[a] += __shfl_down_sync(0xffffffffu, acc[a], off);
    if (lane == 0) {
        #pragma unroll
        for (int a = 0; a < 29; a++)
            dst[row*29 + a] = acc[a] + (half ? Wg_b[a] : 0.f);
    }
}

// ---------------- k3c: broadcast add -> p_graph ----------------
__global__ __launch_bounds__(256) void k3c_add(float* __restrict__ out_pg)
{
    int idx = blockIdx.x*256 + threadIdx.x;
    int c = idx / 29;
    int a = idx - c*29;
    int prow = c >> 4;
    int lrow = (c >> 8)*16 + (c & 15);
    out_pg[idx] = g_Gp[prow*29 + a] + g_Go[lrow*29 + a];
}

// ---------------- launch: fork k1b (HO/OH) onto side stream ----------------
extern "C" void kernel_launch(void* const* d_in, const int* in_sizes, int n_in,
                              void* d_out, int out_size) {
    const float* people  = (const float*)d_in[0];
    const float* objects = (const float*)d_in[1];
    const float* context = (const float*)d_in[2];
    const float* spatial = (const float*)d_in[3];
    const float* Wvis_w  = (const float*)d_in[4];
    const float* Wvis_b  = (const float*)d_in[5];
    const float* Wspat_w = (const float*)d_in[6];
    const float* Wspat_b = (const float*)d_in[7];
    const float* Wip_w   = (const float*)d_in[8];
    const float* Wip_b   = (const float*)d_in[9];
    const float* Wref_w  = (const float*)d_in[10];
    const float* Wref_b  = (const float*)d_in[11];
    const float* Watt_w  = (const float*)d_in[12];
    const float* Watt_b  = (const float*)d_in[13];
    const float* Woh_w   = (const float*)d_in[14];
    const float* Woh_b   = (const float*)d_in[15];
    const float* Who_w   = (const float*)d_in[16];
    const float* Who_b   = (const float*)d_in[17];
    const float* Wg_w    = (const float*)d_in[18];
    const float* Wg_b    = (const float*)d_in[19];
    float* out = (float*)d_out;

    cudaFuncSetAttribute(k1_mma,  cudaFuncAttributeMaxDynamicSharedMemorySize, K1_SMEM);
    cudaFuncSetAttribute(k2_pairs, cudaFuncAttributeMaxDynamicSharedMemorySize, K2_SMEM);

    cudaStream_t s1;
    cudaStreamCreateWithFlags(&s1, cudaStreamNonBlocking);
    cudaEvent_t ev0, ev1;
    cudaEventCreateWithFlags(&ev0, cudaEventDisableTiming);
    cudaEventCreateWithFlags(&ev1, cudaEventDisableTiming);

    // origin stream: prep
    c_prep<<<14528, 256>>>(people, objects, context, spatial,
                           Wvis_w, Who_w, Woh_w, Wspat_w,
                           Wip_w, Wref_w, Watt_w);

    // fork: k1b (HO/OH, blocks 136..391) on side stream
    cudaEventRecord(ev0, 0);
    cudaStreamWaitEvent(s1, ev0, 0);
    k1_mma<<<256, 128, K1_SMEM, s1>>>(Wvis_b, Who_b, Woh_b, 136);
    cudaEventRecord(ev1, s1);

    // origin stream: k1a (Pvis/Ovis/Cvis) then k2
    k1_mma<<<136, 128, K1_SMEM>>>(Wvis_b, Who_b, Woh_b, 0);
    k2_pairs<<<1024, 256, K2_SMEM>>>(Wspat_b, Wip_b, Wref_b, Watt_b, out);

    // join: k3 chain needs HO/OH (k1b) + g_adj (k2)
    cudaStreamWaitEvent(0, ev1, 0);
    k3a_msg<<<512, 256>>>(people, objects);
    k3b_gemm<<<256, 256>>>(Wg_w, Wg_b);
    k3c_add<<<1856, 256>>>(out + 966656);

    cudaEventDestroy(ev0);
    cudaEventDestroy(ev1);
    cudaStreamDestroy(s1);
}

// round 12
// speedup vs baseline: 3.0803x; 1.0524x over previous
#include <cuda_runtime.h>
#include <cuda_fp16.h>
#include <math.h>

typedef unsigned long long ull;
typedef unsigned int u32;

// ---------------- device scratch (allocations are forbidden) ----------------
__device__ float g_Pvis[1024*512];   // people  @ Wvis[0:1024]
__device__ float g_Ovis[1024*512];   // objects @ Wvis[1024:2048]
__device__ float g_Cvis[64*512];     // context @ Wvis[2048:3072] + Wvis_b
__device__ float g_HO[1024*1024];    // relu(people  @ Who + b)
__device__ float g_OH[1024*1024];    // relu(objects @ Woh + b)
__device__ float g_adj[16384];       // sigmoid(i_ho)
__device__ float g_PR[1024*1024];    // people_r
__device__ float g_OBF[1024*1024];   // objects_full
__device__ float g_Gp[1024*29];
__device__ float g_Go[1024*29];

// packed head weights, fp16 hi only, [c=64][k=512]
__device__ __half g_Wcath[64*512];

// fp16 pre-converted operands (A side hi/lo, B side hi only)
__device__ __half g_peh[1024*1024], g_pel[1024*1024];
__device__ __half g_obh[1024*1024], g_obl[1024*1024];
__device__ __half g_cxh[128*1024],  g_cxl[128*1024];
__device__ __half g_Bv0h[512*1024];
__device__ __half g_Bv1h[512*1024];
__device__ __half g_Bv2h[512*1024];
__device__ __half g_Whoh[1024*1024];
__device__ __half g_Wohh[1024*1024];
__device__ __half g_sph[16384*32], g_spl[16384*32];   // spatial h/l
__device__ __half g_Wsh[512*32];                      // Wspat^T [n][k] hi

// ---------------- small helpers ----------------
__device__ __forceinline__ u32 smem_u32(const void* p){
    u32 a; asm("{ .reg .u64 t; cvta.to.shared.u64 t, %1; cvt.u32.u64 %0, t; }":"=r"(a):"l"(p)); return a;
}
__device__ __forceinline__ void ldm_x4(u32* r, u32 addr){
    asm volatile("ldmatrix.sync.aligned.m8n8.x4.shared.b16 {%0,%1,%2,%3}, [%4];"
        :"=r"(r[0]),"=r"(r[1]),"=r"(r[2]),"=r"(r[3]):"r"(addr));
}
__device__ __forceinline__ void mma_f16(float* c, const u32* a, const u32* b){
    asm volatile("mma.sync.aligned.m16n8k16.row.col.f32.f16.f16.f32 "
        "{%0,%1,%2,%3}, {%4,%5,%6,%7}, {%8,%9}, {%0,%1,%2,%3};"
        :"+f"(c[0]),"+f"(c[1]),"+f"(c[2]),"+f"(c[3])
        :"r"(a[0]),"r"(a[1]),"r"(a[2]),"r"(a[3]),"r"(b[0]),"r"(b[1]));
}
__device__ __forceinline__ void cp16(u32 dst, const void* src){
    asm volatile("cp.async.cg.shared.global [%0], [%1], 16;"::"r"(dst),"l"(src));
}
// pack (x,y) -> fp16x2 word (hi only)
__device__ __forceinline__ u32 pack2(float x, float y){
    __half2 h = __floats2half2_rn(x, y);
    return *(u32*)&h;
}

// ---------------- c_prep: all fp32->fp16 conversions + packs ----------------
__global__ __launch_bounds__(256) void c_prep(
    const float* __restrict__ people, const float* __restrict__ objects,
    const float* __restrict__ context, const float* __restrict__ spatial,
    const float* __restrict__ Wvis_w, const float* __restrict__ Who_w,
    const float* __restrict__ Woh_w,  const float* __restrict__ Wspat_w,
    const float* __restrict__ Wip_w,  const float* __restrict__ Wref_w,
    const float* __restrict__ Watt_w)
{
    __shared__ float t[32][33];
    int bid = blockIdx.x;
    int tid = threadIdx.x;

    if (bid < 8704) {                                 // ---- convA (hi/lo) ----
        int idx = bid*256 + tid;
        const float* src; __half *dh, *dl; int e;
        if (idx < 1048576)      { src = people;  dh = g_peh; dl = g_pel; e = idx; }
        else if (idx < 2097152) { src = objects; dh = g_obh; dl = g_obl; e = idx - 1048576; }
        else                    { src = context; dh = g_cxh; dl = g_cxl; e = idx - 2097152; }
        float v = 0.f;
        if (dh != g_cxh || (e >> 10) < 64) v = src[e];
        __half h = __float2half(v);
        dh[e] = h;
        dl[e] = __float2half(v - __half2float(h));
    } else if (bid < 12288) {                         // ---- convB (transpose, hi only) ----
        int lb = bid - 8704;
        const float* W; __half *dh; int N, local;
        if (lb < 512)        { W = Wvis_w;            dh = g_Bv0h; N = 512;  local = lb;       }
        else if (lb < 1024)  { W = Wvis_w + 1024*512; dh = g_Bv1h; N = 512;  local = lb - 512; }
        else if (lb < 1536)  { W = Wvis_w + 2048*512; dh = g_Bv2h; N = 512;  local = lb - 1024;}
        else if (lb < 2560)  { W = Who_w;             dh = g_Whoh; N = 1024; local = lb - 1536;}
        else                 { W = Woh_w;             dh = g_Wohh; N = 1024; local = lb - 2560;}
        int ntN = N >> 5;
        int k0 = (local / ntN) * 32, n0 = (local % ntN) * 32;
        #pragma unroll
        for (int i = 0; i < 4; i++) {
            int e = tid + i*256, r = e >> 5, c = e & 31;
            t[r][c] = W[(k0 + r)*N + n0 + c];
        }
        __syncthreads();
        #pragma unroll
        for (int i = 0; i < 4; i++) {
            int e = tid + i*256, r = e >> 5, c = e & 31;
            dh[(n0 + r)*1024 + k0 + c] = __float2half(t[c][r]);
        }
    } else if (bid < 12416) {                         // ---- head-weight pack (hi only) ----
        int idx = (bid - 12288)*256 + tid;
        int c = idx >> 9, k = idx & 511;
        float v = 0.f;
        if (c == 0)                  v = Wip_w[k];
        else if (c <= 29)            v = Wref_w[k*29 + c - 1];
        else if (c >= 32 && c <= 60) v = Watt_w[k*29 + c - 32];
        g_Wcath[idx] = __float2half(v);
    } else if (bid < 14464) {                         // ---- spatial conv (hi/lo) ----
        int idx = (bid - 12416)*256 + tid;            // 524288
        float v = spatial[idx];
        __half h = __float2half(v);
        g_sph[idx] = h;
        g_spl[idx] = __float2half(v - __half2float(h));
    } else {                                          // ---- Wspat^T (hi only) ----
        int idx = (bid - 14464)*256 + tid;            // 16384
        g_Wsh[idx] = __float2half(Wspat_w[(idx & 31)*512 + (idx >> 5)]);
    }
}

// ---------------- k1: warp-MMA fp16 2-term split GEMM, 128x64 tiles ----------------
#define KP 40
#define TA (128*KP*2)
#define TB (64*KP*2)
#define STAGE_B (2*TA + TB)          // Ah, Al, Bh = 25600
#define K1_SMEM (2*STAGE_B)          // 51200

__global__ __launch_bounds__(128,3) void k1_mma(
    const float* __restrict__ Wvis_b,
    const float* __restrict__ Who_b,
    const float* __restrict__ Woh_b,
    int boff)
{
    extern __shared__ char smem[];
    u32 sb = smem_u32(smem);
    int tid = threadIdx.x, lane = tid & 31, wid = tid >> 5;
    int wm = wid & 1, wn = wid >> 1;
    int bid = blockIdx.x + boff;

    const __half *Ah, *Al, *Bh;
    float* C; const float* bias = 0;
    int relu = 0, Mv = 1024, N, mt0, nt0, local;
    if (bid < 64)       { Ah=g_peh; Al=g_pel; Bh=g_Bv0h; C=g_Pvis; N=512;  local=bid;     mt0=local>>3; nt0=local&7; }
    else if (bid < 128) { Ah=g_obh; Al=g_obl; Bh=g_Bv1h; C=g_Ovis; N=512;  local=bid-64;  mt0=local>>3; nt0=local&7; }
    else if (bid < 136) { Ah=g_cxh; Al=g_cxl; Bh=g_Bv2h; C=g_Cvis; N=512;  local=bid-128; mt0=0; nt0=local; bias=Wvis_b; Mv=64; }
    else if (bid < 264) { Ah=g_peh; Al=g_pel; Bh=g_Whoh; C=g_HO;   N=1024; local=bid-136; mt0=local>>4; nt0=local&15; bias=Who_b; relu=1; }
    else                { Ah=g_obh; Al=g_obl; Bh=g_Wohh; C=g_OH;   N=1024; local=bid-264; mt0=local>>4; nt0=local&15; bias=Woh_b; relu=1; }
    int m0 = mt0 * 128, n0 = nt0 * 64;

    float acc[4][4][4];
    #pragma unroll
    for (int i = 0; i < 4; i++)
        #pragma unroll
        for (int j = 0; j < 4; j++)
            #pragma unroll
            for (int q = 0; q < 4; q++) acc[i][j][q] = 0.f;

    int lg = lane >> 3, lr = lane & 7;
    int a_row_off = lr + ((lg & 1) << 3);
    int a_k_off   = (lg >> 1) << 3;
    int b4_row_off = ((lane >> 4) << 3) + lr;
    int b4_k_off   = ((lane >> 3) & 1) << 3;

    #define LOAD_STAGE(KT, S) do {                                                    \
        u32 _s = (S); int _kt = (KT);                                                 \
        _Pragma("unroll")                                                             \
        for (int i = 0; i < 4; i++) {                                                 \
            int e = tid + i*128, row = e >> 2, sg = (e & 3) * 8;                      \
            cp16(_s      + (row*KP + sg)*2, &Ah[(m0 + row)*1024 + _kt + sg]);         \
            cp16(_s + TA + (row*KP + sg)*2, &Al[(m0 + row)*1024 + _kt + sg]);         \
        }                                                                             \
        _Pragma("unroll")                                                             \
        for (int i = 0; i < 2; i++) {                                                 \
            int e = tid + i*128, row = e >> 2, sg = (e & 3) * 8;                      \
            cp16(_s + 2*TA + (row*KP + sg)*2, &Bh[(n0 + row)*1024 + _kt + sg]);       \
        }                                                                             \
        asm volatile("cp.async.commit_group;");                                       \
    } while(0)

    LOAD_STAGE(0, sb);

    for (int c = 0; c < 32; c++) {
        asm volatile("cp.async.wait_group 0;");
        __syncthreads();
        if (c < 31) LOAD_STAGE((c + 1)*32, sb + ((c + 1) & 1)*STAGE_B);

        u32 st  = sb + (c & 1)*STAGE_B;
        u32 sAh = st, sAl = st + TA, sBh = st + 2*TA;

        #pragma unroll
        for (int ks = 0; ks < 32; ks += 16) {
            u32 bh[4][2];
            #pragma unroll
            for (int j = 0; j < 2; j++) {
                u32 boff2 = ((wn*32 + j*16 + b4_row_off)*KP + ks + b4_k_off) * 2;
                u32 r4[4];
                ldm_x4(r4, sBh + boff2);
                bh[j*2][0] = r4[0]; bh[j*2][1] = r4[1]; bh[j*2+1][0] = r4[2]; bh[j*2+1][1] = r4[3];
            }
            #pragma unroll
            for (int mt = 0; mt < 4; mt++) {
                u32 aoff = ((wm*64 + mt*16 + a_row_off)*KP + ks + a_k_off) * 2;
                u32 ah[4], al[4];
                ldm_x4(ah, sAh + aoff);
                ldm_x4(al, sAl + aoff);
                #pragma unroll
                for (int nt = 0; nt < 4; nt++) {
                    mma_f16(acc[mt][nt], ah, bh[nt]);
                    mma_f16(acc[mt][nt], al, bh[nt]);
                }
            }
        }
    }

    int rq = lane >> 2, cq = (lane & 3) * 2;
    #pragma unroll
    for (int mt = 0; mt < 4; mt++) {
        int gmA = m0 + wm*64 + mt*16 + rq;
        int gmB = gmA + 8;
        #pragma unroll
        for (int nt = 0; nt < 4; nt++) {
            int gn = n0 + wn*32 + nt*8 + cq;
            float b0 = bias ? bias[gn]   : 0.f;
            float b1 = bias ? bias[gn+1] : 0.f;
            float v0 = acc[mt][nt][0] + b0, v1 = acc[mt][nt][1] + b1;
            float v2 = acc[mt][nt][2] + b0, v3 = acc[mt][nt][3] + b1;
            if (relu) { v0=fmaxf(v0,0.f); v1=fmaxf(v1,0.f); v2=fmaxf(v2,0.f); v3=fmaxf(v3,0.f); }
            if (gmA < Mv) *(float2*)&C[gmA*N + gn] = make_float2(v0, v1);
            if (gmB < Mv) *(float2*)&C[gmB*N + gn] = make_float2(v2, v3);
        }
    }
}

// ---------------- k2: per-(b,p) MMA phase1 (a_ho/f_ref) + MMA heads ----------------
// smem layout (bytes):
//   [0      ) A hi tile   16x40 fp16 = 1280
//   [1280   ) A lo tile   = 1280
//   [2560   ) Wsh staged  512x40 fp16 = 40960
//   [43520  ) f/a hi      32x520 fp16 = 33280
//   [76800  ) head W hi   64x136 fp16 = 17408
#define K2P 520
#define OFF_AH  0
#define OFF_AL  1280
#define OFF_WS  2560
#define OFF_FAH 43520
#define OFF_WH  76800
#define K2_SMEM 94208

__global__ __launch_bounds__(256,2) void k2_pairs(
    const float* __restrict__ Wspat_b,
    const float* __restrict__ Wip_b,   const float* __restrict__ Wref_b,
    const float* __restrict__ Watt_b,  float* __restrict__ out)
{
    extern __shared__ char sm2[];
    __half* s_ws  = (__half*)(sm2 + OFF_WS);    // [512][40]
    __half* s_fah = (__half*)(sm2 + OFF_FAH);   // [32][520]
    __half* s_wh  = (__half*)(sm2 + OFF_WH);    // [64][136]

    int tid = threadIdx.x;
    int bp = blockIdx.x;
    int b = bp >> 4;
    int lane = tid & 31, wid = tid >> 5;

    // ---- phase 1: load spatial tile [16][32] fp16 h/l + Wsh [512][32] into smem ----
    {
        int l = tid >> 4, kq = tid & 15;
        ((u32*)(sm2 + OFF_AH))[l*20 + kq] = ((const u32*)g_sph)[(bp*16 + l)*16 + kq];
        ((u32*)(sm2 + OFF_AL))[l*20 + kq] = ((const u32*)g_spl)[(bp*16 + l)*16 + kq];
    }
    #pragma unroll
    for (int i = 0; i < 8; i++) {
        int e = tid + i*256;            // 0..2047
        int n = e >> 2, seg = (e & 3) * 8;
        *(uint4*)&s_ws[n*40 + seg] = *(const uint4*)&g_Wsh[n*32 + seg];
    }
    __syncthreads();

    int lg = lane >> 3, lr = lane & 7;
    int a_row_off = lr + ((lg & 1) << 3);
    int a_koff = (lg >> 1) << 3;
    u32 ah0[4], ah1[4], al0[4], al1[4];
    {
        u32 bah = smem_u32(sm2 + OFF_AH), bal = smem_u32(sm2 + OFF_AL);
        u32 aoff = (a_row_off*40 + a_koff)*2;
        ldm_x4(ah0, bah + aoff);
        ldm_x4(ah1, bah + aoff + 32);
        ldm_x4(al0, bal + aoff);
        ldm_x4(al1, bal + aoff + 32);
    }

    // phase1 MMA: warp w covers n-cols w*64..+63; B frags via ldmatrix from s_ws
    int lq = lane & 3, ln = lane >> 2;
    u32 base_ws = smem_u32(s_ws);
    int ws_koff = (lane >> 3) << 3;            // lanes 0-7:k0, 8-15:k8, 16-23:k16, 24-31:k24
    #pragma unroll
    for (int nt = 0; nt < 8; nt++) {
        u32 bh[4];
        ldm_x4(bh, base_ws + ((wid*64 + nt*8 + lr)*40 + ws_koff)*2);
        float c[4] = {0.f, 0.f, 0.f, 0.f};
        mma_f16(c, ah0, bh);
        mma_f16(c, al0, bh);
        mma_f16(c, ah1, bh + 2);
        mma_f16(c, al1, bh + 2);

        // fused epilogue -> s_fah (hi only)
        int j0 = wid*64 + nt*8 + lq*2;
        int l0 = ln, l1 = ln + 8;
        float2 bs = *(const float2*)&Wspat_b[j0];
        float2 pv = *(const float2*)&g_Pvis[bp*512 + j0];
        float2 cv = *(const float2*)&g_Cvis[b*512 + j0];
        float2 o0 = *(const float2*)&g_Ovis[(b*16 + l0)*512 + j0];
        float2 o1 = *(const float2*)&g_Ovis[(b*16 + l1)*512 + j0];
        float a0 = fmaxf(c[0] + bs.x, 0.f), a1 = fmaxf(c[1] + bs.y, 0.f);
        float a2 = fmaxf(c[2] + bs.x, 0.f), a3 = fmaxf(c[3] + bs.y, 0.f);
        float f0 = fmaxf(pv.x + o0.x + cv.x, 0.f) * a0;
        float f1 = fmaxf(pv.y + o0.y + cv.y, 0.f) * a1;
        float f2 = fmaxf(pv.x + o1.x + cv.x, 0.f) * a2;
        float f3 = fmaxf(pv.y + o1.y + cv.y, 0.f) * a3;
        *(u32*)&s_fah[l0*K2P + j0]        = pack2(f0, f1);
        *(u32*)&s_fah[l1*K2P + j0]        = pack2(f2, f3);
        *(u32*)&s_fah[(16 + l0)*K2P + j0] = pack2(a0, a1);
        *(u32*)&s_fah[(16 + l1)*K2P + j0] = pack2(a2, a3);
    }

    // ---- phase 2: [32 rows] @ heads via fp16 MMA (hi x hi) ----
    int mt = wid >> 2;
    int ntile = (wid & 3) + mt*4;

    u32 base_fah = smem_u32(s_fah);
    u32 base_wh  = smem_u32(s_wh);

    int a_row = mt*16 + lr + ((lg & 1) << 3);
    int b_row = ntile*8 + lr;
    int b4_koff = (lane >> 3) << 3;

    float acc2[4] = {0.f, 0.f, 0.f, 0.f};

    for (int kc = 0; kc < 4; kc++) {
        __syncthreads();
        #pragma unroll
        for (int i = 0; i < 4; i++) {
            int e = tid + i*256;
            int c = e >> 4, k8 = (e & 15) << 3;
            *(uint4*)&s_wh[c*136 + k8] = *(const uint4*)&g_Wcath[c*512 + kc*128 + k8];
        }
        __syncthreads();
        #pragma unroll
        for (int ks = 0; ks < 128; ks += 32) {
            u32 bh4[4];
            ldm_x4(bh4, base_wh + (b_row*136 + ks + b4_koff)*2);
            u32 xh0[4], xh1[4];
            ldm_x4(xh0, base_fah + (a_row*K2P + kc*128 + ks + a_koff)*2);
            ldm_x4(xh1, base_fah + (a_row*K2P + kc*128 + ks + 16 + a_koff)*2);
            mma_f16(acc2, xh0, bh4);
            mma_f16(acc2, xh1, bh4 + 2);
        }
    }

    // ---- outputs ----
    int r0 = mt*16 + (lane >> 2);
    int c0 = ntile*8 + (lane & 3)*2;
    #pragma unroll
    for (int q = 0; q < 4; q++) {
        int r = r0 + ((q >> 1) << 3);
        int c = c0 + (q & 1);
        float v = acc2[q];
        if (r < 16) {
            int cidx = bp*16 + r;
            if (c == 0) {
                v += Wip_b[0];
                out[cidx] = v;
                g_adj[cidx] = 1.f / (1.f + expf(-v));
            } else if (c <= 29) {
                out[16384 + cidx*29 + (c - 1)] = v + Wref_b[c - 1];
            }
        } else {
            int cidx = bp*16 + (r - 16);
            int cc = c - 32;
            if (cc >= 0 && cc <= 28) {
                out[491520 + cidx*29 + cc] = v + Watt_b[cc];
            }
        }
    }
}

// ---------------- k3a: message passing ----------------
__global__ __launch_bounds__(256) void k3a_msg(const float* __restrict__ people,
                                               const float* __restrict__ objects)
{
    __shared__ float adj[240];
    int bid = blockIdx.x;                 // 512
    int b = bid >> 3, ch = (bid >> 1) & 3, role = bid & 1;
    int tid = threadIdx.x;
    if (tid < 240) adj[tid] = g_adj[(b*16 + tid/15)*16 + (tid % 15) + 1];
    __syncthreads();

    int d = ch*256 + tid;
    if (role == 0) {
        float oh[15];
        #pragma unroll
        for (int o = 0; o < 15; o++) oh[o] = g_OH[(b*16 + o + 1)*1024 + d];
        #pragma unroll
        for (int p = 0; p < 16; p++) {
            float acc = people[(b*16 + p)*1024 + d];
            #pragma unroll
            for (int o = 0; o < 15; o++) acc += adj[p*15 + o] * oh[o];
            g_PR[(b*16 + p)*1024 + d] = acc;
        }
    } else {
        float ho[16];
        #pragma unroll
        for (int p = 0; p < 16; p++) ho[p] = g_HO[(b*16 + p)*1024 + d];
        g_OBF[(b*16)*1024 + d] = objects[(b*16)*1024 + d];
        #pragma unroll
        for (int o = 0; o < 15; o++) {
            float acc = objects[(b*16 + o + 1)*1024 + d];
            #pragma unroll
            for (int p = 0; p < 16; p++) acc += adj[p*15 + o] * ho[p];
            g_OBF[(b*16 + o + 1)*1024 + d] = acc;
        }
    }
}

// ---------------- k3b: skinny GEMM [2048,1024]@[1024,29] warp-per-row ----------------
__global__ __launch_bounds__(256) void k3b_gemm(const float* __restrict__ Wg_w,
                                                const float* __restrict__ Wg_b)
{
    __shared__ float Ws[256*33];
    int half = blockIdx.x >> 7;
    int row = (blockIdx.x & 127)*8 + (threadIdx.x >> 5);
    int lane = threadIdx.x & 31;
    const float* src = half ? g_OBF : g_PR;
    const float* W = Wg_w + half*1024*29;
    float* dst = half ? g_Go : g_Gp;

    float acc[29];
    #pragma unroll
    for (int a = 0; a < 29; a++) acc[a] = 0.f;

    for (int kt = 0; kt < 4; kt++) {
        __syncthreads();
        #pragma unroll
        for (int i = 0; i < 29; i++) {
            int idx = threadIdx.x + i*256;
            int k = idx / 29, a = idx - k*29;
            Ws[k*33 + a] = W[kt*7424 + idx];
        }
        __syncthreads();
        #pragma unroll
        for (int t = 0; t < 8; t++) {
            int k = t*32 + lane;
            float rv = src[row*1024 + kt*256 + k];
            #pragma unroll
            for (int a = 0; a < 29; a++) acc[a] += rv * Ws[k*33 + a];
        }
    }
    #pragma unroll
    for (int off = 16; off; off >>= 1)
        #pragma unroll
        for (int a = 0; a < 29; a++)
            acc[a] += __shfl_down_sync(0xffffffffu, acc[a], off);
    if (lane == 0) {
        #pragma unroll
        for (int a = 0; a < 29; a++)
            dst[row*29 + a] = acc[a] + (half ? Wg_b[a] : 0.f);
    }
}

// ---------------- k3c: broadcast add -> p_graph ----------------
__global__ __launch_bounds__(256) void k3c_add(float* __restrict__ out_pg)
{
    int idx = blockIdx.x*256 + threadIdx.x;
    int c = idx / 29;
    int a = idx - c*29;
    int prow = c >> 4;
    int lrow = (c >> 8)*16 + (c & 15);
    out_pg[idx] = g_Gp[prow*29 + a] + g_Go[lrow*29 + a];
}

// ---------------- launch: fork k1b (HO/OH) onto side stream ----------------
extern "C" void kernel_launch(void* const* d_in, const int* in_sizes, int n_in,
                              void* d_out, int out_size) {
    const float* people  = (const float*)d_in[0];
    const float* objects = (const float*)d_in[1];
    const float* context = (const float*)d_in[2];
    const float* spatial = (const float*)d_in[3];
    const float* Wvis_w  = (const float*)d_in[4];
    const float* Wvis_b  = (const float*)d_in[5];
    const float* Wspat_w = (const float*)d_in[6];
    const float* Wspat_b = (const float*)d_in[7];
    const float* Wip_w   = (const float*)d_in[8];
    const float* Wip_b   = (const float*)d_in[9];
    const float* Wref_w  = (const float*)d_in[10];
    const float* Wref_b  = (const float*)d_in[11];
    const float* Watt_w  = (const float*)d_in[12];
    const float* Watt_b  = (const float*)d_in[13];
    const float* Woh_w   = (const float*)d_in[14];
    const float* Woh_b   = (const float*)d_in[15];
    const float* Who_w   = (const float*)d_in[16];
    const float* Who_b   = (const float*)d_in[17];
    const float* Wg_w    = (const float*)d_in[18];
    const float* Wg_b    = (const float*)d_in[19];
    float* out = (float*)d_out;

    cudaFuncSetAttribute(k1_mma,  cudaFuncAttributeMaxDynamicSharedMemorySize, K1_SMEM);
    cudaFuncSetAttribute(k2_pairs, cudaFuncAttributeMaxDynamicSharedMemorySize, K2_SMEM);

    cudaStream_t s1;
    cudaStreamCreateWithFlags(&s1, cudaStreamNonBlocking);
    cudaEvent_t ev0, ev1;
    cudaEventCreateWithFlags(&ev0, cudaEventDisableTiming);
    cudaEventCreateWithFlags(&ev1, cudaEventDisableTiming);

    // origin stream: prep
    c_prep<<<14528, 256>>>(people, objects, context, spatial,
                           Wvis_w, Who_w, Woh_w, Wspat_w,
                           Wip_w, Wref_w, Watt_w);

    // fork: k1b (HO/OH, blocks 136..391) on side stream
    cudaEventRecord(ev0, 0);
    cudaStreamWaitEvent(s1, ev0, 0);
    k1_mma<<<256, 128, K1_SMEM, s1>>>(Wvis_b, Who_b, Woh_b, 136);
    cudaEventRecord(ev1, s1);

    // origin stream: k1a (Pvis/Ovis/Cvis) then k2
    k1_mma<<<136, 128, K1_SMEM>>>(Wvis_b, Who_b, Woh_b, 0);
    k2_pairs<<<1024, 256, K2_SMEM>>>(Wspat_b, Wip_b, Wref_b, Watt_b, out);

    // join: k3 chain needs HO/OH (k1b) + g_adj (k2)
    cudaStreamWaitEvent(0, ev1, 0);
    k3a_msg<<<512, 256>>>(people, objects);
    k3b_gemm<<<256, 256>>>(Wg_w, Wg_b);
    k3c_add<<<1856, 256>>>(out + 966656);

    cudaEventDestroy(ev0);
    cudaEventDestroy(ev1);
    cudaStreamDestroy(s1);
}